// round 2
// baseline (speedup 1.0000x reference)
#include <cuda_runtime.h>
#include <cstdint>

#define N_NODES 100000
#define N_EDGES 1600000
#define IN_CH   17
#define HID     64
#define TDIM    32
#define BATCH   10000
#define BN_EPS  1e-5f

// ---------------- device scratch (no allocations allowed) ----------------
__device__ float g_h  [(size_t)N_NODES * HID];   // node features (hid=64)
__device__ float g_msg[(size_t)N_NODES * HID];   // message accumulator
__device__ float g_deg[N_NODES];                 // in-degree (as float)
__device__ float g_stats[4 * 128];               // BN stats: layer0, layer1, clf1, clf2
__device__ float g_z1[BATCH * 64];
__device__ float g_z2[BATCH * 32];
__device__ int   g_src[N_EDGES];
__device__ int   g_dst[N_EDGES];

__device__ __forceinline__ float tanh_fast(float x) {
    float e = __expf(2.f * x);
    return 1.f - __fdividef(2.f, e + 1.f);
}

// ---------------- edge index conversion (int64 or int32 -> int32) ----------------
__global__ void k_convert_idx(const void* __restrict__ ei_raw) {
    __shared__ int s_is64;
    if (threadIdx.x == 0) {
        // int64 values < 100000 => every odd 32-bit word of the first pairs is 0.
        const unsigned* w = (const unsigned*)ei_raw;
        int is64 = 1;
        for (int i = 1; i < 64; i += 2)
            if (w[i] != 0u) { is64 = 0; break; }
        s_is64 = is64;
    }
    __syncthreads();
    int e = blockIdx.x * 256 + threadIdx.x;
    if (e >= N_EDGES) return;
    if (s_is64) {
        const long long* p = (const long long*)ei_raw;
        g_src[e] = (int)p[e];
        g_dst[e] = (int)p[(size_t)N_EDGES + e];
    } else {
        const int* p = (const int*)ei_raw;
        g_src[e] = p[e];
        g_dst[e] = p[N_EDGES + e];
    }
}

// ---------------- zero scratch ----------------
__global__ void k_zero_all() {
    int i = blockIdx.x * 256 + threadIdx.x;
    int st = gridDim.x * 256;
    for (int k = i; k < N_NODES * HID; k += st) g_msg[k] = 0.f;
    for (int k = i; k < N_NODES; k += st) g_deg[k] = 0.f;
    if (i < 512) g_stats[i] = 0.f;
}

// ---------------- degree count ----------------
__global__ void k_deg() {
    int e = blockIdx.x * 256 + threadIdx.x;
    atomicAdd(&g_deg[g_dst[e]], 1.f);
}

// ---------------- stage 1: temporal edge MLP (66 -> 33 -> 17) ----------------
__global__ void k_stage1(const float* __restrict__ x,
                         const float* __restrict__ dts, const float* __restrict__ bf,
                         const float* __restrict__ ph,
                         const float* __restrict__ W1, const float* __restrict__ b1,
                         const float* __restrict__ W2, const float* __restrict__ b2) {
    __shared__ float sW1[66 * 33], sW2[33 * 17], sB1[33], sB2[17], sF[32], sP[32];
    int tid = threadIdx.x;
    for (int i = tid; i < 66 * 33; i += 256) sW1[i] = W1[i];
    for (int i = tid; i < 33 * 17; i += 256) sW2[i] = W2[i];
    if (tid < 33) sB1[tid] = b1[tid];
    if (tid < 17) sB2[tid] = b2[tid];
    if (tid < 32) { sF[tid] = bf[tid]; sP[tid] = ph[tid]; }
    __syncthreads();

    int e = blockIdx.x * 256 + tid;
    int s = g_src[e];
    int d = g_dst[e];
    float dt = dts[e];

    float acc[33];
#pragma unroll
    for (int j = 0; j < 33; j++) acc[j] = sB1[j];

    const float* xd = x + (size_t)d * IN_CH;
    const float* xs = x + (size_t)s * IN_CH;

#pragma unroll 1
    for (int i = 0; i < 17; i++) {
        float v = xd[i];
        const float* w = &sW1[i * 33];
#pragma unroll
        for (int j = 0; j < 33; j++) acc[j] += v * w[j];
    }
#pragma unroll 1
    for (int i = 0; i < 17; i++) {
        float v = xs[i];
        const float* w = &sW1[(17 + i) * 33];
#pragma unroll
        for (int j = 0; j < 33; j++) acc[j] += v * w[j];
    }
#pragma unroll 1
    for (int t = 0; t < 32; t++) {
        float v = __cosf(dt * sF[t] + sP[t]);
        const float* w = &sW1[(34 + t) * 33];
#pragma unroll
        for (int j = 0; j < 33; j++) acc[j] += v * w[j];
    }
#pragma unroll
    for (int j = 0; j < 33; j++) acc[j] = fmaxf(acc[j], 0.f);

    float* outp = g_msg + (size_t)d * HID;
#pragma unroll 1
    for (int j2 = 0; j2 < 17; j2++) {
        float p = sB2[j2];
#pragma unroll
        for (int i = 0; i < 33; i++) p += acc[i] * sW2[i * 17 + j2];
        float m = (2.f * tanh_fast(p) - 1.f) * xd[j2];
        atomicAdd(&outp[j2], m);
    }
}

// ---------------- node update + projection: h = (x + msg/deg) @ PW + Pb ----------------
__global__ void k_proj(const float* __restrict__ x, const float* __restrict__ PW,
                       const float* __restrict__ Pb) {
    __shared__ float sW[17 * 64];
    __shared__ float sB[64];
    int tid = threadIdx.x;
    for (int i = tid; i < 17 * 64; i += 256) sW[i] = PW[i];
    if (tid < 64) sB[tid] = Pb[tid];
    __syncthreads();

    int n = blockIdx.x * 256 + tid;
    if (n >= N_NODES) return;
    float rdeg = 1.f / fmaxf(g_deg[n], 1.f);

    float acc[64];
#pragma unroll
    for (int c = 0; c < 64; c++) acc[c] = sB[c];

#pragma unroll 1
    for (int k = 0; k < 17; k++) {
        size_t mo = (size_t)n * 64 + k;
        float xm = x[(size_t)n * 17 + k] + g_msg[mo] * rdeg;
        g_msg[mo] = 0.f;  // re-zero for layer passes
        const float* w = &sW[k * 64];
#pragma unroll
        for (int c = 0; c < 64; c++) acc[c] += xm * w[c];
    }
    float* hp = g_h + (size_t)n * 64;
#pragma unroll
    for (int c = 0; c < 64; c++) hp[c] = acc[c];
}

// ---------------- stage 2 layer kernel: per-edge MLP 128 -> 64 -> 64 ----------------
// 128 edges per block, 512 threads. Edge-major smem with odd strides (129/65)
// => conflict-free per-lane scalar LDS in the GEMM mainloop.
#define LK_SMEM_FLOATS 37504
__global__ __launch_bounds__(512, 1)
void k_layer(const float* __restrict__ W1, const float* __restrict__ b1,
             const float* __restrict__ W2, const float* __restrict__ b2) {
    extern __shared__ float sm[];
    const int OW1 = 0, OW2 = 8192, OB1 = 12288, OB2 = 12352;
    const int OM = 12416;      // 128 x 129 edge-major m_in
    const int OH = 28928;      // 128 x 65 edge-major hidden
    const int ODST = 37248, OSRC = 37376;

    int tid = threadIdx.x;
    for (int i = tid; i < 8192; i += 512) sm[OW1 + i] = W1[i];
    for (int i = tid; i < 4096; i += 512) sm[OW2 + i] = W2[i];
    if (tid < 64) { sm[OB1 + tid] = b1[tid]; sm[OB2 + tid] = b2[tid]; }
    int* sD = (int*)(sm + ODST);
    int* sS = (int*)(sm + OSRC);
    if (tid < 128) {
        int e = blockIdx.x * 128 + tid;
        sS[tid] = g_src[e];
        sD[tid] = g_dst[e];
    }
    __syncthreads();

    // gather: m_in[e] = [h[dst[e]] (64), h[src[e]] (64)]
    for (int t = tid; t < 4096; t += 512) {
        int e = t >> 5, q = t & 31, qq = q & 15;
        int row = (q < 16) ? sD[e] : sS[e];
        const float4 v = *(const float4*)(g_h + (size_t)row * 64 + qq * 4);
        float* dp = sm + OM + e * 129 + ((q < 16) ? 0 : 64) + qq * 4;
        dp[0] = v.x; dp[1] = v.y; dp[2] = v.z; dp[3] = v.w;
    }
    __syncthreads();

    int lane = tid & 31, cg = tid >> 5;
    const float* pM0 = sm + OM + lane * 129;   // edge lane + 32*j at offset j*4128

    float acc[4][4];
    {
        float4 bb = *(const float4*)(sm + OB1 + 4 * cg);
#pragma unroll
        for (int j = 0; j < 4; j++) { acc[j][0] = bb.x; acc[j][1] = bb.y; acc[j][2] = bb.z; acc[j][3] = bb.w; }
    }
#pragma unroll 4
    for (int k = 0; k < 128; k++) {
        float4 w = *(const float4*)(sm + OW1 + k * 64 + 4 * cg);
#pragma unroll
        for (int j = 0; j < 4; j++) {
            float m = pM0[j * 4128 + k];
            acc[j][0] += m * w.x; acc[j][1] += m * w.y;
            acc[j][2] += m * w.z; acc[j][3] += m * w.w;
        }
    }
    // hidden = relu -> smem (edge-major, stride 65)
    float* pH0 = sm + OH + lane * 65;
#pragma unroll
    for (int j = 0; j < 4; j++)
#pragma unroll
        for (int i = 0; i < 4; i++)
            pH0[j * 2080 + 4 * cg + i] = fmaxf(acc[j][i], 0.f);
    __syncthreads();

    float acc2[4][4];
    {
        float4 bb = *(const float4*)(sm + OB2 + 4 * cg);
#pragma unroll
        for (int j = 0; j < 4; j++) { acc2[j][0] = bb.x; acc2[j][1] = bb.y; acc2[j][2] = bb.z; acc2[j][3] = bb.w; }
    }
#pragma unroll 4
    for (int k = 0; k < 64; k++) {
        float4 w = *(const float4*)(sm + OW2 + k * 64 + 4 * cg);
#pragma unroll
        for (int j = 0; j < 4; j++) {
            float m = pH0[j * 2080 + k];
            acc2[j][0] += m * w.x; acc2[j][1] += m * w.y;
            acc2[j][2] += m * w.z; acc2[j][3] += m * w.w;
        }
    }
    // msg = (2*tanh(p)-1) * h_dst ; scalar reductions into g_msg
#pragma unroll
    for (int j = 0; j < 4; j++) {
        int dn = sD[lane + 32 * j];
        float* ptr = g_msg + (size_t)dn * 64 + 4 * cg;
#pragma unroll
        for (int i = 0; i < 4; i++) {
            float hval = pM0[j * 4128 + 4 * cg + i];
            float v = (2.f * tanh_fast(acc2[j][i]) - 1.f) * hval;
            atomicAdd(ptr + i, v);
        }
    }
}

// ---------------- node update (h += msg/deg), zero msg, BN partial stats ----------------
__global__ void k_update(int statOff) {
    float* stats = g_stats + statOff;
    int tid = threadIdx.x;
    int c = tid & 63, sub = tid >> 6;
    int base = blockIdx.x * 256;
    float s = 0.f, ss = 0.f;
    for (int i = 0; i < 64; i++) {
        int n = base + i * 4 + sub;
        if (n < N_NODES) {
            size_t o = (size_t)n * 64 + c;
            float rdeg = 1.f / fmaxf(g_deg[n], 1.f);
            float hv = g_h[o] + g_msg[o] * rdeg;
            g_h[o] = hv;
            g_msg[o] = 0.f;
            s += hv;
            ss += hv * hv;
        }
    }
    __shared__ float sA[256], sBm[256];
    sA[tid] = s; sBm[tid] = ss;
    __syncthreads();
    if (tid < 64) {
        s  = sA[tid] + sA[tid + 64] + sA[tid + 128] + sA[tid + 192];
        ss = sBm[tid] + sBm[tid + 64] + sBm[tid + 128] + sBm[tid + 192];
        atomicAdd(&stats[c], s);
        atomicAdd(&stats[64 + c], ss);
    }
}

// ---------------- BN apply + relu on g_h ----------------
__global__ void k_bnrelu(int statOff, const float* __restrict__ g, const float* __restrict__ b) {
    const float* stats = g_stats + statOff;
    int idx = blockIdx.x * 256 + threadIdx.x;  // 1,600,000 float4
    int c0 = (idx & 15) * 4;
    const float invn = 1.f / (float)N_NODES;
    float4* hp = ((float4*)g_h) + idx;
    float4 v = *hp;
    float o[4] = {v.x, v.y, v.z, v.w};
#pragma unroll
    for (int i = 0; i < 4; i++) {
        float m = stats[c0 + i] * invn;
        float var = stats[64 + c0 + i] * invn - m * m;
        float sc = rsqrtf(var + BN_EPS) * g[c0 + i];
        o[i] = fmaxf((o[i] - m) * sc + b[c0 + i], 0.f);
    }
    v.x = o[0]; v.y = o[1]; v.z = o[2]; v.w = o[3];
    *hp = v;
}

// ---------------- classifier ----------------
__global__ void k_clf1(const float* __restrict__ W, const float* __restrict__ b) {
    __shared__ float sW[4096], sB[64];
    int tid = threadIdx.x;
    for (int i = tid; i < 4096; i += 256) sW[i] = W[i];
    if (tid < 64) sB[tid] = b[tid];
    __syncthreads();
    int r = blockIdx.x * 256 + tid;
    if (r >= BATCH) return;
    float acc[64];
#pragma unroll
    for (int c = 0; c < 64; c++) acc[c] = sB[c];
#pragma unroll 1
    for (int k = 0; k < 64; k++) {
        float hk = g_h[(size_t)r * 64 + k];
        const float* w = &sW[k * 64];
#pragma unroll
        for (int c = 0; c < 64; c++) acc[c] += hk * w[c];
    }
    float* z = g_z1 + (size_t)r * 64;
    float* st = g_stats + 256;
#pragma unroll 1
    for (int c = 0; c < 64; c++) {
        z[c] = acc[c];
        atomicAdd(&st[c], acc[c]);
        atomicAdd(&st[64 + c], acc[c] * acc[c]);
    }
}

__global__ void k_clf2(const float* __restrict__ W, const float* __restrict__ b,
                       const float* __restrict__ g1, const float* __restrict__ bb1) {
    __shared__ float sW[2048], sB[32], sScale[64], sBias[64];
    int tid = threadIdx.x;
    for (int i = tid; i < 2048; i += 256) sW[i] = W[i];
    if (tid < 32) sB[tid] = b[tid];
    if (tid < 64) {
        const float invn = 1.f / (float)BATCH;
        float m = g_stats[256 + tid] * invn;
        float var = g_stats[256 + 64 + tid] * invn - m * m;
        float sc = rsqrtf(var + BN_EPS) * g1[tid];
        sScale[tid] = sc;
        sBias[tid] = bb1[tid] - m * sc;
    }
    __syncthreads();
    int r = blockIdx.x * 256 + tid;
    if (r >= BATCH) return;
    float acc[32];
#pragma unroll
    for (int c = 0; c < 32; c++) acc[c] = sB[c];
#pragma unroll 1
    for (int k = 0; k < 64; k++) {
        float v = fmaxf(g_z1[(size_t)r * 64 + k] * sScale[k] + sBias[k], 0.f);
        const float* w = &sW[k * 32];
#pragma unroll
        for (int c = 0; c < 32; c++) acc[c] += v * w[c];
    }
    float* z = g_z2 + (size_t)r * 32;
    float* st = g_stats + 384;
#pragma unroll 1
    for (int c = 0; c < 32; c++) {
        z[c] = acc[c];
        atomicAdd(&st[c], acc[c]);
        atomicAdd(&st[32 + c], acc[c] * acc[c]);
    }
}

__global__ void k_clf3(const float* __restrict__ W3, const float* __restrict__ b3,
                       const float* __restrict__ g2, const float* __restrict__ bb2,
                       float* __restrict__ out) {
    __shared__ float sW[32], sScale[32], sBias[32], sb3;
    int tid = threadIdx.x;
    if (tid < 32) {
        sW[tid] = W3[tid];
        const float invn = 1.f / (float)BATCH;
        float m = g_stats[384 + tid] * invn;
        float var = g_stats[384 + 32 + tid] * invn - m * m;
        float sc = rsqrtf(var + BN_EPS) * g2[tid];
        sScale[tid] = sc;
        sBias[tid] = bb2[tid] - m * sc;
    }
    if (tid == 0) sb3 = b3[0];
    __syncthreads();
    int r = blockIdx.x * 256 + tid;
    if (r >= BATCH) return;
    float a = sb3;
#pragma unroll 1
    for (int k = 0; k < 32; k++)
        a += fmaxf(g_z2[(size_t)r * 32 + k] * sScale[k] + sBias[k], 0.f) * sW[k];
    out[r] = a;
}

// ---------------- launch ----------------
extern "C" void kernel_launch(void* const* d_in, const int* in_sizes, int n_in,
                              void* d_out, int out_size) {
    // input order per reference dict; if batch_size scalar wasn't materialized
    // as a buffer, everything after index 3 shifts down by one.
    auto ix = [&](int i) { return (n_in >= 28) ? i : (i > 3 ? i - 1 : i); };
    const float* x    = (const float*)d_in[ix(0)];
    const void*  ei   = d_in[ix(1)];
    const float* dts  = (const float*)d_in[ix(2)];
    const float* bf   = (const float*)d_in[ix(4)];
    const float* ph   = (const float*)d_in[ix(5)];
    const float* tW1  = (const float*)d_in[ix(6)];
    const float* tb1  = (const float*)d_in[ix(7)];
    const float* tW2  = (const float*)d_in[ix(8)];
    const float* tb2  = (const float*)d_in[ix(9)];
    const float* pW   = (const float*)d_in[ix(10)];
    const float* pb   = (const float*)d_in[ix(11)];
    const float* sW1  = (const float*)d_in[ix(12)];
    const float* sb1  = (const float*)d_in[ix(13)];
    const float* sW2  = (const float*)d_in[ix(14)];
    const float* sb2  = (const float*)d_in[ix(15)];
    const float* bng  = (const float*)d_in[ix(16)];
    const float* bnb  = (const float*)d_in[ix(17)];
    const float* cW1  = (const float*)d_in[ix(18)];
    const float* cb1  = (const float*)d_in[ix(19)];
    const float* cg1  = (const float*)d_in[ix(20)];
    const float* cbb1 = (const float*)d_in[ix(21)];
    const float* cW2  = (const float*)d_in[ix(22)];
    const float* cb2  = (const float*)d_in[ix(23)];
    const float* cg2  = (const float*)d_in[ix(24)];
    const float* cbb2 = (const float*)d_in[ix(25)];
    const float* cW3  = (const float*)d_in[ix(26)];
    const float* cb3  = (const float*)d_in[ix(27)];
    float* out = (float*)d_out;

    const int LK_SMEM_BYTES = LK_SMEM_FLOATS * 4;  // 150016 B
    cudaFuncSetAttribute(k_layer, cudaFuncAttributeMaxDynamicSharedMemorySize, LK_SMEM_BYTES);

    k_zero_all<<<2048, 256>>>();
    k_convert_idx<<<N_EDGES / 256, 256>>>(ei);
    k_deg<<<N_EDGES / 256, 256>>>();
    k_stage1<<<N_EDGES / 256, 256>>>(x, dts, bf, ph, tW1, tb1, tW2, tb2);
    k_proj<<<(N_NODES + 255) / 256, 256>>>(x, pW, pb);

    for (int l = 0; l < 2; l++) {
        k_layer<<<N_EDGES / 128, 512, LK_SMEM_BYTES>>>(sW1 + l * 8192, sb1 + l * 64,
                                                       sW2 + l * 4096, sb2 + l * 64);
        k_update<<<(N_NODES + 255) / 256, 256>>>(l * 128);
        k_bnrelu<<<(N_NODES * HID / 4) / 256, 256>>>(l * 128, bng + l * 64, bnb + l * 64);
    }

    k_clf1<<<(BATCH + 255) / 256, 256>>>(cW1, cb1);
    k_clf2<<<(BATCH + 255) / 256, 256>>>(cW2, cb2, cg1, cbb1);
    k_clf3<<<(BATCH + 255) / 256, 256>>>(cW3, cb3, cg2, cbb2, out);
    (void)in_sizes; (void)out_size;
}

// round 3
// speedup vs baseline: 1.2232x; 1.2232x over previous
#include <cuda_runtime.h>
#include <cstdint>

#define N_NODES 100000
#define N_EDGES 1600000
#define IN_CH   17
#define HID     64
#define BATCH   10000
#define BN_EPS  1e-5f

typedef unsigned long long ull;

// ---------------- device scratch ----------------
__device__ float g_h  [(size_t)N_NODES * HID];
__device__ float g_msg[(size_t)N_NODES * HID];
__device__ float g_deg[N_NODES];
__device__ float g_stats[4 * 128];
__device__ float g_z1[BATCH * 64];
__device__ float g_z2[BATCH * 32];
__device__ int   g_src[N_EDGES];
__device__ int   g_dst[N_EDGES];

__device__ __forceinline__ float tanh_fast(float x) {
    float e = __expf(2.f * x);
    return 1.f - __fdividef(2.f, e + 1.f);
}
__device__ __forceinline__ ull pack2(float x) {
    ull r; asm("mov.b64 %0,{%1,%1};" : "=l"(r) : "f"(x)); return r;
}
__device__ __forceinline__ void unpack2(ull a, float& x, float& y) {
    asm("mov.b64 {%0,%1},%2;" : "=f"(x), "=f"(y) : "l"(a));
}
__device__ __forceinline__ void fma2(ull& d, ull a, ull b) {
    asm("fma.rn.f32x2 %0,%1,%2,%0;" : "+l"(d) : "l"(a), "l"(b));
}
__device__ __forceinline__ void red4(float* p, float a, float b, float c, float d) {
    asm volatile("{\n\t.reg .u64 q;\n\tcvta.to.global.u64 q,%0;\n\t"
                 "red.global.add.v4.f32 [q],{%1,%2,%3,%4};\n\t}"
                 :: "l"(p), "f"(a), "f"(b), "f"(c), "f"(d) : "memory");
}

// ---------------- edge index conversion + degree ----------------
__global__ void k_convert_idx(const void* __restrict__ ei_raw) {
    __shared__ int s_is64;
    if (threadIdx.x == 0) {
        const unsigned* w = (const unsigned*)ei_raw;
        int is64 = 1;
        for (int i = 1; i < 64; i += 2)
            if (w[i] != 0u) { is64 = 0; break; }
        s_is64 = is64;
    }
    __syncthreads();
    int e = blockIdx.x * 256 + threadIdx.x;
    if (e >= N_EDGES) return;
    int s, d;
    if (s_is64) {
        const long long* p = (const long long*)ei_raw;
        s = (int)p[e]; d = (int)p[(size_t)N_EDGES + e];
    } else {
        const int* p = (const int*)ei_raw;
        s = p[e]; d = p[N_EDGES + e];
    }
    g_src[e] = s; g_dst[e] = d;
    atomicAdd(&g_deg[d], 1.f);
}

// ---------------- zero scratch ----------------
__global__ void k_zero_all() {
    int i = blockIdx.x * 256 + threadIdx.x;
    int st = gridDim.x * 256;
    for (int k = i; k < N_NODES * HID; k += st) g_msg[k] = 0.f;
    for (int k = i; k < N_NODES; k += st) g_deg[k] = 0.f;
    if (i < 512) g_stats[i] = 0.f;
}

// ---------------- stage 1: temporal edge MLP (66 -> 33 -> 17), 2 edges/thread ----
__global__ __launch_bounds__(256)
void k_stage1(const float* __restrict__ x,
              const float* __restrict__ dts, const float* __restrict__ bf,
              const float* __restrict__ ph,
              const float* __restrict__ W1, const float* __restrict__ b1,
              const float* __restrict__ W2, const float* __restrict__ b2) {
    // repacked: W1 rows stride 36 (66x33), W2 rows stride 20 (33x17)
    __shared__ float sW1[66 * 36];   // 2376
    __shared__ float sW2[33 * 20];   // 660
    __shared__ __align__(16) float sB1[34], sB2[18], sF[32], sP[32];
    int tid = threadIdx.x;
    for (int i = tid; i < 66 * 33; i += 256) {
        int r = i / 33, c = i - r * 33;
        sW1[r * 36 + c] = W1[i];
    }
    for (int i = tid; i < 33 * 17; i += 256) {
        int r = i / 17, c = i - r * 17;
        sW2[r * 20 + c] = W2[i];
    }
    if (tid < 33) sB1[tid] = b1[tid];
    if (tid < 17) sB2[tid] = b2[tid];
    if (tid < 32) { sF[tid] = bf[tid]; sP[tid] = ph[tid]; }
    __syncthreads();

    int e0 = blockIdx.x * 512 + tid;
    int e1 = e0 + 256;
    int s0 = g_src[e0], d0 = g_dst[e0];
    int s1 = g_src[e1], d1 = g_dst[e1];
    float dt0 = dts[e0], dt1 = dts[e1];

    const float* xd0 = x + (size_t)d0 * IN_CH;
    const float* xs0 = x + (size_t)s0 * IN_CH;
    const float* xd1 = x + (size_t)d1 * IN_CH;
    const float* xs1 = x + (size_t)s1 * IN_CH;

    ull a0[16], a1[16];
    float t0, t1;
    {
        const ull* bp = (const ull*)sB1;
#pragma unroll
        for (int p = 0; p < 16; p++) { a0[p] = bp[p]; a1[p] = bp[p]; }
        t0 = sB1[32]; t1 = sB1[32];
    }

#define S1_ROW(ROW, V0, V1)                                             \
    {                                                                   \
        ull m0 = pack2(V0), m1 = pack2(V1);                             \
        const ulonglong2* wp = (const ulonglong2*)(sW1 + (ROW) * 36);   \
        ulonglong2 wa = wp[0], wb = wp[1], wc = wp[2], wd = wp[3];      \
        ulonglong2 we = wp[4], wf = wp[5], wg = wp[6], wh = wp[7];      \
        fma2(a0[0], m0, wa.x);  fma2(a1[0], m1, wa.x);                  \
        fma2(a0[1], m0, wa.y);  fma2(a1[1], m1, wa.y);                  \
        fma2(a0[2], m0, wb.x);  fma2(a1[2], m1, wb.x);                  \
        fma2(a0[3], m0, wb.y);  fma2(a1[3], m1, wb.y);                  \
        fma2(a0[4], m0, wc.x);  fma2(a1[4], m1, wc.x);                  \
        fma2(a0[5], m0, wc.y);  fma2(a1[5], m1, wc.y);                  \
        fma2(a0[6], m0, wd.x);  fma2(a1[6], m1, wd.x);                  \
        fma2(a0[7], m0, wd.y);  fma2(a1[7], m1, wd.y);                  \
        fma2(a0[8], m0, we.x);  fma2(a1[8], m1, we.x);                  \
        fma2(a0[9], m0, we.y);  fma2(a1[9], m1, we.y);                  \
        fma2(a0[10], m0, wf.x); fma2(a1[10], m1, wf.x);                 \
        fma2(a0[11], m0, wf.y); fma2(a1[11], m1, wf.y);                 \
        fma2(a0[12], m0, wg.x); fma2(a1[12], m1, wg.x);                 \
        fma2(a0[13], m0, wg.y); fma2(a1[13], m1, wg.y);                 \
        fma2(a0[14], m0, wh.x); fma2(a1[14], m1, wh.x);                 \
        fma2(a0[15], m0, wh.y); fma2(a1[15], m1, wh.y);                 \
        float ws = sW1[(ROW) * 36 + 32];                                \
        t0 = fmaf(V0, ws, t0); t1 = fmaf(V1, ws, t1);                   \
    }

#pragma unroll 1
    for (int i = 0; i < 17; i++) { float v0 = xd0[i], v1 = xd1[i]; S1_ROW(i, v0, v1); }
#pragma unroll 1
    for (int i = 0; i < 17; i++) { float v0 = xs0[i], v1 = xs1[i]; S1_ROW(17 + i, v0, v1); }
#pragma unroll 1
    for (int t = 0; t < 32; t++) {
        float f = sF[t], p = sP[t];
        float v0 = __cosf(dt0 * f + p);
        float v1 = __cosf(dt1 * f + p);
        S1_ROW(34 + t, v0, v1);
    }

    // unpack + relu hidden
    float h0[33], h1[33];
#pragma unroll
    for (int p = 0; p < 16; p++) {
        unpack2(a0[p], h0[2 * p], h0[2 * p + 1]);
        unpack2(a1[p], h1[2 * p], h1[2 * p + 1]);
    }
    h0[32] = t0; h1[32] = t1;
#pragma unroll
    for (int i = 0; i < 33; i++) { h0[i] = fmaxf(h0[i], 0.f); h1[i] = fmaxf(h1[i], 0.f); }

    // second MLP: 33 -> 17
    ull c0[8], c1[8]; float q0, q1;
    {
        const ull* bp = (const ull*)sB2;
#pragma unroll
        for (int p = 0; p < 8; p++) { c0[p] = bp[p]; c1[p] = bp[p]; }
        q0 = sB2[16]; q1 = sB2[16];
    }
#pragma unroll 1
    for (int i = 0; i < 33; i++) {
        ull m0 = pack2(h0[i]), m1 = pack2(h1[i]);
        const ulonglong2* wp = (const ulonglong2*)(sW2 + i * 20);
        ulonglong2 wa = wp[0], wb = wp[1], wc = wp[2], wd = wp[3];
        fma2(c0[0], m0, wa.x); fma2(c1[0], m1, wa.x);
        fma2(c0[1], m0, wa.y); fma2(c1[1], m1, wa.y);
        fma2(c0[2], m0, wb.x); fma2(c1[2], m1, wb.x);
        fma2(c0[3], m0, wb.y); fma2(c1[3], m1, wb.y);
        fma2(c0[4], m0, wc.x); fma2(c1[4], m1, wc.x);
        fma2(c0[5], m0, wc.y); fma2(c1[5], m1, wc.y);
        fma2(c0[6], m0, wd.x); fma2(c1[6], m1, wd.x);
        fma2(c0[7], m0, wd.y); fma2(c1[7], m1, wd.y);
        float ws = sW2[i * 20 + 16];
        q0 = fmaf(h0[i], ws, q0); q1 = fmaf(h1[i], ws, q1);
    }

    // messages: (2*tanh(p)-1) * x_dst, scatter 17 cols
    {
        float pv[17];
#pragma unroll
        for (int p = 0; p < 8; p++) unpack2(c0[p], pv[2 * p], pv[2 * p + 1]);
        pv[16] = q0;
        float m[17];
#pragma unroll
        for (int j = 0; j < 17; j++) m[j] = (2.f * tanh_fast(pv[j]) - 1.f) * xd0[j];
        float* base = g_msg + (size_t)d0 * 64;
        red4(base + 0, m[0], m[1], m[2], m[3]);
        red4(base + 4, m[4], m[5], m[6], m[7]);
        red4(base + 8, m[8], m[9], m[10], m[11]);
        red4(base + 12, m[12], m[13], m[14], m[15]);
        atomicAdd(base + 16, m[16]);
    }
    {
        float pv[17];
#pragma unroll
        for (int p = 0; p < 8; p++) unpack2(c1[p], pv[2 * p], pv[2 * p + 1]);
        pv[16] = q1;
        float m[17];
#pragma unroll
        for (int j = 0; j < 17; j++) m[j] = (2.f * tanh_fast(pv[j]) - 1.f) * xd1[j];
        float* base = g_msg + (size_t)d1 * 64;
        red4(base + 0, m[0], m[1], m[2], m[3]);
        red4(base + 4, m[4], m[5], m[6], m[7]);
        red4(base + 8, m[8], m[9], m[10], m[11]);
        red4(base + 12, m[12], m[13], m[14], m[15]);
        atomicAdd(base + 16, m[16]);
    }
}

// ---------------- node update + projection ----------------
__global__ void k_proj(const float* __restrict__ x, const float* __restrict__ PW,
                       const float* __restrict__ Pb) {
    __shared__ float sW[17 * 64];
    __shared__ float sB[64];
    int tid = threadIdx.x;
    for (int i = tid; i < 17 * 64; i += 256) sW[i] = PW[i];
    if (tid < 64) sB[tid] = Pb[tid];
    __syncthreads();

    int n = blockIdx.x * 256 + tid;
    if (n >= N_NODES) return;
    float rdeg = 1.f / fmaxf(g_deg[n], 1.f);

    float acc[64];
#pragma unroll
    for (int c = 0; c < 64; c++) acc[c] = sB[c];

#pragma unroll 1
    for (int k = 0; k < 17; k++) {
        size_t mo = (size_t)n * 64 + k;
        float xm = x[(size_t)n * 17 + k] + g_msg[mo] * rdeg;
        g_msg[mo] = 0.f;
        const float* w = &sW[k * 64];
#pragma unroll
        for (int c = 0; c < 64; c++) acc[c] += xm * w[c];
    }
    float* hp = g_h + (size_t)n * 64;
#pragma unroll
    for (int c = 0; c < 64; c++) hp[c] = acc[c];
}

// ---------------- stage 2 layer kernel: per-edge MLP 128 -> 64 -> 64 -------------
// 128 edges / block, 256 threads. thread (lane,cg): edges lane+32j (j<4),
// cols 8cg..8cg+7 as 4 f32x2 pairs. M edge-major stride 132, H stride 68.
#define LK_SMEM_FLOATS 38272
__global__ __launch_bounds__(256, 1)
void k_layer(const float* __restrict__ W1, const float* __restrict__ b1,
             const float* __restrict__ W2, const float* __restrict__ b2) {
    extern __shared__ float sm[];
    const int OW1 = 0, OW2 = 8192, OB1 = 12288, OB2 = 12352;
    const int OM = 12416;       // 128 x 132
    const int OH = 29312;       // 128 x 68
    const int ODST = 38016, OSRC = 38144;

    int tid = threadIdx.x;
    for (int i = tid; i < 8192; i += 256) sm[OW1 + i] = W1[i];
    for (int i = tid; i < 4096; i += 256) sm[OW2 + i] = W2[i];
    if (tid < 64) { sm[OB1 + tid] = b1[tid]; sm[OB2 + tid] = b2[tid]; }
    int* sD = (int*)(sm + ODST);
    int* sS = (int*)(sm + OSRC);
    if (tid < 128) {
        int e = blockIdx.x * 128 + tid;
        sS[tid] = g_src[e];
        sD[tid] = g_dst[e];
    }
    __syncthreads();

    // gather m_in[e] = [h[dst] | h[src]]
    for (int t = tid; t < 4096; t += 256) {
        int e = t >> 5, q = t & 31, qq = q & 15;
        int row = (q < 16) ? sD[e] : sS[e];
        const float4 v = *(const float4*)(g_h + (size_t)row * 64 + qq * 4);
        *(float4*)(sm + OM + e * 132 + ((q < 16) ? 0 : 64) + qq * 4) = v;
    }
    __syncthreads();

    int lane = tid & 31, cg = tid >> 5;      // cg 0..7
    const float* pM0 = sm + OM + lane * 132; // edge lane+32j at +j*4224
    float* pH0 = sm + OH + lane * 68;        // edge lane+32j at +j*2176

    ull acc[4][4];
    {
        const ull* bp = (const ull*)(sm + OB1 + 8 * cg);
#pragma unroll
        for (int j = 0; j < 4; j++)
#pragma unroll
            for (int p = 0; p < 4; p++) acc[j][p] = bp[p];
    }

#pragma unroll 4
    for (int k = 0; k < 128; k += 4) {
        ull w[4][4];
#pragma unroll
        for (int r = 0; r < 4; r++) {
            const ulonglong2* wp = (const ulonglong2*)(sm + OW1 + (k + r) * 64 + 8 * cg);
            ulonglong2 wa = wp[0], wb = wp[1];
            w[r][0] = wa.x; w[r][1] = wa.y; w[r][2] = wb.x; w[r][3] = wb.y;
        }
#pragma unroll
        for (int j = 0; j < 4; j++) {
            float4 mf = *(const float4*)(pM0 + j * 4224 + k);
            ull m0 = pack2(mf.x), m1 = pack2(mf.y), m2 = pack2(mf.z), m3 = pack2(mf.w);
#pragma unroll
            for (int p = 0; p < 4; p++) {
                fma2(acc[j][p], m0, w[0][p]);
                fma2(acc[j][p], m1, w[1][p]);
                fma2(acc[j][p], m2, w[2][p]);
                fma2(acc[j][p], m3, w[3][p]);
            }
        }
    }

    // relu -> H
#pragma unroll
    for (int j = 0; j < 4; j++) {
        float h[8];
#pragma unroll
        for (int p = 0; p < 4; p++) unpack2(acc[j][p], h[2 * p], h[2 * p + 1]);
#pragma unroll
        for (int c = 0; c < 8; c++) h[c] = fmaxf(h[c], 0.f);
        *(float4*)(pH0 + j * 2176 + 8 * cg) = make_float4(h[0], h[1], h[2], h[3]);
        *(float4*)(pH0 + j * 2176 + 8 * cg + 4) = make_float4(h[4], h[5], h[6], h[7]);
    }
    __syncthreads();

    ull acc2[4][4];
    {
        const ull* bp = (const ull*)(sm + OB2 + 8 * cg);
#pragma unroll
        for (int j = 0; j < 4; j++)
#pragma unroll
            for (int p = 0; p < 4; p++) acc2[j][p] = bp[p];
    }

#pragma unroll 4
    for (int k = 0; k < 64; k += 4) {
        ull w[4][4];
#pragma unroll
        for (int r = 0; r < 4; r++) {
            const ulonglong2* wp = (const ulonglong2*)(sm + OW2 + (k + r) * 64 + 8 * cg);
            ulonglong2 wa = wp[0], wb = wp[1];
            w[r][0] = wa.x; w[r][1] = wa.y; w[r][2] = wb.x; w[r][3] = wb.y;
        }
#pragma unroll
        for (int j = 0; j < 4; j++) {
            float4 mf = *(const float4*)(pH0 + j * 2176 + k);
            ull m0 = pack2(mf.x), m1 = pack2(mf.y), m2 = pack2(mf.z), m3 = pack2(mf.w);
#pragma unroll
            for (int p = 0; p < 4; p++) {
                fma2(acc2[j][p], m0, w[0][p]);
                fma2(acc2[j][p], m1, w[1][p]);
                fma2(acc2[j][p], m2, w[2][p]);
                fma2(acc2[j][p], m3, w[3][p]);
            }
        }
    }

    // msg = (2*tanh(p)-1) * h_dst -> vector reductions
#pragma unroll
    for (int j = 0; j < 4; j++) {
        int dn = sD[lane + 32 * j];
        float pv[8];
#pragma unroll
        for (int p = 0; p < 4; p++) unpack2(acc2[j][p], pv[2 * p], pv[2 * p + 1]);
        float4 hd0 = *(const float4*)(pM0 + j * 4224 + 8 * cg);
        float4 hd1 = *(const float4*)(pM0 + j * 4224 + 8 * cg + 4);
        float v0 = (2.f * tanh_fast(pv[0]) - 1.f) * hd0.x;
        float v1 = (2.f * tanh_fast(pv[1]) - 1.f) * hd0.y;
        float v2 = (2.f * tanh_fast(pv[2]) - 1.f) * hd0.z;
        float v3 = (2.f * tanh_fast(pv[3]) - 1.f) * hd0.w;
        float v4 = (2.f * tanh_fast(pv[4]) - 1.f) * hd1.x;
        float v5 = (2.f * tanh_fast(pv[5]) - 1.f) * hd1.y;
        float v6 = (2.f * tanh_fast(pv[6]) - 1.f) * hd1.z;
        float v7 = (2.f * tanh_fast(pv[7]) - 1.f) * hd1.w;
        float* base = g_msg + (size_t)dn * 64 + 8 * cg;
        red4(base, v0, v1, v2, v3);
        red4(base + 4, v4, v5, v6, v7);
    }
}

// ---------------- node update + BN partial stats ----------------
__global__ void k_update(int statOff) {
    float* stats = g_stats + statOff;
    int tid = threadIdx.x;
    int c = tid & 63, sub = tid >> 6;
    int base = blockIdx.x * 256;
    float s = 0.f, ss = 0.f;
    for (int i = 0; i < 64; i++) {
        int n = base + i * 4 + sub;
        if (n < N_NODES) {
            size_t o = (size_t)n * 64 + c;
            float rdeg = 1.f / fmaxf(g_deg[n], 1.f);
            float hv = g_h[o] + g_msg[o] * rdeg;
            g_h[o] = hv;
            g_msg[o] = 0.f;
            s += hv;
            ss += hv * hv;
        }
    }
    __shared__ float sA[256], sBm[256];
    sA[tid] = s; sBm[tid] = ss;
    __syncthreads();
    if (tid < 64) {
        s  = sA[tid] + sA[tid + 64] + sA[tid + 128] + sA[tid + 192];
        ss = sBm[tid] + sBm[tid + 64] + sBm[tid + 128] + sBm[tid + 192];
        atomicAdd(&stats[c], s);
        atomicAdd(&stats[64 + c], ss);
    }
}

// ---------------- BN apply + relu ----------------
__global__ void k_bnrelu(int statOff, const float* __restrict__ g, const float* __restrict__ b) {
    const float* stats = g_stats + statOff;
    int idx = blockIdx.x * 256 + threadIdx.x;
    int c0 = (idx & 15) * 4;
    const float invn = 1.f / (float)N_NODES;
    float4* hp = ((float4*)g_h) + idx;
    float4 v = *hp;
    float o[4] = {v.x, v.y, v.z, v.w};
#pragma unroll
    for (int i = 0; i < 4; i++) {
        float m = stats[c0 + i] * invn;
        float var = stats[64 + c0 + i] * invn - m * m;
        float sc = rsqrtf(var + BN_EPS) * g[c0 + i];
        o[i] = fmaxf((o[i] - m) * sc + b[c0 + i], 0.f);
    }
    v.x = o[0]; v.y = o[1]; v.z = o[2]; v.w = o[3];
    *hp = v;
}

// ---------------- classifier ----------------
__global__ void k_clf1(const float* __restrict__ W, const float* __restrict__ b) {
    __shared__ float sW[4096], sB[64];
    int tid = threadIdx.x;
    for (int i = tid; i < 4096; i += 256) sW[i] = W[i];
    if (tid < 64) sB[tid] = b[tid];
    __syncthreads();
    int r = blockIdx.x * 256 + tid;
    if (r >= BATCH) return;
    float acc[64];
#pragma unroll
    for (int c = 0; c < 64; c++) acc[c] = sB[c];
#pragma unroll 1
    for (int k = 0; k < 64; k++) {
        float hk = g_h[(size_t)r * 64 + k];
        const float* w = &sW[k * 64];
#pragma unroll
        for (int c = 0; c < 64; c++) acc[c] += hk * w[c];
    }
    float* z = g_z1 + (size_t)r * 64;
    float* st = g_stats + 256;
#pragma unroll 1
    for (int c = 0; c < 64; c++) {
        z[c] = acc[c];
        atomicAdd(&st[c], acc[c]);
        atomicAdd(&st[64 + c], acc[c] * acc[c]);
    }
}

__global__ void k_clf2(const float* __restrict__ W, const float* __restrict__ b,
                       const float* __restrict__ g1, const float* __restrict__ bb1) {
    __shared__ float sW[2048], sB[32], sScale[64], sBias[64];
    int tid = threadIdx.x;
    for (int i = tid; i < 2048; i += 256) sW[i] = W[i];
    if (tid < 32) sB[tid] = b[tid];
    if (tid < 64) {
        const float invn = 1.f / (float)BATCH;
        float m = g_stats[256 + tid] * invn;
        float var = g_stats[256 + 64 + tid] * invn - m * m;
        float sc = rsqrtf(var + BN_EPS) * g1[tid];
        sScale[tid] = sc;
        sBias[tid] = bb1[tid] - m * sc;
    }
    __syncthreads();
    int r = blockIdx.x * 256 + tid;
    if (r >= BATCH) return;
    float acc[32];
#pragma unroll
    for (int c = 0; c < 32; c++) acc[c] = sB[c];
#pragma unroll 1
    for (int k = 0; k < 64; k++) {
        float v = fmaxf(g_z1[(size_t)r * 64 + k] * sScale[k] + sBias[k], 0.f);
        const float* w = &sW[k * 32];
#pragma unroll
        for (int c = 0; c < 32; c++) acc[c] += v * w[c];
    }
    float* z = g_z2 + (size_t)r * 32;
    float* st = g_stats + 384;
#pragma unroll 1
    for (int c = 0; c < 32; c++) {
        z[c] = acc[c];
        atomicAdd(&st[c], acc[c]);
        atomicAdd(&st[32 + c], acc[c] * acc[c]);
    }
}

__global__ void k_clf3(const float* __restrict__ W3, const float* __restrict__ b3,
                       const float* __restrict__ g2, const float* __restrict__ bb2,
                       float* __restrict__ out) {
    __shared__ float sW[32], sScale[32], sBias[32], sb3;
    int tid = threadIdx.x;
    if (tid < 32) {
        sW[tid] = W3[tid];
        const float invn = 1.f / (float)BATCH;
        float m = g_stats[384 + tid] * invn;
        float var = g_stats[384 + 32 + tid] * invn - m * m;
        float sc = rsqrtf(var + BN_EPS) * g2[tid];
        sScale[tid] = sc;
        sBias[tid] = bb2[tid] - m * sc;
    }
    if (tid == 0) sb3 = b3[0];
    __syncthreads();
    int r = blockIdx.x * 256 + tid;
    if (r >= BATCH) return;
    float a = sb3;
#pragma unroll 1
    for (int k = 0; k < 32; k++)
        a += fmaxf(g_z2[(size_t)r * 32 + k] * sScale[k] + sBias[k], 0.f) * sW[k];
    out[r] = a;
}

// ---------------- launch ----------------
extern "C" void kernel_launch(void* const* d_in, const int* in_sizes, int n_in,
                              void* d_out, int out_size) {
    auto ix = [&](int i) { return (n_in >= 28) ? i : (i > 3 ? i - 1 : i); };
    const float* x    = (const float*)d_in[ix(0)];
    const void*  ei   = d_in[ix(1)];
    const float* dts  = (const float*)d_in[ix(2)];
    const float* bf   = (const float*)d_in[ix(4)];
    const float* ph   = (const float*)d_in[ix(5)];
    const float* tW1  = (const float*)d_in[ix(6)];
    const float* tb1  = (const float*)d_in[ix(7)];
    const float* tW2  = (const float*)d_in[ix(8)];
    const float* tb2  = (const float*)d_in[ix(9)];
    const float* pW   = (const float*)d_in[ix(10)];
    const float* pb   = (const float*)d_in[ix(11)];
    const float* sW1  = (const float*)d_in[ix(12)];
    const float* sb1  = (const float*)d_in[ix(13)];
    const float* sW2  = (const float*)d_in[ix(14)];
    const float* sb2  = (const float*)d_in[ix(15)];
    const float* bng  = (const float*)d_in[ix(16)];
    const float* bnb  = (const float*)d_in[ix(17)];
    const float* cW1  = (const float*)d_in[ix(18)];
    const float* cb1  = (const float*)d_in[ix(19)];
    const float* cg1  = (const float*)d_in[ix(20)];
    const float* cbb1 = (const float*)d_in[ix(21)];
    const float* cW2  = (const float*)d_in[ix(22)];
    const float* cb2  = (const float*)d_in[ix(23)];
    const float* cg2  = (const float*)d_in[ix(24)];
    const float* cbb2 = (const float*)d_in[ix(25)];
    const float* cW3  = (const float*)d_in[ix(26)];
    const float* cb3  = (const float*)d_in[ix(27)];
    float* out = (float*)d_out;

    const int LK_SMEM_BYTES = LK_SMEM_FLOATS * 4;  // 153088 B
    cudaFuncSetAttribute(k_layer, cudaFuncAttributeMaxDynamicSharedMemorySize, LK_SMEM_BYTES);

    k_zero_all<<<2048, 256>>>();
    k_convert_idx<<<N_EDGES / 256, 256>>>(ei);
    k_stage1<<<N_EDGES / 512, 256>>>(x, dts, bf, ph, tW1, tb1, tW2, tb2);
    k_proj<<<(N_NODES + 255) / 256, 256>>>(x, pW, pb);

    for (int l = 0; l < 2; l++) {
        k_layer<<<N_EDGES / 128, 256, LK_SMEM_BYTES>>>(sW1 + l * 8192, sb1 + l * 64,
                                                       sW2 + l * 4096, sb2 + l * 64);
        k_update<<<(N_NODES + 255) / 256, 256>>>(l * 128);
        k_bnrelu<<<(N_NODES * HID / 4) / 256, 256>>>(l * 128, bng + l * 64, bnb + l * 64);
    }

    k_clf1<<<(BATCH + 255) / 256, 256>>>(cW1, cb1);
    k_clf2<<<(BATCH + 255) / 256, 256>>>(cW2, cb2, cg1, cbb1);
    k_clf3<<<(BATCH + 255) / 256, 256>>>(cW3, cb3, cg2, cbb2, out);
    (void)in_sizes; (void)out_size;
}

// round 4
// speedup vs baseline: 1.2978x; 1.0611x over previous
#include <cuda_runtime.h>
#include <cstdint>

#define N_NODES 100000
#define N_EDGES 1600000
#define IN_CH   17
#define HID     64
#define BATCH   10000
#define BN_EPS  1e-5f

typedef unsigned long long ull;

// ---------------- device scratch ----------------
__device__ float g_h  [(size_t)N_NODES * HID];
__device__ float g_msg[(size_t)N_NODES * HID];
__device__ float g_deg[N_NODES];                 // raw degree, then inverted in-place
__device__ float g_stats[4 * 128];
__device__ float g_z1[BATCH * 64];
__device__ float g_z2[BATCH * 32];
__device__ int   g_src[N_EDGES];
__device__ int   g_dst[N_EDGES];

__device__ __forceinline__ float tanh_fast(float x) {
    float e = __expf(2.f * x);
    return 1.f - __fdividef(2.f, e + 1.f);
}
__device__ __forceinline__ ull pack2(float x) {
    ull r; asm("mov.b64 %0,{%1,%1};" : "=l"(r) : "f"(x)); return r;
}
__device__ __forceinline__ void unpack2(ull a, float& x, float& y) {
    asm("mov.b64 {%0,%1},%2;" : "=f"(x), "=f"(y) : "l"(a));
}
__device__ __forceinline__ void fma2(ull& d, ull a, ull b) {
    asm("fma.rn.f32x2 %0,%1,%2,%0;" : "+l"(d) : "l"(a), "l"(b));
}
__device__ __forceinline__ void red4(float* p, float a, float b, float c, float d) {
    asm volatile("{\n\t.reg .u64 q;\n\tcvta.to.global.u64 q,%0;\n\t"
                 "red.global.add.v4.f32 [q],{%1,%2,%3,%4};\n\t}"
                 :: "l"(p), "f"(a), "f"(b), "f"(c), "f"(d) : "memory");
}

// ---------------- edge index conversion + degree ----------------
__global__ void k_convert_idx(const void* __restrict__ ei_raw) {
    __shared__ int s_is64;
    if (threadIdx.x == 0) {
        const unsigned* w = (const unsigned*)ei_raw;
        int is64 = 1;
        for (int i = 1; i < 64; i += 2)
            if (w[i] != 0u) { is64 = 0; break; }
        s_is64 = is64;
    }
    __syncthreads();
    int e = blockIdx.x * 256 + threadIdx.x;
    if (e >= N_EDGES) return;
    int s, d;
    if (s_is64) {
        const long long* p = (const long long*)ei_raw;
        s = (int)p[e]; d = (int)p[(size_t)N_EDGES + e];
    } else {
        const int* p = (const int*)ei_raw;
        s = p[e]; d = p[N_EDGES + e];
    }
    g_src[e] = s; g_dst[e] = d;
    atomicAdd(&g_deg[d], 1.f);
}

// ---------------- zero scratch (vectorized) ----------------
__global__ void k_zero_all() {
    int i = blockIdx.x * 256 + threadIdx.x;
    int st = gridDim.x * 256;
    float4 z = make_float4(0.f, 0.f, 0.f, 0.f);
    float4* m4 = (float4*)g_msg;
    for (int k = i; k < N_NODES * HID / 4; k += st) m4[k] = z;
    for (int k = i; k < N_NODES; k += st) g_deg[k] = 0.f;
    if (i < 512) g_stats[i] = 0.f;
}

// ---------------- invert degree in place ----------------
__global__ void k_rdeg() {
    int n = blockIdx.x * 256 + threadIdx.x;
    if (n < N_NODES) g_deg[n] = 1.f / fmaxf(g_deg[n], 1.f);
}

// ---------------- stage 1: temporal edge MLP (66 -> 33 -> 17), 2 edges/thread ----
__global__ __launch_bounds__(256)
void k_stage1(const float* __restrict__ x,
              const float* __restrict__ dts, const float* __restrict__ bf,
              const float* __restrict__ ph,
              const float* __restrict__ W1, const float* __restrict__ b1,
              const float* __restrict__ W2, const float* __restrict__ b2) {
    __shared__ float sW1[66 * 36];
    __shared__ float sW2[33 * 20];
    __shared__ __align__(16) float sB1[34], sB2[18], sF[32], sP[32];
    int tid = threadIdx.x;
    for (int i = tid; i < 66 * 33; i += 256) {
        int r = i / 33, c = i - r * 33;
        sW1[r * 36 + c] = W1[i];
    }
    for (int i = tid; i < 33 * 17; i += 256) {
        int r = i / 17, c = i - r * 17;
        sW2[r * 20 + c] = W2[i];
    }
    if (tid < 33) sB1[tid] = b1[tid];
    if (tid < 17) sB2[tid] = b2[tid];
    if (tid < 32) { sF[tid] = bf[tid]; sP[tid] = ph[tid]; }
    __syncthreads();

    int e0 = blockIdx.x * 512 + tid;
    int e1 = e0 + 256;
    int s0 = g_src[e0], d0 = g_dst[e0];
    int s1 = g_src[e1], d1 = g_dst[e1];
    float dt0 = dts[e0], dt1 = dts[e1];

    const float* xd0 = x + (size_t)d0 * IN_CH;
    const float* xs0 = x + (size_t)s0 * IN_CH;
    const float* xd1 = x + (size_t)d1 * IN_CH;
    const float* xs1 = x + (size_t)s1 * IN_CH;

    ull a0[16], a1[16];
    float t0, t1;
    {
        const ull* bp = (const ull*)sB1;
#pragma unroll
        for (int p = 0; p < 16; p++) { a0[p] = bp[p]; a1[p] = bp[p]; }
        t0 = sB1[32]; t1 = sB1[32];
    }

#define S1_ROW(ROW, V0, V1)                                             \
    {                                                                   \
        ull m0 = pack2(V0), m1 = pack2(V1);                             \
        const ulonglong2* wp = (const ulonglong2*)(sW1 + (ROW) * 36);   \
        ulonglong2 wa = wp[0], wb = wp[1], wc = wp[2], wd = wp[3];      \
        ulonglong2 we = wp[4], wf = wp[5], wg = wp[6], wh = wp[7];      \
        fma2(a0[0], m0, wa.x);  fma2(a1[0], m1, wa.x);                  \
        fma2(a0[1], m0, wa.y);  fma2(a1[1], m1, wa.y);                  \
        fma2(a0[2], m0, wb.x);  fma2(a1[2], m1, wb.x);                  \
        fma2(a0[3], m0, wb.y);  fma2(a1[3], m1, wb.y);                  \
        fma2(a0[4], m0, wc.x);  fma2(a1[4], m1, wc.x);                  \
        fma2(a0[5], m0, wc.y);  fma2(a1[5], m1, wc.y);                  \
        fma2(a0[6], m0, wd.x);  fma2(a1[6], m1, wd.x);                  \
        fma2(a0[7], m0, wd.y);  fma2(a1[7], m1, wd.y);                  \
        fma2(a0[8], m0, we.x);  fma2(a1[8], m1, we.x);                  \
        fma2(a0[9], m0, we.y);  fma2(a1[9], m1, we.y);                  \
        fma2(a0[10], m0, wf.x); fma2(a1[10], m1, wf.x);                 \
        fma2(a0[11], m0, wf.y); fma2(a1[11], m1, wf.y);                 \
        fma2(a0[12], m0, wg.x); fma2(a1[12], m1, wg.x);                 \
        fma2(a0[13], m0, wg.y); fma2(a1[13], m1, wg.y);                 \
        fma2(a0[14], m0, wh.x); fma2(a1[14], m1, wh.x);                 \
        fma2(a0[15], m0, wh.y); fma2(a1[15], m1, wh.y);                 \
        float ws = sW1[(ROW) * 36 + 32];                                \
        t0 = fmaf(V0, ws, t0); t1 = fmaf(V1, ws, t1);                   \
    }

#pragma unroll 1
    for (int i = 0; i < 17; i++) { float v0 = xd0[i], v1 = xd1[i]; S1_ROW(i, v0, v1); }
#pragma unroll 1
    for (int i = 0; i < 17; i++) { float v0 = xs0[i], v1 = xs1[i]; S1_ROW(17 + i, v0, v1); }
#pragma unroll 1
    for (int t = 0; t < 32; t++) {
        float f = sF[t], p = sP[t];
        float v0 = __cosf(dt0 * f + p);
        float v1 = __cosf(dt1 * f + p);
        S1_ROW(34 + t, v0, v1);
    }

    float h0[33], h1[33];
#pragma unroll
    for (int p = 0; p < 16; p++) {
        unpack2(a0[p], h0[2 * p], h0[2 * p + 1]);
        unpack2(a1[p], h1[2 * p], h1[2 * p + 1]);
    }
    h0[32] = t0; h1[32] = t1;
#pragma unroll
    for (int i = 0; i < 33; i++) { h0[i] = fmaxf(h0[i], 0.f); h1[i] = fmaxf(h1[i], 0.f); }

    ull c0[8], c1[8]; float q0, q1;
    {
        const ull* bp = (const ull*)sB2;
#pragma unroll
        for (int p = 0; p < 8; p++) { c0[p] = bp[p]; c1[p] = bp[p]; }
        q0 = sB2[16]; q1 = sB2[16];
    }
#pragma unroll 1
    for (int i = 0; i < 33; i++) {
        ull m0 = pack2(h0[i]), m1 = pack2(h1[i]);
        const ulonglong2* wp = (const ulonglong2*)(sW2 + i * 20);
        ulonglong2 wa = wp[0], wb = wp[1], wc = wp[2], wd = wp[3];
        fma2(c0[0], m0, wa.x); fma2(c1[0], m1, wa.x);
        fma2(c0[1], m0, wa.y); fma2(c1[1], m1, wa.y);
        fma2(c0[2], m0, wb.x); fma2(c1[2], m1, wb.x);
        fma2(c0[3], m0, wb.y); fma2(c1[3], m1, wb.y);
        fma2(c0[4], m0, wc.x); fma2(c1[4], m1, wc.x);
        fma2(c0[5], m0, wc.y); fma2(c1[5], m1, wc.y);
        fma2(c0[6], m0, wd.x); fma2(c1[6], m1, wd.x);
        fma2(c0[7], m0, wd.y); fma2(c1[7], m1, wd.y);
        float ws = sW2[i * 20 + 16];
        q0 = fmaf(h0[i], ws, q0); q1 = fmaf(h1[i], ws, q1);
    }

    {
        float pv[17];
#pragma unroll
        for (int p = 0; p < 8; p++) unpack2(c0[p], pv[2 * p], pv[2 * p + 1]);
        pv[16] = q0;
        float m[17];
#pragma unroll
        for (int j = 0; j < 17; j++) m[j] = (2.f * tanh_fast(pv[j]) - 1.f) * xd0[j];
        float* base = g_msg + (size_t)d0 * 64;
        red4(base + 0, m[0], m[1], m[2], m[3]);
        red4(base + 4, m[4], m[5], m[6], m[7]);
        red4(base + 8, m[8], m[9], m[10], m[11]);
        red4(base + 12, m[12], m[13], m[14], m[15]);
        atomicAdd(base + 16, m[16]);
    }
    {
        float pv[17];
#pragma unroll
        for (int p = 0; p < 8; p++) unpack2(c1[p], pv[2 * p], pv[2 * p + 1]);
        pv[16] = q1;
        float m[17];
#pragma unroll
        for (int j = 0; j < 17; j++) m[j] = (2.f * tanh_fast(pv[j]) - 1.f) * xd1[j];
        float* base = g_msg + (size_t)d1 * 64;
        red4(base + 0, m[0], m[1], m[2], m[3]);
        red4(base + 4, m[4], m[5], m[6], m[7]);
        red4(base + 8, m[8], m[9], m[10], m[11]);
        red4(base + 12, m[12], m[13], m[14], m[15]);
        atomicAdd(base + 16, m[16]);
    }
}

// ---------------- node update + projection: h = (x + msg*rdeg) @ PW + Pb ----------
// 2 threads per node, 32 cols each (16 f32x2 accumulators). 128 nodes/block.
__global__ __launch_bounds__(256)
void k_proj(const float* __restrict__ x, const float* __restrict__ PW,
            const float* __restrict__ Pb) {
    __shared__ float sW[17 * 64];
    __shared__ __align__(16) float sB[64];
    int tid = threadIdx.x;
    for (int i = tid; i < 17 * 64; i += 256) sW[i] = PW[i];
    if (tid < 64) sB[tid] = Pb[tid];
    __syncthreads();

    int n = blockIdx.x * 128 + (tid >> 1);
    int q = tid & 1;
    if (n >= N_NODES) return;
    float rdeg = g_deg[n];   // already inverted

    ull acc[16];
    {
        const ull* bp = (const ull*)(sB + 32 * q);
#pragma unroll
        for (int p = 0; p < 16; p++) acc[p] = bp[p];
    }

    const float* xp = x + (size_t)n * 17;
    float* mp = g_msg + (size_t)n * 64;

#pragma unroll 1
    for (int k = 0; k < 17; k++) {
        float xm = xp[k] + mp[k] * rdeg;
        ull m = pack2(xm);
        const ulonglong2* wp = (const ulonglong2*)(sW + k * 64 + 32 * q);
#pragma unroll
        for (int h = 0; h < 8; h++) {
            ulonglong2 w = wp[h];
            fma2(acc[2 * h], m, w.x);
            fma2(acc[2 * h + 1], m, w.y);
        }
    }

    float* hp = g_h + (size_t)n * 64 + 32 * q;
#pragma unroll
    for (int h = 0; h < 8; h++) {
        float a, b2, c, d;
        unpack2(acc[2 * h], a, b2);
        unpack2(acc[2 * h + 1], c, d);
        *(float4*)(hp + 4 * h) = make_float4(a, b2, c, d);
    }
    // re-zero msg cols 0..16 (cols 17..63 still zero from init)
    if (q == 0) {
        float4 z = make_float4(0.f, 0.f, 0.f, 0.f);
        *(float4*)(mp + 0) = z; *(float4*)(mp + 4) = z;
        *(float4*)(mp + 8) = z; *(float4*)(mp + 12) = z;
        mp[16] = 0.f;
    }
}

// ---------------- stage 2 layer kernel: per-edge MLP 128 -> 64 -> 64 -------------
// 128 edges / block, 512 threads (16 warps). thread (lane, cg, eh):
// edges lane+32*(2eh+j) j<2, cols 8cg..8cg+7 as 4 f32x2 pairs.
#define LK_SMEM_FLOATS 38272
__global__ __launch_bounds__(512, 1)
void k_layer(const float* __restrict__ W1, const float* __restrict__ b1,
             const float* __restrict__ W2, const float* __restrict__ b2) {
    extern __shared__ float sm[];
    const int OW1 = 0, OW2 = 8192, OB1 = 12288, OB2 = 12352;
    const int OM = 12416;       // 128 x 132
    const int OH = 29312;       // 128 x 68
    const int ODST = 38016, OSRC = 38144;

    int tid = threadIdx.x;
    for (int i = tid; i < 8192; i += 512) sm[OW1 + i] = W1[i];
    for (int i = tid; i < 4096; i += 512) sm[OW2 + i] = W2[i];
    if (tid < 64) { sm[OB1 + tid] = b1[tid]; sm[OB2 + tid] = b2[tid]; }
    int* sD = (int*)(sm + ODST);
    int* sS = (int*)(sm + OSRC);
    if (tid < 128) {
        int e = blockIdx.x * 128 + tid;
        sS[tid] = g_src[e];
        sD[tid] = g_dst[e];
    }
    __syncthreads();

    // gather m_in[e] = [h[dst] | h[src]]
    for (int t = tid; t < 4096; t += 512) {
        int e = t >> 5, q = t & 31, qq = q & 15;
        int row = (q < 16) ? sD[e] : sS[e];
        const float4 v = *(const float4*)(g_h + (size_t)row * 64 + qq * 4);
        *(float4*)(sm + OM + e * 132 + ((q < 16) ? 0 : 64) + qq * 4) = v;
    }
    __syncthreads();

    int lane = tid & 31;
    int cg = (tid >> 5) & 7;      // col group: cols 8cg..8cg+7
    int eh = tid >> 8;            // edge half: 0 or 1
    const float* pM0 = sm + OM + lane * 132;
    float* pH0 = sm + OH + lane * 68;

    ull acc[2][4];
    {
        const ull* bp = (const ull*)(sm + OB1 + 8 * cg);
#pragma unroll
        for (int j = 0; j < 2; j++)
#pragma unroll
            for (int p = 0; p < 4; p++) acc[j][p] = bp[p];
    }

#pragma unroll 4
    for (int k = 0; k < 128; k += 4) {
        ull w[4][4];
#pragma unroll
        for (int r = 0; r < 4; r++) {
            const ulonglong2* wp = (const ulonglong2*)(sm + OW1 + (k + r) * 64 + 8 * cg);
            ulonglong2 wa = wp[0], wb = wp[1];
            w[r][0] = wa.x; w[r][1] = wa.y; w[r][2] = wb.x; w[r][3] = wb.y;
        }
#pragma unroll
        for (int j = 0; j < 2; j++) {
            int jj = 2 * eh + j;
            float4 mf = *(const float4*)(pM0 + jj * 4224 + k);
            ull m0 = pack2(mf.x), m1 = pack2(mf.y), m2 = pack2(mf.z), m3 = pack2(mf.w);
#pragma unroll
            for (int p = 0; p < 4; p++) {
                fma2(acc[j][p], m0, w[0][p]);
                fma2(acc[j][p], m1, w[1][p]);
                fma2(acc[j][p], m2, w[2][p]);
                fma2(acc[j][p], m3, w[3][p]);
            }
        }
    }

    // relu -> H
#pragma unroll
    for (int j = 0; j < 2; j++) {
        int jj = 2 * eh + j;
        float h[8];
#pragma unroll
        for (int p = 0; p < 4; p++) unpack2(acc[j][p], h[2 * p], h[2 * p + 1]);
#pragma unroll
        for (int c = 0; c < 8; c++) h[c] = fmaxf(h[c], 0.f);
        *(float4*)(pH0 + jj * 2176 + 8 * cg) = make_float4(h[0], h[1], h[2], h[3]);
        *(float4*)(pH0 + jj * 2176 + 8 * cg + 4) = make_float4(h[4], h[5], h[6], h[7]);
    }
    __syncthreads();

    ull acc2[2][4];
    {
        const ull* bp = (const ull*)(sm + OB2 + 8 * cg);
#pragma unroll
        for (int j = 0; j < 2; j++)
#pragma unroll
            for (int p = 0; p < 4; p++) acc2[j][p] = bp[p];
    }

#pragma unroll 4
    for (int k = 0; k < 64; k += 4) {
        ull w[4][4];
#pragma unroll
        for (int r = 0; r < 4; r++) {
            const ulonglong2* wp = (const ulonglong2*)(sm + OW2 + (k + r) * 64 + 8 * cg);
            ulonglong2 wa = wp[0], wb = wp[1];
            w[r][0] = wa.x; w[r][1] = wa.y; w[r][2] = wb.x; w[r][3] = wb.y;
        }
#pragma unroll
        for (int j = 0; j < 2; j++) {
            int jj = 2 * eh + j;
            float4 mf = *(const float4*)(pH0 + jj * 2176 + k);
            ull m0 = pack2(mf.x), m1 = pack2(mf.y), m2 = pack2(mf.z), m3 = pack2(mf.w);
#pragma unroll
            for (int p = 0; p < 4; p++) {
                fma2(acc2[j][p], m0, w[0][p]);
                fma2(acc2[j][p], m1, w[1][p]);
                fma2(acc2[j][p], m2, w[2][p]);
                fma2(acc2[j][p], m3, w[3][p]);
            }
        }
    }

    // msg = (2*tanh(p)-1) * h_dst -> vector reductions
#pragma unroll
    for (int j = 0; j < 2; j++) {
        int jj = 2 * eh + j;
        int dn = sD[lane + 32 * jj];
        float pv[8];
#pragma unroll
        for (int p = 0; p < 4; p++) unpack2(acc2[j][p], pv[2 * p], pv[2 * p + 1]);
        float4 hd0 = *(const float4*)(pM0 + jj * 4224 + 8 * cg);
        float4 hd1 = *(const float4*)(pM0 + jj * 4224 + 8 * cg + 4);
        float v0 = (2.f * tanh_fast(pv[0]) - 1.f) * hd0.x;
        float v1 = (2.f * tanh_fast(pv[1]) - 1.f) * hd0.y;
        float v2 = (2.f * tanh_fast(pv[2]) - 1.f) * hd0.z;
        float v3 = (2.f * tanh_fast(pv[3]) - 1.f) * hd0.w;
        float v4 = (2.f * tanh_fast(pv[4]) - 1.f) * hd1.x;
        float v5 = (2.f * tanh_fast(pv[5]) - 1.f) * hd1.y;
        float v6 = (2.f * tanh_fast(pv[6]) - 1.f) * hd1.z;
        float v7 = (2.f * tanh_fast(pv[7]) - 1.f) * hd1.w;
        float* base = g_msg + (size_t)dn * 64 + 8 * cg;
        red4(base, v0, v1, v2, v3);
        red4(base + 4, v4, v5, v6, v7);
    }
}

// ---------------- node update (h += msg*rdeg), zero msg, BN partial stats ---------
// vectorized: 391 blocks x 256 threads, each thread 16 float4s (fixed col group)
__global__ __launch_bounds__(256)
void k_update(int statOff) {
    float* stats = g_stats + statOff;
    int tid = threadIdx.x;
    int base = blockIdx.x * 4096;
    float4* h4 = (float4*)g_h;
    float4* m4 = (float4*)g_msg;
    float s[4] = {0.f, 0.f, 0.f, 0.f}, ss[4] = {0.f, 0.f, 0.f, 0.f};
#pragma unroll 4
    for (int i = 0; i < 16; i++) {
        int idx = base + tid + i * 256;
        if (idx < N_NODES * 16) {
            int n = idx >> 4;
            float rdeg = g_deg[n];   // inverted
            float4 hv = h4[idx];
            float4 mv = m4[idx];
            hv.x += mv.x * rdeg; hv.y += mv.y * rdeg;
            hv.z += mv.z * rdeg; hv.w += mv.w * rdeg;
            h4[idx] = hv;
            m4[idx] = make_float4(0.f, 0.f, 0.f, 0.f);
            s[0] += hv.x; s[1] += hv.y; s[2] += hv.z; s[3] += hv.w;
            ss[0] += hv.x * hv.x; ss[1] += hv.y * hv.y;
            ss[2] += hv.z * hv.z; ss[3] += hv.w * hv.w;
        }
    }
    __shared__ float sA[256][4], sBm[256][4];
#pragma unroll
    for (int p = 0; p < 4; p++) { sA[tid][p] = s[p]; sBm[tid][p] = ss[p]; }
    __syncthreads();
    if (tid < 16) {
        float rs[4] = {0.f, 0.f, 0.f, 0.f}, rss[4] = {0.f, 0.f, 0.f, 0.f};
#pragma unroll
        for (int j = 0; j < 16; j++) {
#pragma unroll
            for (int p = 0; p < 4; p++) {
                rs[p] += sA[tid + 16 * j][p];
                rss[p] += sBm[tid + 16 * j][p];
            }
        }
        int c0 = tid * 4;
#pragma unroll
        for (int p = 0; p < 4; p++) {
            atomicAdd(&stats[c0 + p], rs[p]);
            atomicAdd(&stats[64 + c0 + p], rss[p]);
        }
    }
}

// ---------------- BN apply + relu ----------------
__global__ void k_bnrelu(int statOff, const float* __restrict__ g, const float* __restrict__ b) {
    const float* stats = g_stats + statOff;
    int idx = blockIdx.x * 256 + threadIdx.x;
    int c0 = (idx & 15) * 4;
    const float invn = 1.f / (float)N_NODES;
    float4* hp = ((float4*)g_h) + idx;
    float4 v = *hp;
    float o[4] = {v.x, v.y, v.z, v.w};
#pragma unroll
    for (int i = 0; i < 4; i++) {
        float m = stats[c0 + i] * invn;
        float var = stats[64 + c0 + i] * invn - m * m;
        float sc = rsqrtf(var + BN_EPS) * g[c0 + i];
        o[i] = fmaxf((o[i] - m) * sc + b[c0 + i], 0.f);
    }
    v.x = o[0]; v.y = o[1]; v.z = o[2]; v.w = o[3];
    *hp = v;
}

// ---------------- classifier ----------------
__global__ void k_clf1(const float* __restrict__ W, const float* __restrict__ b) {
    __shared__ float sW[4096], sB[64];
    int tid = threadIdx.x;
    for (int i = tid; i < 4096; i += 256) sW[i] = W[i];
    if (tid < 64) sB[tid] = b[tid];
    __syncthreads();
    int r = blockIdx.x * 256 + tid;
    if (r >= BATCH) return;
    float acc[64];
#pragma unroll
    for (int c = 0; c < 64; c++) acc[c] = sB[c];
#pragma unroll 1
    for (int k = 0; k < 64; k++) {
        float hk = g_h[(size_t)r * 64 + k];
        const float* w = &sW[k * 64];
#pragma unroll
        for (int c = 0; c < 64; c++) acc[c] += hk * w[c];
    }
    float* z = g_z1 + (size_t)r * 64;
    float* st = g_stats + 256;
#pragma unroll 1
    for (int c = 0; c < 64; c++) {
        z[c] = acc[c];
        atomicAdd(&st[c], acc[c]);
        atomicAdd(&st[64 + c], acc[c] * acc[c]);
    }
}

__global__ void k_clf2(const float* __restrict__ W, const float* __restrict__ b,
                       const float* __restrict__ g1, const float* __restrict__ bb1) {
    __shared__ float sW[2048], sB[32], sScale[64], sBias[64];
    int tid = threadIdx.x;
    for (int i = tid; i < 2048; i += 256) sW[i] = W[i];
    if (tid < 32) sB[tid] = b[tid];
    if (tid < 64) {
        const float invn = 1.f / (float)BATCH;
        float m = g_stats[256 + tid] * invn;
        float var = g_stats[256 + 64 + tid] * invn - m * m;
        float sc = rsqrtf(var + BN_EPS) * g1[tid];
        sScale[tid] = sc;
        sBias[tid] = bb1[tid] - m * sc;
    }
    __syncthreads();
    int r = blockIdx.x * 256 + tid;
    if (r >= BATCH) return;
    float acc[32];
#pragma unroll
    for (int c = 0; c < 32; c++) acc[c] = sB[c];
#pragma unroll 1
    for (int k = 0; k < 64; k++) {
        float v = fmaxf(g_z1[(size_t)r * 64 + k] * sScale[k] + sBias[k], 0.f);
        const float* w = &sW[k * 32];
#pragma unroll
        for (int c = 0; c < 32; c++) acc[c] += v * w[c];
    }
    float* z = g_z2 + (size_t)r * 32;
    float* st = g_stats + 384;
#pragma unroll 1
    for (int c = 0; c < 32; c++) {
        z[c] = acc[c];
        atomicAdd(&st[c], acc[c]);
        atomicAdd(&st[32 + c], acc[c] * acc[c]);
    }
}

__global__ void k_clf3(const float* __restrict__ W3, const float* __restrict__ b3,
                       const float* __restrict__ g2, const float* __restrict__ bb2,
                       float* __restrict__ out) {
    __shared__ float sW[32], sScale[32], sBias[32], sb3;
    int tid = threadIdx.x;
    if (tid < 32) {
        sW[tid] = W3[tid];
        const float invn = 1.f / (float)BATCH;
        float m = g_stats[384 + tid] * invn;
        float var = g_stats[384 + 32 + tid] * invn - m * m;
        float sc = rsqrtf(var + BN_EPS) * g2[tid];
        sScale[tid] = sc;
        sBias[tid] = bb2[tid] - m * sc;
    }
    if (tid == 0) sb3 = b3[0];
    __syncthreads();
    int r = blockIdx.x * 256 + tid;
    if (r >= BATCH) return;
    float a = sb3;
#pragma unroll 1
    for (int k = 0; k < 32; k++)
        a += fmaxf(g_z2[(size_t)r * 32 + k] * sScale[k] + sBias[k], 0.f) * sW[k];
    out[r] = a;
}

// ---------------- launch ----------------
extern "C" void kernel_launch(void* const* d_in, const int* in_sizes, int n_in,
                              void* d_out, int out_size) {
    auto ix = [&](int i) { return (n_in >= 28) ? i : (i > 3 ? i - 1 : i); };
    const float* x    = (const float*)d_in[ix(0)];
    const void*  ei   = d_in[ix(1)];
    const float* dts  = (const float*)d_in[ix(2)];
    const float* bf   = (const float*)d_in[ix(4)];
    const float* ph   = (const float*)d_in[ix(5)];
    const float* tW1  = (const float*)d_in[ix(6)];
    const float* tb1  = (const float*)d_in[ix(7)];
    const float* tW2  = (const float*)d_in[ix(8)];
    const float* tb2  = (const float*)d_in[ix(9)];
    const float* pW   = (const float*)d_in[ix(10)];
    const float* pb   = (const float*)d_in[ix(11)];
    const float* sW1  = (const float*)d_in[ix(12)];
    const float* sb1  = (const float*)d_in[ix(13)];
    const float* sW2  = (const float*)d_in[ix(14)];
    const float* sb2  = (const float*)d_in[ix(15)];
    const float* bng  = (const float*)d_in[ix(16)];
    const float* bnb  = (const float*)d_in[ix(17)];
    const float* cW1  = (const float*)d_in[ix(18)];
    const float* cb1  = (const float*)d_in[ix(19)];
    const float* cg1  = (const float*)d_in[ix(20)];
    const float* cbb1 = (const float*)d_in[ix(21)];
    const float* cW2  = (const float*)d_in[ix(22)];
    const float* cb2  = (const float*)d_in[ix(23)];
    const float* cg2  = (const float*)d_in[ix(24)];
    const float* cbb2 = (const float*)d_in[ix(25)];
    const float* cW3  = (const float*)d_in[ix(26)];
    const float* cb3  = (const float*)d_in[ix(27)];
    float* out = (float*)d_out;

    const int LK_SMEM_BYTES = LK_SMEM_FLOATS * 4;  // 153088 B
    cudaFuncSetAttribute(k_layer, cudaFuncAttributeMaxDynamicSharedMemorySize, LK_SMEM_BYTES);

    k_zero_all<<<1024, 256>>>();
    k_convert_idx<<<N_EDGES / 256, 256>>>(ei);
    k_rdeg<<<(N_NODES + 255) / 256, 256>>>();
    k_stage1<<<N_EDGES / 512, 256>>>(x, dts, bf, ph, tW1, tb1, tW2, tb2);
    k_proj<<<(N_NODES + 127) / 128, 256>>>(x, pW, pb);

    for (int l = 0; l < 2; l++) {
        k_layer<<<N_EDGES / 128, 512, LK_SMEM_BYTES>>>(sW1 + l * 8192, sb1 + l * 64,
                                                       sW2 + l * 4096, sb2 + l * 64);
        k_update<<<(N_NODES * 16 + 4095) / 4096, 256>>>(l * 128);
        k_bnrelu<<<(N_NODES * HID / 4) / 256, 256>>>(l * 128, bng + l * 64, bnb + l * 64);
    }

    k_clf1<<<(BATCH + 255) / 256, 256>>>(cW1, cb1);
    k_clf2<<<(BATCH + 255) / 256, 256>>>(cW2, cb2, cg1, cbb1);
    k_clf3<<<(BATCH + 255) / 256, 256>>>(cW3, cb3, cg2, cbb2, out);
    (void)in_sizes; (void)out_size;
}

// round 6
// speedup vs baseline: 1.4451x; 1.1135x over previous
#include <cuda_runtime.h>
#include <cuda_bf16.h>
#include <cstdint>

#define N_NODES 100000
#define N_EDGES 1600000
#define IN_CH   17
#define HID     64
#define BATCH   10000
#define BN_EPS  1e-5f

typedef unsigned long long ull;

// ---------------- device scratch ----------------
__device__ float g_h  [(size_t)N_NODES * HID];
__device__ float g_msg[(size_t)N_NODES * HID];
__device__ float g_deg[N_NODES];                 // raw degree, then inverted in-place
__device__ float g_stats[4 * 128];
__device__ float g_z1[BATCH * 64];
__device__ float g_z2[BATCH * 32];
__device__ int   g_src[N_EDGES];
__device__ int   g_dst[N_EDGES];
// pre-packed bf16 hi/lo weight images: W^T row-major [n][k], padded row strides
__device__ __align__(16) unsigned char g_B1hi[64 * 272];   // stride 272B (136 bf16)
__device__ __align__(16) unsigned char g_B1lo[64 * 272];
__device__ __align__(16) unsigned char g_B2hi[64 * 144];   // stride 144B (72 bf16)
__device__ __align__(16) unsigned char g_B2lo[64 * 144];

__device__ __forceinline__ float tanh_fast(float x) {
    float e = __expf(2.f * x);
    return 1.f - __fdividef(2.f, e + 1.f);
}
__device__ __forceinline__ ull pack2(float x) {
    ull r; asm("mov.b64 %0,{%1,%1};" : "=l"(r) : "f"(x)); return r;
}
__device__ __forceinline__ void unpack2(ull a, float& x, float& y) {
    asm("mov.b64 {%0,%1},%2;" : "=f"(x), "=f"(y) : "l"(a));
}
__device__ __forceinline__ void fma2(ull& d, ull a, ull b) {
    asm("fma.rn.f32x2 %0,%1,%2,%0;" : "+l"(d) : "l"(a), "l"(b));
}
__device__ __forceinline__ void red4(float* p, float a, float b, float c, float d) {
    asm volatile("{\n\t.reg .u64 q;\n\tcvta.to.global.u64 q,%0;\n\t"
                 "red.global.add.v4.f32 [q],{%1,%2,%3,%4};\n\t}"
                 :: "l"(p), "f"(a), "f"(b), "f"(c), "f"(d) : "memory");
}
__device__ __forceinline__ uint32_t smem_u32(const void* p) {
    uint32_t a;
    asm("{.reg .u64 t; cvta.to.shared.u64 t, %1; cvt.u32.u64 %0, t;}" : "=r"(a) : "l"(p));
    return a;
}
__device__ __forceinline__ void ldx4(uint32_t* r, uint32_t a) {
    asm volatile("ldmatrix.sync.aligned.m8n8.x4.shared.b16 {%0,%1,%2,%3}, [%4];"
                 : "=r"(r[0]), "=r"(r[1]), "=r"(r[2]), "=r"(r[3]) : "r"(a));
}
__device__ __forceinline__ void mma16816(float* d, const uint32_t* a, uint32_t b0, uint32_t b1) {
    asm volatile("mma.sync.aligned.m16n8k16.row.col.f32.bf16.bf16.f32 "
                 "{%0,%1,%2,%3},{%4,%5,%6,%7},{%8,%9},{%0,%1,%2,%3};"
                 : "+f"(d[0]), "+f"(d[1]), "+f"(d[2]), "+f"(d[3])
                 : "r"(a[0]), "r"(a[1]), "r"(a[2]), "r"(a[3]), "r"(b0), "r"(b1));
}
__device__ __forceinline__ void split2(float x, float y, uint32_t& hi, uint32_t& lo) {
    __nv_bfloat162 h = __float22bfloat162_rn(make_float2(x, y));
    float2 hf = __bfloat1622float2(h);
    __nv_bfloat162 l = __float22bfloat162_rn(make_float2(x - hf.x, y - hf.y));
    hi = *(uint32_t*)&h; lo = *(uint32_t*)&l;
}

// ---------------- edge index conversion + degree ----------------
__global__ void k_convert_idx(const void* __restrict__ ei_raw) {
    __shared__ int s_is64;
    if (threadIdx.x == 0) {
        const unsigned* w = (const unsigned*)ei_raw;
        int is64 = 1;
        for (int i = 1; i < 64; i += 2)
            if (w[i] != 0u) { is64 = 0; break; }
        s_is64 = is64;
    }
    __syncthreads();
    int e = blockIdx.x * 256 + threadIdx.x;
    if (e >= N_EDGES) return;
    int s, d;
    if (s_is64) {
        const long long* p = (const long long*)ei_raw;
        s = (int)p[e]; d = (int)p[(size_t)N_EDGES + e];
    } else {
        const int* p = (const int*)ei_raw;
        s = p[e]; d = p[N_EDGES + e];
    }
    g_src[e] = s; g_dst[e] = d;
    atomicAdd(&g_deg[d], 1.f);
}

// ---------------- zero scratch (vectorized) ----------------
__global__ void k_zero_all() {
    int i = blockIdx.x * 256 + threadIdx.x;
    int st = gridDim.x * 256;
    float4 z = make_float4(0.f, 0.f, 0.f, 0.f);
    float4* m4 = (float4*)g_msg;
    for (int k = i; k < N_NODES * HID / 4; k += st) m4[k] = z;
    for (int k = i; k < N_NODES; k += st) g_deg[k] = 0.f;
    if (i < 512) g_stats[i] = 0.f;
}

// ---------------- invert degree in place ----------------
__global__ void k_rdeg() {
    int n = blockIdx.x * 256 + threadIdx.x;
    if (n < N_NODES) g_deg[n] = 1.f / fmaxf(g_deg[n], 1.f);
}

// ---------------- weight prep: W^T -> bf16 hi/lo padded row-major images ----------
__global__ void k_prep_w(const float* __restrict__ W1, const float* __restrict__ W2) {
    int idx = blockIdx.x * 256 + threadIdx.x;
    if (idx < 8192) {                 // B1[n][k] = W1[k*64+n], n<64, k<128
        int n = idx >> 7, k = idx & 127;
        float w = W1[k * 64 + n];
        __nv_bfloat16 h = __float2bfloat16_rn(w);
        __nv_bfloat16 l = __float2bfloat16_rn(w - __bfloat162float(h));
        uint32_t off = (uint32_t)n * 272u + 2u * (uint32_t)k;
        *(__nv_bfloat16*)(g_B1hi + off) = h;
        *(__nv_bfloat16*)(g_B1lo + off) = l;
    }
    if (idx < 4096) {                 // B2[n][k] = W2[k*64+n], n<64, k<64
        int n = idx >> 6, k = idx & 63;
        float w = W2[k * 64 + n];
        __nv_bfloat16 h = __float2bfloat16_rn(w);
        __nv_bfloat16 l = __float2bfloat16_rn(w - __bfloat162float(h));
        uint32_t off = (uint32_t)n * 144u + 2u * (uint32_t)k;
        *(__nv_bfloat16*)(g_B2hi + off) = h;
        *(__nv_bfloat16*)(g_B2lo + off) = l;
    }
}

// ---------------- stage 1: temporal edge MLP (66 -> 33 -> 17), 2 edges/thread ----
__global__ __launch_bounds__(256)
void k_stage1(const float* __restrict__ x,
              const float* __restrict__ dts, const float* __restrict__ bf,
              const float* __restrict__ ph,
              const float* __restrict__ W1, const float* __restrict__ b1,
              const float* __restrict__ W2, const float* __restrict__ b2) {
    __shared__ float sW1[66 * 36];
    __shared__ float sW2[33 * 20];
    __shared__ __align__(16) float sB1[34], sB2[18], sF[32], sP[32];
    int tid = threadIdx.x;
    for (int i = tid; i < 66 * 33; i += 256) {
        int r = i / 33, c = i - r * 33;
        sW1[r * 36 + c] = W1[i];
    }
    for (int i = tid; i < 33 * 17; i += 256) {
        int r = i / 17, c = i - r * 17;
        sW2[r * 20 + c] = W2[i];
    }
    if (tid < 33) sB1[tid] = b1[tid];
    if (tid < 17) sB2[tid] = b2[tid];
    if (tid < 32) { sF[tid] = bf[tid]; sP[tid] = ph[tid]; }
    __syncthreads();

    int e0 = blockIdx.x * 512 + tid;
    int e1 = e0 + 256;
    int s0 = g_src[e0], d0 = g_dst[e0];
    int s1 = g_src[e1], d1 = g_dst[e1];
    float dt0 = dts[e0], dt1 = dts[e1];

    const float* xd0 = x + (size_t)d0 * IN_CH;
    const float* xs0 = x + (size_t)s0 * IN_CH;
    const float* xd1 = x + (size_t)d1 * IN_CH;
    const float* xs1 = x + (size_t)s1 * IN_CH;

    ull a0[16], a1[16];
    float t0, t1;
    {
        const ull* bp = (const ull*)sB1;
#pragma unroll
        for (int p = 0; p < 16; p++) { a0[p] = bp[p]; a1[p] = bp[p]; }
        t0 = sB1[32]; t1 = sB1[32];
    }

#define S1_ROW(ROW, V0, V1)                                             \
    {                                                                   \
        ull m0 = pack2(V0), m1 = pack2(V1);                             \
        const ulonglong2* wp = (const ulonglong2*)(sW1 + (ROW) * 36);   \
        ulonglong2 wa = wp[0], wb = wp[1], wc = wp[2], wd = wp[3];      \
        ulonglong2 we = wp[4], wf = wp[5], wg = wp[6], wh = wp[7];      \
        fma2(a0[0], m0, wa.x);  fma2(a1[0], m1, wa.x);                  \
        fma2(a0[1], m0, wa.y);  fma2(a1[1], m1, wa.y);                  \
        fma2(a0[2], m0, wb.x);  fma2(a1[2], m1, wb.x);                  \
        fma2(a0[3], m0, wb.y);  fma2(a1[3], m1, wb.y);                  \
        fma2(a0[4], m0, wc.x);  fma2(a1[4], m1, wc.x);                  \
        fma2(a0[5], m0, wc.y);  fma2(a1[5], m1, wc.y);                  \
        fma2(a0[6], m0, wd.x);  fma2(a1[6], m1, wd.x);                  \
        fma2(a0[7], m0, wd.y);  fma2(a1[7], m1, wd.y);                  \
        fma2(a0[8], m0, we.x);  fma2(a1[8], m1, we.x);                  \
        fma2(a0[9], m0, we.y);  fma2(a1[9], m1, we.y);                  \
        fma2(a0[10], m0, wf.x); fma2(a1[10], m1, wf.x);                 \
        fma2(a0[11], m0, wf.y); fma2(a1[11], m1, wf.y);                 \
        fma2(a0[12], m0, wg.x); fma2(a1[12], m1, wg.x);                 \
        fma2(a0[13], m0, wg.y); fma2(a1[13], m1, wg.y);                 \
        fma2(a0[14], m0, wh.x); fma2(a1[14], m1, wh.x);                 \
        fma2(a0[15], m0, wh.y); fma2(a1[15], m1, wh.y);                 \
        float ws = sW1[(ROW) * 36 + 32];                                \
        t0 = fmaf(V0, ws, t0); t1 = fmaf(V1, ws, t1);                   \
    }

#pragma unroll 1
    for (int i = 0; i < 17; i++) { float v0 = xd0[i], v1 = xd1[i]; S1_ROW(i, v0, v1); }
#pragma unroll 1
    for (int i = 0; i < 17; i++) { float v0 = xs0[i], v1 = xs1[i]; S1_ROW(17 + i, v0, v1); }
#pragma unroll 1
    for (int t = 0; t < 32; t++) {
        float f = sF[t], p = sP[t];
        float v0 = __cosf(dt0 * f + p);
        float v1 = __cosf(dt1 * f + p);
        S1_ROW(34 + t, v0, v1);
    }

    float h0[33], h1[33];
#pragma unroll
    for (int p = 0; p < 16; p++) {
        unpack2(a0[p], h0[2 * p], h0[2 * p + 1]);
        unpack2(a1[p], h1[2 * p], h1[2 * p + 1]);
    }
    h0[32] = t0; h1[32] = t1;
#pragma unroll
    for (int i = 0; i < 33; i++) { h0[i] = fmaxf(h0[i], 0.f); h1[i] = fmaxf(h1[i], 0.f); }

    ull c0[8], c1[8]; float q0, q1;
    {
        const ull* bp = (const ull*)sB2;
#pragma unroll
        for (int p = 0; p < 8; p++) { c0[p] = bp[p]; c1[p] = bp[p]; }
        q0 = sB2[16]; q1 = sB2[16];
    }
#pragma unroll 1
    for (int i = 0; i < 33; i++) {
        ull m0 = pack2(h0[i]), m1 = pack2(h1[i]);
        const ulonglong2* wp = (const ulonglong2*)(sW2 + i * 20);
        ulonglong2 wa = wp[0], wb = wp[1], wc = wp[2], wd = wp[3];
        fma2(c0[0], m0, wa.x); fma2(c1[0], m1, wa.x);
        fma2(c0[1], m0, wa.y); fma2(c1[1], m1, wa.y);
        fma2(c0[2], m0, wb.x); fma2(c1[2], m1, wb.x);
        fma2(c0[3], m0, wb.y); fma2(c1[3], m1, wb.y);
        fma2(c0[4], m0, wc.x); fma2(c1[4], m1, wc.x);
        fma2(c0[5], m0, wc.y); fma2(c1[5], m1, wc.y);
        fma2(c0[6], m0, wd.x); fma2(c1[6], m1, wd.x);
        fma2(c0[7], m0, wd.y); fma2(c1[7], m1, wd.y);
        float ws = sW2[i * 20 + 16];
        q0 = fmaf(h0[i], ws, q0); q1 = fmaf(h1[i], ws, q1);
    }

    {
        float pv[17];
#pragma unroll
        for (int p = 0; p < 8; p++) unpack2(c0[p], pv[2 * p], pv[2 * p + 1]);
        pv[16] = q0;
        float m[17];
#pragma unroll
        for (int j = 0; j < 17; j++) m[j] = (2.f * tanh_fast(pv[j]) - 1.f) * xd0[j];
        float* base = g_msg + (size_t)d0 * 64;
        red4(base + 0, m[0], m[1], m[2], m[3]);
        red4(base + 4, m[4], m[5], m[6], m[7]);
        red4(base + 8, m[8], m[9], m[10], m[11]);
        red4(base + 12, m[12], m[13], m[14], m[15]);
        atomicAdd(base + 16, m[16]);
    }
    {
        float pv[17];
#pragma unroll
        for (int p = 0; p < 8; p++) unpack2(c1[p], pv[2 * p], pv[2 * p + 1]);
        pv[16] = q1;
        float m[17];
#pragma unroll
        for (int j = 0; j < 17; j++) m[j] = (2.f * tanh_fast(pv[j]) - 1.f) * xd1[j];
        float* base = g_msg + (size_t)d1 * 64;
        red4(base + 0, m[0], m[1], m[2], m[3]);
        red4(base + 4, m[4], m[5], m[6], m[7]);
        red4(base + 8, m[8], m[9], m[10], m[11]);
        red4(base + 12, m[12], m[13], m[14], m[15]);
        atomicAdd(base + 16, m[16]);
    }
}

// ---------------- node update + projection: h = (x + msg*rdeg) @ PW + Pb ----------
__global__ __launch_bounds__(256)
void k_proj(const float* __restrict__ x, const float* __restrict__ PW,
            const float* __restrict__ Pb) {
    __shared__ float sW[17 * 64];
    __shared__ __align__(16) float sB[64];
    int tid = threadIdx.x;
    for (int i = tid; i < 17 * 64; i += 256) sW[i] = PW[i];
    if (tid < 64) sB[tid] = Pb[tid];
    __syncthreads();

    int n = blockIdx.x * 128 + (tid >> 1);
    int q = tid & 1;
    if (n >= N_NODES) return;
    float rdeg = g_deg[n];

    ull acc[16];
    {
        const ull* bp = (const ull*)(sB + 32 * q);
#pragma unroll
        for (int p = 0; p < 16; p++) acc[p] = bp[p];
    }

    const float* xp = x + (size_t)n * 17;
    float* mp = g_msg + (size_t)n * 64;

#pragma unroll 1
    for (int k = 0; k < 17; k++) {
        float xm = xp[k] + mp[k] * rdeg;
        ull m = pack2(xm);
        const ulonglong2* wp = (const ulonglong2*)(sW + k * 64 + 32 * q);
#pragma unroll
        for (int h = 0; h < 8; h++) {
            ulonglong2 w = wp[h];
            fma2(acc[2 * h], m, w.x);
            fma2(acc[2 * h + 1], m, w.y);
        }
    }

    float* hp = g_h + (size_t)n * 64 + 32 * q;
#pragma unroll
    for (int h = 0; h < 8; h++) {
        float a, b2, c, d;
        unpack2(acc[2 * h], a, b2);
        unpack2(acc[2 * h + 1], c, d);
        *(float4*)(hp + 4 * h) = make_float4(a, b2, c, d);
    }
    if (q == 0) {
        float4 z = make_float4(0.f, 0.f, 0.f, 0.f);
        *(float4*)(mp + 0) = z; *(float4*)(mp + 4) = z;
        *(float4*)(mp + 8) = z; *(float4*)(mp + 12) = z;
        mp[16] = 0.f;
    }
}

// ---------------- stage 2 layer kernel: warp HMMA bf16 hi/lo split ----------------
// 128 edges/block, 8 warps. Warp w: edge rows 16w..16w+15, full N=64.
// A1 [128][136bf16] (stride 272B), B1 [64][136bf16]; A2/B2 stride 144B.
// H2 fp32 (stride 66 fl) aliases dead A1hi region. XD = fp32 h_dst rows.
#define MM_SMEM_BYTES 194560
__global__ __launch_bounds__(256, 1)
void k_layer_mma(const float* __restrict__ b1, const float* __restrict__ b2) {
    extern __shared__ unsigned char sm[];
    const uint32_t O_D = 0, O_S = 512, O_BI1 = 1024, O_BI2 = 1280;
    const uint32_t O_A1H = 2048, O_A1L = 36864, O_B1H = 71680, O_B1L = 89088;
    const uint32_t O_A2H = 106496, O_A2L = 124928, O_B2H = 143360, O_B2L = 152576;
    const uint32_t O_XD = 161792;
    const uint32_t O_H2 = 2048;     // alias A1H (dead after GEMM1)

    uint32_t sb = smem_u32(sm);
    int tid = threadIdx.x;
    int w = tid >> 5, l = tid & 31;

    int* sD = (int*)(sm + O_D);
    int* sS = (int*)(sm + O_S);
    float* sB1f = (float*)(sm + O_BI1);
    float* sB2f = (float*)(sm + O_BI2);
    if (tid < 128) {
        int e = blockIdx.x * 128 + tid;
        sD[tid] = g_dst[e];
        sS[tid] = g_src[e];
    }
    if (tid < 64) { sB1f[tid] = b1[tid]; sB2f[tid] = b2[tid]; }
    {
        const float4* s; float4* d;
        s = (const float4*)g_B1hi; d = (float4*)(sm + O_B1H);
        for (int i = tid; i < 1088; i += 256) d[i] = s[i];
        s = (const float4*)g_B1lo; d = (float4*)(sm + O_B1L);
        for (int i = tid; i < 1088; i += 256) d[i] = s[i];
        s = (const float4*)g_B2hi; d = (float4*)(sm + O_B2H);
        for (int i = tid; i < 576; i += 256) d[i] = s[i];
        s = (const float4*)g_B2lo; d = (float4*)(sm + O_B2L);
        for (int i = tid; i < 576; i += 256) d[i] = s[i];
    }
    __syncthreads();

    // gather: A1[e] = bf16(hi/lo)[h_dst | h_src]; XD[e] = fp32 h_dst
    {
        int e = tid >> 1, q = tid & 1;
        int row = q ? sS[e] : sD[e];
        const float4* hp = (const float4*)(g_h + (size_t)row * 64);
        uint32_t bo = (uint32_t)e * 272u + (q ? 128u : 0u);
        float* xr = (float*)(sm + O_XD) + e * 64;
#pragma unroll
        for (int i = 0; i < 16; i++) {
            float4 v = hp[i];
            uint32_t h01, l01, h23, l23;
            split2(v.x, v.y, h01, l01);
            split2(v.z, v.w, h23, l23);
            *(uint2*)(sm + O_A1H + bo + 8u * i) = make_uint2(h01, h23);
            *(uint2*)(sm + O_A1L + bo + 8u * i) = make_uint2(l01, l23);
            if (!q) *(float4*)(xr + 4 * i) = v;
        }
    }
    __syncwarp();

    // per-lane ldmatrix bases
    uint32_t arow = (uint32_t)(16 * w + (l & 7) + ((l >> 3) & 1) * 8);
    uint32_t acol = (uint32_t)(l >> 4) * 16u;
    uint32_t brow = (uint32_t)((l & 7) + ((l >> 3) & 2) * 4);
    uint32_t bk = (uint32_t)((l >> 3) & 1) * 16u;

    // ---------------- GEMM1: D1 = m_in @ W1 (hi/lo 3-term split) ----------------
    float d1[8][4];
#pragma unroll
    for (int t = 0; t < 8; t++)
#pragma unroll
        for (int p = 0; p < 4; p++) d1[t][p] = 0.f;
    {
        uint32_t aAh = sb + O_A1H + arow * 272u + acol;
        uint32_t aAl = aAh + (O_A1L - O_A1H);
        uint32_t aBh = sb + O_B1H + brow * 272u + bk;
        uint32_t aBl = aBh + (O_B1L - O_B1H);
#pragma unroll
        for (int ks = 0; ks < 8; ks++) {
            uint32_t ah[4], al[4];
            ldx4(ah, aAh + 32u * ks);
            ldx4(al, aAl + 32u * ks);
#pragma unroll
            for (int tp = 0; tp < 4; tp++) {
                uint32_t bh[4], bl[4];
                uint32_t toff = (uint32_t)tp * (16u * 272u) + 32u * ks;
                ldx4(bh, aBh + toff);
                ldx4(bl, aBl + toff);
                mma16816(d1[2 * tp], ah, bh[0], bh[1]);
                mma16816(d1[2 * tp], al, bh[0], bh[1]);
                mma16816(d1[2 * tp], ah, bl[0], bl[1]);
                mma16816(d1[2 * tp + 1], ah, bh[2], bh[3]);
                mma16816(d1[2 * tp + 1], al, bh[2], bh[3]);
                mma16816(d1[2 * tp + 1], ah, bl[2], bl[3]);
            }
        }
    }

    // epilogue1: bias + relu + split -> A2 (warp-local rows)
    {
        int r0 = 16 * w + (l >> 2);
        int cc = 2 * (l & 3);
#pragma unroll
        for (int t = 0; t < 8; t++) {
            int c = 8 * t + cc;
            float f0 = fmaxf(d1[t][0] + sB1f[c], 0.f);
            float f1 = fmaxf(d1[t][1] + sB1f[c + 1], 0.f);
            float f2 = fmaxf(d1[t][2] + sB1f[c], 0.f);
            float f3 = fmaxf(d1[t][3] + sB1f[c + 1], 0.f);
            uint32_t h01, l01, h23, l23;
            split2(f0, f1, h01, l01);
            split2(f2, f3, h23, l23);
            uint32_t o0 = (uint32_t)r0 * 144u + (uint32_t)c * 2u;
            uint32_t o1 = (uint32_t)(r0 + 8) * 144u + (uint32_t)c * 2u;
            *(uint32_t*)(sm + O_A2H + o0) = h01;
            *(uint32_t*)(sm + O_A2L + o0) = l01;
            *(uint32_t*)(sm + O_A2H + o1) = h23;
            *(uint32_t*)(sm + O_A2L + o1) = l23;
        }
    }
    __syncwarp();

    // ---------------- GEMM2: D2 = hidden @ W2 ----------------
    float d2[8][4];
#pragma unroll
    for (int t = 0; t < 8; t++)
#pragma unroll
        for (int p = 0; p < 4; p++) d2[t][p] = 0.f;
    {
        uint32_t aAh = sb + O_A2H + arow * 144u + acol;
        uint32_t aAl = aAh + (O_A2L - O_A2H);
        uint32_t aBh = sb + O_B2H + brow * 144u + bk;
        uint32_t aBl = aBh + (O_B2L - O_B2H);
#pragma unroll
        for (int ks = 0; ks < 4; ks++) {
            uint32_t ah[4], al[4];
            ldx4(ah, aAh + 32u * ks);
            ldx4(al, aAl + 32u * ks);
#pragma unroll
            for (int tp = 0; tp < 4; tp++) {
                uint32_t bh[4], bl[4];
                uint32_t toff = (uint32_t)tp * (16u * 144u) + 32u * ks;
                ldx4(bh, aBh + toff);
                ldx4(bl, aBl + toff);
                mma16816(d2[2 * tp], ah, bh[0], bh[1]);
                mma16816(d2[2 * tp], al, bh[0], bh[1]);
                mma16816(d2[2 * tp], ah, bl[0], bl[1]);
                mma16816(d2[2 * tp + 1], ah, bh[2], bh[3]);
                mma16816(d2[2 * tp + 1], al, bh[2], bh[3]);
                mma16816(d2[2 * tp + 1], ah, bl[2], bl[3]);
            }
        }
    }

    // H2 aliases A1: wait until ALL warps are past GEMM1 (A1 reads)
    __syncthreads();

    // epilogue2: raw D2 -> H2 fp32 (stride 66 floats)
    {
        int r0 = 16 * w + (l >> 2);
        int cc = 2 * (l & 3);
#pragma unroll
        for (int t = 0; t < 8; t++) {
            int c = 8 * t + cc;
            *(float2*)(sm + O_H2 + ((uint32_t)r0 * 66u + (uint32_t)c) * 4u)
                = make_float2(d2[t][0], d2[t][1]);
            *(float2*)(sm + O_H2 + ((uint32_t)(r0 + 8) * 66u + (uint32_t)c) * 4u)
                = make_float2(d2[t][2], d2[t][3]);
        }
    }
    __syncthreads();

    // scatter: msg = (2*tanh(D2+b2)-1) * h_dst -> vector RED
    if (tid < 128) {
        int dn = sD[tid];
        const float* hr = (const float*)(sm + O_H2) + tid * 66;
        const float* xr = (const float*)(sm + O_XD) + tid * 64;
        float* base = g_msg + (size_t)dn * 64;
#pragma unroll
        for (int c = 0; c < 64; c += 4) {
            float v0 = (2.f * tanh_fast(hr[c + 0] + sB2f[c + 0]) - 1.f) * xr[c + 0];
            float v1 = (2.f * tanh_fast(hr[c + 1] + sB2f[c + 1]) - 1.f) * xr[c + 1];
            float v2 = (2.f * tanh_fast(hr[c + 2] + sB2f[c + 2]) - 1.f) * xr[c + 2];
            float v3 = (2.f * tanh_fast(hr[c + 3] + sB2f[c + 3]) - 1.f) * xr[c + 3];
            red4(base + c, v0, v1, v2, v3);
        }
    }
}

// ---------------- node update (h += msg*rdeg), zero msg, BN partial stats ---------
__global__ __launch_bounds__(256)
void k_update(int statOff) {
    float* stats = g_stats + statOff;
    int tid = threadIdx.x;
    int base = blockIdx.x * 4096;
    float4* h4 = (float4*)g_h;
    float4* m4 = (float4*)g_msg;
    float s[4] = {0.f, 0.f, 0.f, 0.f}, ss[4] = {0.f, 0.f, 0.f, 0.f};
#pragma unroll 4
    for (int i = 0; i < 16; i++) {
        int idx = base + tid + i * 256;
        if (idx < N_NODES * 16) {
            int n = idx >> 4;
            float rdeg = g_deg[n];
            float4 hv = h4[idx];
            float4 mv = m4[idx];
            hv.x += mv.x * rdeg; hv.y += mv.y * rdeg;
            hv.z += mv.z * rdeg; hv.w += mv.w * rdeg;
            h4[idx] = hv;
            m4[idx] = make_float4(0.f, 0.f, 0.f, 0.f);
            s[0] += hv.x; s[1] += hv.y; s[2] += hv.z; s[3] += hv.w;
            ss[0] += hv.x * hv.x; ss[1] += hv.y * hv.y;
            ss[2] += hv.z * hv.z; ss[3] += hv.w * hv.w;
        }
    }
    __shared__ float sA[256][4], sBm[256][4];
#pragma unroll
    for (int p = 0; p < 4; p++) { sA[tid][p] = s[p]; sBm[tid][p] = ss[p]; }
    __syncthreads();
    if (tid < 16) {
        float rs[4] = {0.f, 0.f, 0.f, 0.f}, rss[4] = {0.f, 0.f, 0.f, 0.f};
#pragma unroll
        for (int j = 0; j < 16; j++) {
#pragma unroll
            for (int p = 0; p < 4; p++) {
                rs[p] += sA[tid + 16 * j][p];
                rss[p] += sBm[tid + 16 * j][p];
            }
        }
        int c0 = tid * 4;
#pragma unroll
        for (int p = 0; p < 4; p++) {
            atomicAdd(&stats[c0 + p], rs[p]);
            atomicAdd(&stats[64 + c0 + p], rss[p]);
        }
    }
}

// ---------------- BN apply + relu ----------------
__global__ void k_bnrelu(int statOff, const float* __restrict__ g, const float* __restrict__ b) {
    const float* stats = g_stats + statOff;
    int idx = blockIdx.x * 256 + threadIdx.x;
    int c0 = (idx & 15) * 4;
    const float invn = 1.f / (float)N_NODES;
    float4* hp = ((float4*)g_h) + idx;
    float4 v = *hp;
    float o[4] = {v.x, v.y, v.z, v.w};
#pragma unroll
    for (int i = 0; i < 4; i++) {
        float m = stats[c0 + i] * invn;
        float var = stats[64 + c0 + i] * invn - m * m;
        float sc = rsqrtf(var + BN_EPS) * g[c0 + i];
        o[i] = fmaxf((o[i] - m) * sc + b[c0 + i], 0.f);
    }
    v.x = o[0]; v.y = o[1]; v.z = o[2]; v.w = o[3];
    *hp = v;
}

// ---------------- classifier ----------------
__global__ void k_clf1(const float* __restrict__ W, const float* __restrict__ b) {
    __shared__ float sW[4096], sB[64];
    int tid = threadIdx.x;
    for (int i = tid; i < 4096; i += 256) sW[i] = W[i];
    if (tid < 64) sB[tid] = b[tid];
    __syncthreads();
    int r = blockIdx.x * 256 + tid;
    if (r >= BATCH) return;
    float acc[64];
#pragma unroll
    for (int c = 0; c < 64; c++) acc[c] = sB[c];
#pragma unroll 1
    for (int k = 0; k < 64; k++) {
        float hk = g_h[(size_t)r * 64 + k];
        const float* w = &sW[k * 64];
#pragma unroll
        for (int c = 0; c < 64; c++) acc[c] += hk * w[c];
    }
    float* z = g_z1 + (size_t)r * 64;
    float* st = g_stats + 256;
#pragma unroll 1
    for (int c = 0; c < 64; c++) {
        z[c] = acc[c];
        atomicAdd(&st[c], acc[c]);
        atomicAdd(&st[64 + c], acc[c] * acc[c]);
    }
}

__global__ void k_clf2(const float* __restrict__ W, const float* __restrict__ b,
                       const float* __restrict__ g1, const float* __restrict__ bb1) {
    __shared__ float sW[2048], sB[32], sScale[64], sBias[64];
    int tid = threadIdx.x;
    for (int i = tid; i < 2048; i += 256) sW[i] = W[i];
    if (tid < 32) sB[tid] = b[tid];
    if (tid < 64) {
        const float invn = 1.f / (float)BATCH;
        float m = g_stats[256 + tid] * invn;
        float var = g_stats[256 + 64 + tid] * invn - m * m;
        float sc = rsqrtf(var + BN_EPS) * g1[tid];
        sScale[tid] = sc;
        sBias[tid] = bb1[tid] - m * sc;
    }
    __syncthreads();
    int r = blockIdx.x * 256 + tid;
    if (r >= BATCH) return;
    float acc[32];
#pragma unroll
    for (int c = 0; c < 32; c++) acc[c] = sB[c];
#pragma unroll 1
    for (int k = 0; k < 64; k++) {
        float v = fmaxf(g_z1[(size_t)r * 64 + k] * sScale[k] + sBias[k], 0.f);
        const float* w = &sW[k * 32];
#pragma unroll
        for (int c = 0; c < 32; c++) acc[c] += v * w[c];
    }
    float* z = g_z2 + (size_t)r * 32;
    float* st = g_stats + 384;
#pragma unroll 1
    for (int c = 0; c < 32; c++) {
        z[c] = acc[c];
        atomicAdd(&st[c], acc[c]);
        atomicAdd(&st[32 + c], acc[c] * acc[c]);
    }
}

__global__ void k_clf3(const float* __restrict__ W3, const float* __restrict__ b3,
                       const float* __restrict__ g2, const float* __restrict__ bb2,
                       float* __restrict__ out) {
    __shared__ float sW[32], sScale[32], sBias[32], sb3;
    int tid = threadIdx.x;
    if (tid < 32) {
        sW[tid] = W3[tid];
        const float invn = 1.f / (float)BATCH;
        float m = g_stats[384 + tid] * invn;
        float var = g_stats[384 + 32 + tid] * invn - m * m;
        float sc = rsqrtf(var + BN_EPS) * g2[tid];
        sScale[tid] = sc;
        sBias[tid] = bb2[tid] - m * sc;
    }
    if (tid == 0) sb3 = b3[0];
    __syncthreads();
    int r = blockIdx.x * 256 + tid;
    if (r >= BATCH) return;
    float a = sb3;
#pragma unroll 1
    for (int k = 0; k < 32; k++)
        a += fmaxf(g_z2[(size_t)r * 32 + k] * sScale[k] + sBias[k], 0.f) * sW[k];
    out[r] = a;
}

// ---------------- launch ----------------
extern "C" void kernel_launch(void* const* d_in, const int* in_sizes, int n_in,
                              void* d_out, int out_size) {
    auto ix = [&](int i) { return (n_in >= 28) ? i : (i > 3 ? i - 1 : i); };
    const float* x    = (const float*)d_in[ix(0)];
    const void*  ei   = d_in[ix(1)];
    const float* dts  = (const float*)d_in[ix(2)];
    const float* bf   = (const float*)d_in[ix(4)];
    const float* ph   = (const float*)d_in[ix(5)];
    const float* tW1  = (const float*)d_in[ix(6)];
    const float* tb1  = (const float*)d_in[ix(7)];
    const float* tW2  = (const float*)d_in[ix(8)];
    const float* tb2  = (const float*)d_in[ix(9)];
    const float* pW   = (const float*)d_in[ix(10)];
    const float* pb   = (const float*)d_in[ix(11)];
    const float* sW1  = (const float*)d_in[ix(12)];
    const float* sb1  = (const float*)d_in[ix(13)];
    const float* sW2  = (const float*)d_in[ix(14)];
    const float* sb2  = (const float*)d_in[ix(15)];
    const float* bng  = (const float*)d_in[ix(16)];
    const float* bnb  = (const float*)d_in[ix(17)];
    const float* cW1  = (const float*)d_in[ix(18)];
    const float* cb1  = (const float*)d_in[ix(19)];
    const float* cg1  = (const float*)d_in[ix(20)];
    const float* cbb1 = (const float*)d_in[ix(21)];
    const float* cW2  = (const float*)d_in[ix(22)];
    const float* cb2  = (const float*)d_in[ix(23)];
    const float* cg2  = (const float*)d_in[ix(24)];
    const float* cbb2 = (const float*)d_in[ix(25)];
    const float* cW3  = (const float*)d_in[ix(26)];
    const float* cb3  = (const float*)d_in[ix(27)];
    float* out = (float*)d_out;

    cudaFuncSetAttribute(k_layer_mma, cudaFuncAttributeMaxDynamicSharedMemorySize, MM_SMEM_BYTES);

    k_zero_all<<<1024, 256>>>();
    k_convert_idx<<<N_EDGES / 256, 256>>>(ei);
    k_rdeg<<<(N_NODES + 255) / 256, 256>>>();
    k_stage1<<<N_EDGES / 512, 256>>>(x, dts, bf, ph, tW1, tb1, tW2, tb2);
    k_proj<<<(N_NODES + 127) / 128, 256>>>(x, pW, pb);

    for (int l = 0; l < 2; l++) {
        k_prep_w<<<32, 256>>>(sW1 + l * 8192, sW2 + l * 4096);
        k_layer_mma<<<N_EDGES / 128, 256, MM_SMEM_BYTES>>>(sb1 + l * 64, sb2 + l * 64);
        k_update<<<(N_NODES * 16 + 4095) / 4096, 256>>>(l * 128);
        k_bnrelu<<<(N_NODES * HID / 4) / 256, 256>>>(l * 128, bng + l * 64, bnb + l * 64);
    }

    k_clf1<<<(BATCH + 255) / 256, 256>>>(cW1, cb1);
    k_clf2<<<(BATCH + 255) / 256, 256>>>(cW2, cb2, cg1, cbb1);
    k_clf3<<<(BATCH + 255) / 256, 256>>>(cW3, cb3, cg2, cbb2, out);
    (void)in_sizes; (void)out_size;
}

// round 7
// speedup vs baseline: 1.8504x; 1.2805x over previous
#include <cuda_runtime.h>
#include <cuda_bf16.h>
#include <cstdint>

#define N_NODES 100000
#define N_EDGES 1600000
#define IN_CH   17
#define HID     64
#define BATCH   10000
#define BN_EPS  1e-5f

typedef unsigned long long ull;

// ---------------- device scratch ----------------
__device__ float g_h  [(size_t)N_NODES * HID];
__device__ float g_msg[(size_t)N_NODES * HID];
__device__ float g_deg[N_NODES];                 // raw degree, then inverted in-place
__device__ float g_stats[4 * 128];
__device__ float g_z1[BATCH * 64];
__device__ float g_z2[BATCH * 32];
__device__ int   g_src[N_EDGES];
__device__ int   g_dst[N_EDGES];
// pre-packed bf16 hi/lo weight images: W^T row-major [n][k], padded row strides
__device__ __align__(16) unsigned char g_B1hi[64 * 272];   // stride 272B (136 bf16)
__device__ __align__(16) unsigned char g_B1lo[64 * 272];
__device__ __align__(16) unsigned char g_B2hi[64 * 144];   // stride 144B (72 bf16)
__device__ __align__(16) unsigned char g_B2lo[64 * 144];

__device__ __forceinline__ float tanh_fast(float x) {
    float e = __expf(2.f * x);
    return 1.f - __fdividef(2.f, e + 1.f);
}
__device__ __forceinline__ ull pack2(float x) {
    ull r; asm("mov.b64 %0,{%1,%1};" : "=l"(r) : "f"(x)); return r;
}
__device__ __forceinline__ void unpack2(ull a, float& x, float& y) {
    asm("mov.b64 {%0,%1},%2;" : "=f"(x), "=f"(y) : "l"(a));
}
__device__ __forceinline__ void fma2(ull& d, ull a, ull b) {
    asm("fma.rn.f32x2 %0,%1,%2,%0;" : "+l"(d) : "l"(a), "l"(b));
}
__device__ __forceinline__ void red4(float* p, float a, float b, float c, float d) {
    asm volatile("{\n\t.reg .u64 q;\n\tcvta.to.global.u64 q,%0;\n\t"
                 "red.global.add.v4.f32 [q],{%1,%2,%3,%4};\n\t}"
                 :: "l"(p), "f"(a), "f"(b), "f"(c), "f"(d) : "memory");
}
__device__ __forceinline__ uint32_t smem_u32(const void* p) {
    uint32_t a;
    asm("{.reg .u64 t; cvta.to.shared.u64 t, %1; cvt.u32.u64 %0, t;}" : "=r"(a) : "l"(p));
    return a;
}
__device__ __forceinline__ void ldx4(uint32_t* r, uint32_t a) {
    asm volatile("ldmatrix.sync.aligned.m8n8.x4.shared.b16 {%0,%1,%2,%3}, [%4];"
                 : "=r"(r[0]), "=r"(r[1]), "=r"(r[2]), "=r"(r[3]) : "r"(a));
}
__device__ __forceinline__ void mma16816(float* d, const uint32_t* a, uint32_t b0, uint32_t b1) {
    asm volatile("mma.sync.aligned.m16n8k16.row.col.f32.bf16.bf16.f32 "
                 "{%0,%1,%2,%3},{%4,%5,%6,%7},{%8,%9},{%0,%1,%2,%3};"
                 : "+f"(d[0]), "+f"(d[1]), "+f"(d[2]), "+f"(d[3])
                 : "r"(a[0]), "r"(a[1]), "r"(a[2]), "r"(a[3]), "r"(b0), "r"(b1));
}
__device__ __forceinline__ void split2(float x, float y, uint32_t& hi, uint32_t& lo) {
    __nv_bfloat162 h = __float22bfloat162_rn(make_float2(x, y));
    float2 hf = __bfloat1622float2(h);
    __nv_bfloat162 l = __float22bfloat162_rn(make_float2(x - hf.x, y - hf.y));
    hi = *(uint32_t*)&h; lo = *(uint32_t*)&l;
}

// ---------------- edge index conversion + degree ----------------
__global__ void k_convert_idx(const void* __restrict__ ei_raw) {
    __shared__ int s_is64;
    if (threadIdx.x == 0) {
        const unsigned* w = (const unsigned*)ei_raw;
        int is64 = 1;
        for (int i = 1; i < 64; i += 2)
            if (w[i] != 0u) { is64 = 0; break; }
        s_is64 = is64;
    }
    __syncthreads();
    int e = blockIdx.x * 256 + threadIdx.x;
    if (e >= N_EDGES) return;
    int s, d;
    if (s_is64) {
        const long long* p = (const long long*)ei_raw;
        s = (int)p[e]; d = (int)p[(size_t)N_EDGES + e];
    } else {
        const int* p = (const int*)ei_raw;
        s = p[e]; d = p[N_EDGES + e];
    }
    g_src[e] = s; g_dst[e] = d;
    atomicAdd(&g_deg[d], 1.f);
}

// ---------------- zero scratch (vectorized) ----------------
__global__ void k_zero_all() {
    int i = blockIdx.x * 256 + threadIdx.x;
    int st = gridDim.x * 256;
    float4 z = make_float4(0.f, 0.f, 0.f, 0.f);
    float4* m4 = (float4*)g_msg;
    for (int k = i; k < N_NODES * HID / 4; k += st) m4[k] = z;
    for (int k = i; k < N_NODES; k += st) g_deg[k] = 0.f;
    if (i < 512) g_stats[i] = 0.f;
}

// ---------------- invert degree in place ----------------
__global__ void k_rdeg() {
    int n = blockIdx.x * 256 + threadIdx.x;
    if (n < N_NODES) g_deg[n] = 1.f / fmaxf(g_deg[n], 1.f);
}

// ---------------- weight prep: W^T -> bf16 hi/lo padded row-major images ----------
__global__ void k_prep_w(const float* __restrict__ W1, const float* __restrict__ W2) {
    int idx = blockIdx.x * 256 + threadIdx.x;
    if (idx < 8192) {                 // B1[n][k] = W1[k*64+n], n<64, k<128
        int n = idx >> 7, k = idx & 127;
        float w = W1[k * 64 + n];
        __nv_bfloat16 h = __float2bfloat16_rn(w);
        __nv_bfloat16 l = __float2bfloat16_rn(w - __bfloat162float(h));
        uint32_t off = (uint32_t)n * 272u + 2u * (uint32_t)k;
        *(__nv_bfloat16*)(g_B1hi + off) = h;
        *(__nv_bfloat16*)(g_B1lo + off) = l;
    }
    if (idx < 4096) {                 // B2[n][k] = W2[k*64+n], n<64, k<64
        int n = idx >> 6, k = idx & 63;
        float w = W2[k * 64 + n];
        __nv_bfloat16 h = __float2bfloat16_rn(w);
        __nv_bfloat16 l = __float2bfloat16_rn(w - __bfloat162float(h));
        uint32_t off = (uint32_t)n * 144u + 2u * (uint32_t)k;
        *(__nv_bfloat16*)(g_B2hi + off) = h;
        *(__nv_bfloat16*)(g_B2lo + off) = l;
    }
}

// ---------------- stage 1: temporal edge MLP (66 -> 33 -> 17), 2 edges/thread ----
__global__ __launch_bounds__(256)
void k_stage1(const float* __restrict__ x,
              const float* __restrict__ dts, const float* __restrict__ bf,
              const float* __restrict__ ph,
              const float* __restrict__ W1, const float* __restrict__ b1,
              const float* __restrict__ W2, const float* __restrict__ b2) {
    __shared__ float sW1[66 * 36];
    __shared__ float sW2[33 * 20];
    __shared__ __align__(16) float sB1[34], sB2[18], sF[32], sP[32];
    int tid = threadIdx.x;
    for (int i = tid; i < 66 * 33; i += 256) {
        int r = i / 33, c = i - r * 33;
        sW1[r * 36 + c] = W1[i];
    }
    for (int i = tid; i < 33 * 17; i += 256) {
        int r = i / 17, c = i - r * 17;
        sW2[r * 20 + c] = W2[i];
    }
    if (tid < 33) sB1[tid] = b1[tid];
    if (tid < 17) sB2[tid] = b2[tid];
    if (tid < 32) { sF[tid] = bf[tid]; sP[tid] = ph[tid]; }
    __syncthreads();

    int e0 = blockIdx.x * 512 + tid;
    int e1 = e0 + 256;
    int s0 = g_src[e0], d0 = g_dst[e0];
    int s1 = g_src[e1], d1 = g_dst[e1];
    float dt0 = dts[e0], dt1 = dts[e1];

    const float* xd0 = x + (size_t)d0 * IN_CH;
    const float* xs0 = x + (size_t)s0 * IN_CH;
    const float* xd1 = x + (size_t)d1 * IN_CH;
    const float* xs1 = x + (size_t)s1 * IN_CH;

    ull a0[16], a1[16];
    float t0, t1;
    {
        const ull* bp = (const ull*)sB1;
#pragma unroll
        for (int p = 0; p < 16; p++) { a0[p] = bp[p]; a1[p] = bp[p]; }
        t0 = sB1[32]; t1 = sB1[32];
    }

#define S1_ROW(ROW, V0, V1)                                             \
    {                                                                   \
        ull m0 = pack2(V0), m1 = pack2(V1);                             \
        const ulonglong2* wp = (const ulonglong2*)(sW1 + (ROW) * 36);   \
        ulonglong2 wa = wp[0], wb = wp[1], wc = wp[2], wd = wp[3];      \
        ulonglong2 we = wp[4], wf = wp[5], wg = wp[6], wh = wp[7];      \
        fma2(a0[0], m0, wa.x);  fma2(a1[0], m1, wa.x);                  \
        fma2(a0[1], m0, wa.y);  fma2(a1[1], m1, wa.y);                  \
        fma2(a0[2], m0, wb.x);  fma2(a1[2], m1, wb.x);                  \
        fma2(a0[3], m0, wb.y);  fma2(a1[3], m1, wb.y);                  \
        fma2(a0[4], m0, wc.x);  fma2(a1[4], m1, wc.x);                  \
        fma2(a0[5], m0, wc.y);  fma2(a1[5], m1, wc.y);                  \
        fma2(a0[6], m0, wd.x);  fma2(a1[6], m1, wd.x);                  \
        fma2(a0[7], m0, wd.y);  fma2(a1[7], m1, wd.y);                  \
        fma2(a0[8], m0, we.x);  fma2(a1[8], m1, we.x);                  \
        fma2(a0[9], m0, we.y);  fma2(a1[9], m1, we.y);                  \
        fma2(a0[10], m0, wf.x); fma2(a1[10], m1, wf.x);                 \
        fma2(a0[11], m0, wf.y); fma2(a1[11], m1, wf.y);                 \
        fma2(a0[12], m0, wg.x); fma2(a1[12], m1, wg.x);                 \
        fma2(a0[13], m0, wg.y); fma2(a1[13], m1, wg.y);                 \
        fma2(a0[14], m0, wh.x); fma2(a1[14], m1, wh.x);                 \
        fma2(a0[15], m0, wh.y); fma2(a1[15], m1, wh.y);                 \
        float ws = sW1[(ROW) * 36 + 32];                                \
        t0 = fmaf(V0, ws, t0); t1 = fmaf(V1, ws, t1);                   \
    }

#pragma unroll 1
    for (int i = 0; i < 17; i++) { float v0 = xd0[i], v1 = xd1[i]; S1_ROW(i, v0, v1); }
#pragma unroll 1
    for (int i = 0; i < 17; i++) { float v0 = xs0[i], v1 = xs1[i]; S1_ROW(17 + i, v0, v1); }
#pragma unroll 1
    for (int t = 0; t < 32; t++) {
        float f = sF[t], p = sP[t];
        float v0 = __cosf(dt0 * f + p);
        float v1 = __cosf(dt1 * f + p);
        S1_ROW(34 + t, v0, v1);
    }

    float h0[33], h1[33];
#pragma unroll
    for (int p = 0; p < 16; p++) {
        unpack2(a0[p], h0[2 * p], h0[2 * p + 1]);
        unpack2(a1[p], h1[2 * p], h1[2 * p + 1]);
    }
    h0[32] = t0; h1[32] = t1;
#pragma unroll
    for (int i = 0; i < 33; i++) { h0[i] = fmaxf(h0[i], 0.f); h1[i] = fmaxf(h1[i], 0.f); }

    ull c0[8], c1[8]; float q0, q1;
    {
        const ull* bp = (const ull*)sB2;
#pragma unroll
        for (int p = 0; p < 8; p++) { c0[p] = bp[p]; c1[p] = bp[p]; }
        q0 = sB2[16]; q1 = sB2[16];
    }
#pragma unroll 1
    for (int i = 0; i < 33; i++) {
        ull m0 = pack2(h0[i]), m1 = pack2(h1[i]);
        const ulonglong2* wp = (const ulonglong2*)(sW2 + i * 20);
        ulonglong2 wa = wp[0], wb = wp[1], wc = wp[2], wd = wp[3];
        fma2(c0[0], m0, wa.x); fma2(c1[0], m1, wa.x);
        fma2(c0[1], m0, wa.y); fma2(c1[1], m1, wa.y);
        fma2(c0[2], m0, wb.x); fma2(c1[2], m1, wb.x);
        fma2(c0[3], m0, wb.y); fma2(c1[3], m1, wb.y);
        fma2(c0[4], m0, wc.x); fma2(c1[4], m1, wc.x);
        fma2(c0[5], m0, wc.y); fma2(c1[5], m1, wc.y);
        fma2(c0[6], m0, wd.x); fma2(c1[6], m1, wd.x);
        fma2(c0[7], m0, wd.y); fma2(c1[7], m1, wd.y);
        float ws = sW2[i * 20 + 16];
        q0 = fmaf(h0[i], ws, q0); q1 = fmaf(h1[i], ws, q1);
    }

    {
        float pv[17];
#pragma unroll
        for (int p = 0; p < 8; p++) unpack2(c0[p], pv[2 * p], pv[2 * p + 1]);
        pv[16] = q0;
        float m[17];
#pragma unroll
        for (int j = 0; j < 17; j++) m[j] = (2.f * tanh_fast(pv[j]) - 1.f) * xd0[j];
        float* base = g_msg + (size_t)d0 * 64;
        red4(base + 0, m[0], m[1], m[2], m[3]);
        red4(base + 4, m[4], m[5], m[6], m[7]);
        red4(base + 8, m[8], m[9], m[10], m[11]);
        red4(base + 12, m[12], m[13], m[14], m[15]);
        atomicAdd(base + 16, m[16]);
    }
    {
        float pv[17];
#pragma unroll
        for (int p = 0; p < 8; p++) unpack2(c1[p], pv[2 * p], pv[2 * p + 1]);
        pv[16] = q1;
        float m[17];
#pragma unroll
        for (int j = 0; j < 17; j++) m[j] = (2.f * tanh_fast(pv[j]) - 1.f) * xd1[j];
        float* base = g_msg + (size_t)d1 * 64;
        red4(base + 0, m[0], m[1], m[2], m[3]);
        red4(base + 4, m[4], m[5], m[6], m[7]);
        red4(base + 8, m[8], m[9], m[10], m[11]);
        red4(base + 12, m[12], m[13], m[14], m[15]);
        atomicAdd(base + 16, m[16]);
    }
}

// ---------------- node update + projection: h = (x + msg*rdeg) @ PW + Pb ----------
__global__ __launch_bounds__(256)
void k_proj(const float* __restrict__ x, const float* __restrict__ PW,
            const float* __restrict__ Pb) {
    __shared__ float sW[17 * 64];
    __shared__ __align__(16) float sB[64];
    int tid = threadIdx.x;
    for (int i = tid; i < 17 * 64; i += 256) sW[i] = PW[i];
    if (tid < 64) sB[tid] = Pb[tid];
    __syncthreads();

    int n = blockIdx.x * 128 + (tid >> 1);
    int q = tid & 1;
    if (n >= N_NODES) return;
    float rdeg = g_deg[n];

    ull acc[16];
    {
        const ull* bp = (const ull*)(sB + 32 * q);
#pragma unroll
        for (int p = 0; p < 16; p++) acc[p] = bp[p];
    }

    const float* xp = x + (size_t)n * 17;
    float* mp = g_msg + (size_t)n * 64;

#pragma unroll 1
    for (int k = 0; k < 17; k++) {
        float xm = xp[k] + mp[k] * rdeg;
        ull m = pack2(xm);
        const ulonglong2* wp = (const ulonglong2*)(sW + k * 64 + 32 * q);
#pragma unroll
        for (int h = 0; h < 8; h++) {
            ulonglong2 w = wp[h];
            fma2(acc[2 * h], m, w.x);
            fma2(acc[2 * h + 1], m, w.y);
        }
    }

    float* hp = g_h + (size_t)n * 64 + 32 * q;
#pragma unroll
    for (int h = 0; h < 8; h++) {
        float a, b2, c, d;
        unpack2(acc[2 * h], a, b2);
        unpack2(acc[2 * h + 1], c, d);
        *(float4*)(hp + 4 * h) = make_float4(a, b2, c, d);
    }
    if (q == 0) {
        float4 z = make_float4(0.f, 0.f, 0.f, 0.f);
        *(float4*)(mp + 0) = z; *(float4*)(mp + 4) = z;
        *(float4*)(mp + 8) = z; *(float4*)(mp + 12) = z;
        mp[16] = 0.f;
    }
}

// ---------------- stage 2 layer kernel: persistent HMMA, 64-edge tiles ------------
// 128 threads (4 warps x 16 rows), 2 CTAs/SM. Weights staged once per CTA.
// A1 [64][136bf16] hi/lo, A2 [64][72bf16] hi/lo, H2 fp32 aliases A2.
#define LP_SMEM_BYTES 107520
#define N_TILES (N_EDGES / 64)
__global__ __launch_bounds__(128, 2)
void k_layer_p(const float* __restrict__ b1, const float* __restrict__ b2) {
    extern __shared__ unsigned char sm[];
    const uint32_t O_B1H = 0, O_B1L = 17408, O_B2H = 34816, O_B2L = 44032;
    const uint32_t O_BI1 = 53248, O_BI2 = 53504;
    const uint32_t O_A1H = 54272, O_A1L = 71680;
    const uint32_t O_A2H = 89088, O_A2L = 98304;
    const uint32_t O_H2 = 89088;   // alias A2 (dead after GEMM2)

    uint32_t sb = smem_u32(sm);
    int tid = threadIdx.x;
    int w = tid >> 5, l = tid & 31;

    float* sB1f = (float*)(sm + O_BI1);
    float* sB2f = (float*)(sm + O_BI2);
    if (tid < 64) { sB1f[tid] = b1[tid]; sB2f[tid] = b2[tid]; }
    {
        const float4* s; float4* d;
        s = (const float4*)g_B1hi; d = (float4*)(sm + O_B1H);
        for (int i = tid; i < 1088; i += 128) d[i] = s[i];
        s = (const float4*)g_B1lo; d = (float4*)(sm + O_B1L);
        for (int i = tid; i < 1088; i += 128) d[i] = s[i];
        s = (const float4*)g_B2hi; d = (float4*)(sm + O_B2H);
        for (int i = tid; i < 576; i += 128) d[i] = s[i];
        s = (const float4*)g_B2lo; d = (float4*)(sm + O_B2L);
        for (int i = tid; i < 576; i += 128) d[i] = s[i];
    }

    int e = tid >> 1, q = tid & 1;
    uint32_t arow = (uint32_t)(16 * w + (l & 7) + ((l >> 3) & 1) * 8);
    uint32_t acol = (uint32_t)(l >> 4) * 16u;
    uint32_t brow = (uint32_t)((l & 7) + ((l >> 3) & 2) * 4);
    uint32_t bk = (uint32_t)((l >> 3) & 1) * 16u;

    for (int tile = blockIdx.x; tile < N_TILES; tile += gridDim.x) {
        __syncthreads();   // prev tile's scatter done; (iter 0: weights visible)

        int ge = tile * 64 + e;
        int dn = g_dst[ge];
        int row = q ? g_src[ge] : dn;

        // gather: A1[e] = bf16 hi/lo of [h_dst | h_src]
        {
            const float4* hp = (const float4*)(g_h + (size_t)row * 64);
            uint32_t bo = (uint32_t)e * 272u + (q ? 128u : 0u);
#pragma unroll
            for (int i = 0; i < 16; i++) {
                float4 v = hp[i];
                uint32_t h01, l01, h23, l23;
                split2(v.x, v.y, h01, l01);
                split2(v.z, v.w, h23, l23);
                *(uint2*)(sm + O_A1H + bo + 8u * i) = make_uint2(h01, h23);
                *(uint2*)(sm + O_A1L + bo + 8u * i) = make_uint2(l01, l23);
            }
        }
        __syncwarp();   // A1 rows are warp-local to their consumers

        // GEMM1: D1 = m_in @ W1 (3-term hi/lo split), K=128
        float d1[8][4];
#pragma unroll
        for (int t = 0; t < 8; t++)
#pragma unroll
            for (int p = 0; p < 4; p++) d1[t][p] = 0.f;
        {
            uint32_t aAh = sb + O_A1H + arow * 272u + acol;
            uint32_t aAl = sb + O_A1L + arow * 272u + acol;
            uint32_t aBh = sb + O_B1H + brow * 272u + bk;
            uint32_t aBl = sb + O_B1L + brow * 272u + bk;
#pragma unroll
            for (int ks = 0; ks < 8; ks++) {
                uint32_t ah[4], al[4];
                ldx4(ah, aAh + 32u * ks);
                ldx4(al, aAl + 32u * ks);
#pragma unroll
                for (int tp = 0; tp < 4; tp++) {
                    uint32_t bh[4], bl[4];
                    uint32_t toff = (uint32_t)tp * (16u * 272u) + 32u * ks;
                    ldx4(bh, aBh + toff);
                    ldx4(bl, aBl + toff);
                    mma16816(d1[2 * tp], ah, bh[0], bh[1]);
                    mma16816(d1[2 * tp], al, bh[0], bh[1]);
                    mma16816(d1[2 * tp], ah, bl[0], bl[1]);
                    mma16816(d1[2 * tp + 1], ah, bh[2], bh[3]);
                    mma16816(d1[2 * tp + 1], al, bh[2], bh[3]);
                    mma16816(d1[2 * tp + 1], ah, bl[2], bl[3]);
                }
            }
        }

        // epilogue1: bias + relu + split -> A2 (rows warp-local)
        {
            int r0 = 16 * w + (l >> 2);
            int cc = 2 * (l & 3);
#pragma unroll
            for (int t = 0; t < 8; t++) {
                int c = 8 * t + cc;
                float f0 = fmaxf(d1[t][0] + sB1f[c], 0.f);
                float f1 = fmaxf(d1[t][1] + sB1f[c + 1], 0.f);
                float f2 = fmaxf(d1[t][2] + sB1f[c], 0.f);
                float f3 = fmaxf(d1[t][3] + sB1f[c + 1], 0.f);
                uint32_t h01, l01, h23, l23;
                split2(f0, f1, h01, l01);
                split2(f2, f3, h23, l23);
                uint32_t o0 = (uint32_t)r0 * 144u + (uint32_t)c * 2u;
                uint32_t o1 = (uint32_t)(r0 + 8) * 144u + (uint32_t)c * 2u;
                *(uint32_t*)(sm + O_A2H + o0) = h01;
                *(uint32_t*)(sm + O_A2L + o0) = l01;
                *(uint32_t*)(sm + O_A2H + o1) = h23;
                *(uint32_t*)(sm + O_A2L + o1) = l23;
            }
        }
        __syncwarp();

        // GEMM2: D2 = hidden @ W2, K=64
        float d2[8][4];
#pragma unroll
        for (int t = 0; t < 8; t++)
#pragma unroll
            for (int p = 0; p < 4; p++) d2[t][p] = 0.f;
        {
            uint32_t aAh = sb + O_A2H + arow * 144u + acol;
            uint32_t aAl = sb + O_A2L + arow * 144u + acol;
            uint32_t aBh = sb + O_B2H + brow * 144u + bk;
            uint32_t aBl = sb + O_B2L + brow * 144u + bk;
#pragma unroll
            for (int ks = 0; ks < 4; ks++) {
                uint32_t ah[4], al[4];
                ldx4(ah, aAh + 32u * ks);
                ldx4(al, aAl + 32u * ks);
#pragma unroll
                for (int tp = 0; tp < 4; tp++) {
                    uint32_t bh[4], bl[4];
                    uint32_t toff = (uint32_t)tp * (16u * 144u) + 32u * ks;
                    ldx4(bh, aBh + toff);
                    ldx4(bl, aBl + toff);
                    mma16816(d2[2 * tp], ah, bh[0], bh[1]);
                    mma16816(d2[2 * tp], al, bh[0], bh[1]);
                    mma16816(d2[2 * tp], ah, bl[0], bl[1]);
                    mma16816(d2[2 * tp + 1], ah, bh[2], bh[3]);
                    mma16816(d2[2 * tp + 1], al, bh[2], bh[3]);
                    mma16816(d2[2 * tp + 1], ah, bl[2], bl[3]);
                }
            }
        }

        // H2 aliases A2: all warps must finish reading A2 first
        __syncthreads();

        // epilogue2: raw D2 -> H2 fp32 (stride 66 floats)
        {
            int r0 = 16 * w + (l >> 2);
            int cc = 2 * (l & 3);
#pragma unroll
            for (int t = 0; t < 8; t++) {
                int c = 8 * t + cc;
                *(float2*)(sm + O_H2 + ((uint32_t)r0 * 66u + (uint32_t)c) * 4u)
                    = make_float2(d2[t][0], d2[t][1]);
                *(float2*)(sm + O_H2 + ((uint32_t)(r0 + 8) * 66u + (uint32_t)c) * 4u)
                    = make_float2(d2[t][2], d2[t][3]);
            }
        }
        __syncwarp();   // H2/A1 rows warp-local to scatter readers

        // scatter: thread (e,q) handles cols q*32..q*32+31 of edge e
        {
            const float* hr = (const float*)(sm + O_H2) + e * 66 + q * 32;
            const float* b2p = sB2f + q * 32;
            float* base = g_msg + (size_t)dn * 64 + q * 32;
            uint32_t a1o = (uint32_t)e * 272u + (uint32_t)q * 64u;  // dst half
#pragma unroll
            for (int c = 0; c < 32; c += 4) {
                uint32_t hu0 = *(uint32_t*)(sm + O_A1H + a1o + 2u * c);
                uint32_t hu1 = *(uint32_t*)(sm + O_A1H + a1o + 2u * c + 4u);
                uint32_t lu0 = *(uint32_t*)(sm + O_A1L + a1o + 2u * c);
                uint32_t lu1 = *(uint32_t*)(sm + O_A1L + a1o + 2u * c + 4u);
                float2 h0f = __bfloat1622float2(*(__nv_bfloat162*)&hu0);
                float2 h1f = __bfloat1622float2(*(__nv_bfloat162*)&hu1);
                float2 l0f = __bfloat1622float2(*(__nv_bfloat162*)&lu0);
                float2 l1f = __bfloat1622float2(*(__nv_bfloat162*)&lu1);
                float x0 = h0f.x + l0f.x, x1 = h0f.y + l0f.y;
                float x2 = h1f.x + l1f.x, x3 = h1f.y + l1f.y;
                float v0 = (2.f * tanh_fast(hr[c + 0] + b2p[c + 0]) - 1.f) * x0;
                float v1 = (2.f * tanh_fast(hr[c + 1] + b2p[c + 1]) - 1.f) * x1;
                float v2 = (2.f * tanh_fast(hr[c + 2] + b2p[c + 2]) - 1.f) * x2;
                float v3 = (2.f * tanh_fast(hr[c + 3] + b2p[c + 3]) - 1.f) * x3;
                red4(base + c, v0, v1, v2, v3);
            }
        }
    }
}

// ---------------- node update (h += msg*rdeg), zero msg, BN partial stats ---------
__global__ __launch_bounds__(256)
void k_update(int statOff) {
    float* stats = g_stats + statOff;
    int tid = threadIdx.x;
    int base = blockIdx.x * 4096;
    float4* h4 = (float4*)g_h;
    float4* m4 = (float4*)g_msg;
    float s[4] = {0.f, 0.f, 0.f, 0.f}, ss[4] = {0.f, 0.f, 0.f, 0.f};
#pragma unroll 4
    for (int i = 0; i < 16; i++) {
        int idx = base + tid + i * 256;
        if (idx < N_NODES * 16) {
            int n = idx >> 4;
            float rdeg = g_deg[n];
            float4 hv = h4[idx];
            float4 mv = m4[idx];
            hv.x += mv.x * rdeg; hv.y += mv.y * rdeg;
            hv.z += mv.z * rdeg; hv.w += mv.w * rdeg;
            h4[idx] = hv;
            m4[idx] = make_float4(0.f, 0.f, 0.f, 0.f);
            s[0] += hv.x; s[1] += hv.y; s[2] += hv.z; s[3] += hv.w;
            ss[0] += hv.x * hv.x; ss[1] += hv.y * hv.y;
            ss[2] += hv.z * hv.z; ss[3] += hv.w * hv.w;
        }
    }
    __shared__ float sA[256][4], sBm[256][4];
#pragma unroll
    for (int p = 0; p < 4; p++) { sA[tid][p] = s[p]; sBm[tid][p] = ss[p]; }
    __syncthreads();
    if (tid < 16) {
        float rs[4] = {0.f, 0.f, 0.f, 0.f}, rss[4] = {0.f, 0.f, 0.f, 0.f};
#pragma unroll
        for (int j = 0; j < 16; j++) {
#pragma unroll
            for (int p = 0; p < 4; p++) {
                rs[p] += sA[tid + 16 * j][p];
                rss[p] += sBm[tid + 16 * j][p];
            }
        }
        int c0 = tid * 4;
#pragma unroll
        for (int p = 0; p < 4; p++) {
            atomicAdd(&stats[c0 + p], rs[p]);
            atomicAdd(&stats[64 + c0 + p], rss[p]);
        }
    }
}

// ---------------- BN apply + relu ----------------
__global__ void k_bnrelu(int statOff, const float* __restrict__ g, const float* __restrict__ b) {
    const float* stats = g_stats + statOff;
    int idx = blockIdx.x * 256 + threadIdx.x;
    int c0 = (idx & 15) * 4;
    const float invn = 1.f / (float)N_NODES;
    float4* hp = ((float4*)g_h) + idx;
    float4 v = *hp;
    float o[4] = {v.x, v.y, v.z, v.w};
#pragma unroll
    for (int i = 0; i < 4; i++) {
        float m = stats[c0 + i] * invn;
        float var = stats[64 + c0 + i] * invn - m * m;
        float sc = rsqrtf(var + BN_EPS) * g[c0 + i];
        o[i] = fmaxf((o[i] - m) * sc + b[c0 + i], 0.f);
    }
    v.x = o[0]; v.y = o[1]; v.z = o[2]; v.w = o[3];
    *hp = v;
}

// ---------------- classifier ----------------
__global__ void k_clf1(const float* __restrict__ W, const float* __restrict__ b) {
    __shared__ float sW[4096], sB[64];
    int tid = threadIdx.x;
    for (int i = tid; i < 4096; i += 256) sW[i] = W[i];
    if (tid < 64) sB[tid] = b[tid];
    __syncthreads();
    int r = blockIdx.x * 256 + tid;
    if (r >= BATCH) return;
    float acc[64];
#pragma unroll
    for (int c = 0; c < 64; c++) acc[c] = sB[c];
#pragma unroll 1
    for (int k = 0; k < 64; k++) {
        float hk = g_h[(size_t)r * 64 + k];
        const float* w = &sW[k * 64];
#pragma unroll
        for (int c = 0; c < 64; c++) acc[c] += hk * w[c];
    }
    float* z = g_z1 + (size_t)r * 64;
    float* st = g_stats + 256;
#pragma unroll 1
    for (int c = 0; c < 64; c++) {
        z[c] = acc[c];
        atomicAdd(&st[c], acc[c]);
        atomicAdd(&st[64 + c], acc[c] * acc[c]);
    }
}

__global__ void k_clf2(const float* __restrict__ W, const float* __restrict__ b,
                       const float* __restrict__ g1, const float* __restrict__ bb1) {
    __shared__ float sW[2048], sB[32], sScale[64], sBias[64];
    int tid = threadIdx.x;
    for (int i = tid; i < 2048; i += 256) sW[i] = W[i];
    if (tid < 32) sB[tid] = b[tid];
    if (tid < 64) {
        const float invn = 1.f / (float)BATCH;
        float m = g_stats[256 + tid] * invn;
        float var = g_stats[256 + 64 + tid] * invn - m * m;
        float sc = rsqrtf(var + BN_EPS) * g1[tid];
        sScale[tid] = sc;
        sBias[tid] = bb1[tid] - m * sc;
    }
    __syncthreads();
    int r = blockIdx.x * 256 + tid;
    if (r >= BATCH) return;
    float acc[32];
#pragma unroll
    for (int c = 0; c < 32; c++) acc[c] = sB[c];
#pragma unroll 1
    for (int k = 0; k < 64; k++) {
        float v = fmaxf(g_z1[(size_t)r * 64 + k] * sScale[k] + sBias[k], 0.f);
        const float* w = &sW[k * 32];
#pragma unroll
        for (int c = 0; c < 32; c++) acc[c] += v * w[c];
    }
    float* z = g_z2 + (size_t)r * 32;
    float* st = g_stats + 384;
#pragma unroll 1
    for (int c = 0; c < 32; c++) {
        z[c] = acc[c];
        atomicAdd(&st[c], acc[c]);
        atomicAdd(&st[32 + c], acc[c] * acc[c]);
    }
}

__global__ void k_clf3(const float* __restrict__ W3, const float* __restrict__ b3,
                       const float* __restrict__ g2, const float* __restrict__ bb2,
                       float* __restrict__ out) {
    __shared__ float sW[32], sScale[32], sBias[32], sb3;
    int tid = threadIdx.x;
    if (tid < 32) {
        sW[tid] = W3[tid];
        const float invn = 1.f / (float)BATCH;
        float m = g_stats[384 + tid] * invn;
        float var = g_stats[384 + 32 + tid] * invn - m * m;
        float sc = rsqrtf(var + BN_EPS) * g2[tid];
        sScale[tid] = sc;
        sBias[tid] = bb2[tid] - m * sc;
    }
    if (tid == 0) sb3 = b3[0];
    __syncthreads();
    int r = blockIdx.x * 256 + tid;
    if (r >= BATCH) return;
    float a = sb3;
#pragma unroll 1
    for (int k = 0; k < 32; k++)
        a += fmaxf(g_z2[(size_t)r * 32 + k] * sScale[k] + sBias[k], 0.f) * sW[k];
    out[r] = a;
}

// ---------------- launch ----------------
extern "C" void kernel_launch(void* const* d_in, const int* in_sizes, int n_in,
                              void* d_out, int out_size) {
    auto ix = [&](int i) { return (n_in >= 28) ? i : (i > 3 ? i - 1 : i); };
    const float* x    = (const float*)d_in[ix(0)];
    const void*  ei   = d_in[ix(1)];
    const float* dts  = (const float*)d_in[ix(2)];
    const float* bf   = (const float*)d_in[ix(4)];
    const float* ph   = (const float*)d_in[ix(5)];
    const float* tW1  = (const float*)d_in[ix(6)];
    const float* tb1  = (const float*)d_in[ix(7)];
    const float* tW2  = (const float*)d_in[ix(8)];
    const float* tb2  = (const float*)d_in[ix(9)];
    const float* pW   = (const float*)d_in[ix(10)];
    const float* pb   = (const float*)d_in[ix(11)];
    const float* sW1  = (const float*)d_in[ix(12)];
    const float* sb1  = (const float*)d_in[ix(13)];
    const float* sW2  = (const float*)d_in[ix(14)];
    const float* sb2  = (const float*)d_in[ix(15)];
    const float* bng  = (const float*)d_in[ix(16)];
    const float* bnb  = (const float*)d_in[ix(17)];
    const float* cW1  = (const float*)d_in[ix(18)];
    const float* cb1  = (const float*)d_in[ix(19)];
    const float* cg1  = (const float*)d_in[ix(20)];
    const float* cbb1 = (const float*)d_in[ix(21)];
    const float* cW2  = (const float*)d_in[ix(22)];
    const float* cb2  = (const float*)d_in[ix(23)];
    const float* cg2  = (const float*)d_in[ix(24)];
    const float* cbb2 = (const float*)d_in[ix(25)];
    const float* cW3  = (const float*)d_in[ix(26)];
    const float* cb3  = (const float*)d_in[ix(27)];
    float* out = (float*)d_out;

    cudaFuncSetAttribute(k_layer_p, cudaFuncAttributeMaxDynamicSharedMemorySize, LP_SMEM_BYTES);

    k_zero_all<<<1024, 256>>>();
    k_convert_idx<<<N_EDGES / 256, 256>>>(ei);
    k_rdeg<<<(N_NODES + 255) / 256, 256>>>();
    k_stage1<<<N_EDGES / 512, 256>>>(x, dts, bf, ph, tW1, tb1, tW2, tb2);
    k_proj<<<(N_NODES + 127) / 128, 256>>>(x, pW, pb);

    for (int l = 0; l < 2; l++) {
        k_prep_w<<<32, 256>>>(sW1 + l * 8192, sW2 + l * 4096);
        k_layer_p<<<304, 128, LP_SMEM_BYTES>>>(sb1 + l * 64, sb2 + l * 64);
        k_update<<<(N_NODES * 16 + 4095) / 4096, 256>>>(l * 128);
        k_bnrelu<<<(N_NODES * HID / 4) / 256, 256>>>(l * 128, bng + l * 64, bnb + l * 64);
    }

    k_clf1<<<(BATCH + 255) / 256, 256>>>(cW1, cb1);
    k_clf2<<<(BATCH + 255) / 256, 256>>>(cW2, cb2, cg1, cbb1);
    k_clf3<<<(BATCH + 255) / 256, 256>>>(cW3, cb3, cg2, cbb2, out);
    (void)in_sizes; (void)out_size;
}

// round 8
// speedup vs baseline: 1.9064x; 1.0303x over previous
#include <cuda_runtime.h>
#include <cuda_bf16.h>
#include <cstdint>

#define N_NODES 100000
#define N_EDGES 1600000
#define IN_CH   17
#define HID     64
#define BATCH   10000
#define BN_EPS  1e-5f

typedef unsigned long long ull;

// ---------------- device scratch ----------------
__device__ float g_h  [(size_t)N_NODES * HID];
__device__ float g_msg[(size_t)N_NODES * HID];
__device__ float g_deg[N_NODES];                 // raw degree, then inverted in-place
__device__ float g_stats[4 * 128];
__device__ float g_z1[BATCH * 64];
__device__ float g_z2[BATCH * 32];
__device__ int   g_src[N_EDGES];
__device__ int   g_dst[N_EDGES];
// pre-packed bf16 hi/lo weight images: W^T row-major [n][k], padded row strides
__device__ __align__(16) unsigned char g_B1hi[64 * 272];   // stride 272B (136 bf16)
__device__ __align__(16) unsigned char g_B1lo[64 * 272];
__device__ __align__(16) unsigned char g_B2hi[64 * 144];   // stride 144B (72 bf16)
__device__ __align__(16) unsigned char g_B2lo[64 * 144];

__device__ __forceinline__ float tanh_fast(float x) {
    float e = __expf(2.f * x);
    return 1.f - __fdividef(2.f, e + 1.f);
}
__device__ __forceinline__ ull pack2(float x) {
    ull r; asm("mov.b64 %0,{%1,%1};" : "=l"(r) : "f"(x)); return r;
}
__device__ __forceinline__ void unpack2(ull a, float& x, float& y) {
    asm("mov.b64 {%0,%1},%2;" : "=f"(x), "=f"(y) : "l"(a));
}
__device__ __forceinline__ void fma2(ull& d, ull a, ull b) {
    asm("fma.rn.f32x2 %0,%1,%2,%0;" : "+l"(d) : "l"(a), "l"(b));
}
__device__ __forceinline__ void red4(float* p, float a, float b, float c, float d) {
    asm volatile("{\n\t.reg .u64 q;\n\tcvta.to.global.u64 q,%0;\n\t"
                 "red.global.add.v4.f32 [q],{%1,%2,%3,%4};\n\t}"
                 :: "l"(p), "f"(a), "f"(b), "f"(c), "f"(d) : "memory");
}
__device__ __forceinline__ uint32_t smem_u32(const void* p) {
    uint32_t a;
    asm("{.reg .u64 t; cvta.to.shared.u64 t, %1; cvt.u32.u64 %0, t;}" : "=r"(a) : "l"(p));
    return a;
}
__device__ __forceinline__ void ldx4(uint32_t* r, uint32_t a) {
    asm volatile("ldmatrix.sync.aligned.m8n8.x4.shared.b16 {%0,%1,%2,%3}, [%4];"
                 : "=r"(r[0]), "=r"(r[1]), "=r"(r[2]), "=r"(r[3]) : "r"(a));
}
__device__ __forceinline__ void mma16816(float* d, const uint32_t* a, uint32_t b0, uint32_t b1) {
    asm volatile("mma.sync.aligned.m16n8k16.row.col.f32.bf16.bf16.f32 "
                 "{%0,%1,%2,%3},{%4,%5,%6,%7},{%8,%9},{%0,%1,%2,%3};"
                 : "+f"(d[0]), "+f"(d[1]), "+f"(d[2]), "+f"(d[3])
                 : "r"(a[0]), "r"(a[1]), "r"(a[2]), "r"(a[3]), "r"(b0), "r"(b1));
}
__device__ __forceinline__ void split2(float x, float y, uint32_t& hi, uint32_t& lo) {
    __nv_bfloat162 h = __float22bfloat162_rn(make_float2(x, y));
    float2 hf = __bfloat1622float2(h);
    __nv_bfloat162 l = __float22bfloat162_rn(make_float2(x - hf.x, y - hf.y));
    hi = *(uint32_t*)&h; lo = *(uint32_t*)&l;
}

// ---------------- edge index conversion + degree ----------------
__global__ void k_convert_idx(const void* __restrict__ ei_raw) {
    __shared__ int s_is64;
    if (threadIdx.x == 0) {
        const unsigned* w = (const unsigned*)ei_raw;
        int is64 = 1;
        for (int i = 1; i < 64; i += 2)
            if (w[i] != 0u) { is64 = 0; break; }
        s_is64 = is64;
    }
    __syncthreads();
    int e = blockIdx.x * 256 + threadIdx.x;
    if (e >= N_EDGES) return;
    int s, d;
    if (s_is64) {
        const long long* p = (const long long*)ei_raw;
        s = (int)p[e]; d = (int)p[(size_t)N_EDGES + e];
    } else {
        const int* p = (const int*)ei_raw;
        s = p[e]; d = p[N_EDGES + e];
    }
    g_src[e] = s; g_dst[e] = d;
    atomicAdd(&g_deg[d], 1.f);
}

// ---------------- zero scratch (vectorized) ----------------
__global__ void k_zero_all() {
    int i = blockIdx.x * 256 + threadIdx.x;
    int st = gridDim.x * 256;
    float4 z = make_float4(0.f, 0.f, 0.f, 0.f);
    float4* m4 = (float4*)g_msg;
    for (int k = i; k < N_NODES * HID / 4; k += st) m4[k] = z;
    for (int k = i; k < N_NODES; k += st) g_deg[k] = 0.f;
    if (i < 512) g_stats[i] = 0.f;
}

// ---------------- invert degree in place ----------------
__global__ void k_rdeg() {
    int n = blockIdx.x * 256 + threadIdx.x;
    if (n < N_NODES) g_deg[n] = 1.f / fmaxf(g_deg[n], 1.f);
}

// ---------------- weight prep: W^T -> bf16 hi/lo padded row-major images ----------
__global__ void k_prep_w(const float* __restrict__ W1, const float* __restrict__ W2) {
    int idx = blockIdx.x * 256 + threadIdx.x;
    if (idx < 8192) {                 // B1[n][k] = W1[k*64+n], n<64, k<128
        int n = idx >> 7, k = idx & 127;
        float w = W1[k * 64 + n];
        __nv_bfloat16 h = __float2bfloat16_rn(w);
        __nv_bfloat16 l = __float2bfloat16_rn(w - __bfloat162float(h));
        uint32_t off = (uint32_t)n * 272u + 2u * (uint32_t)k;
        *(__nv_bfloat16*)(g_B1hi + off) = h;
        *(__nv_bfloat16*)(g_B1lo + off) = l;
    }
    if (idx < 4096) {                 // B2[n][k] = W2[k*64+n], n<64, k<64
        int n = idx >> 6, k = idx & 63;
        float w = W2[k * 64 + n];
        __nv_bfloat16 h = __float2bfloat16_rn(w);
        __nv_bfloat16 l = __float2bfloat16_rn(w - __bfloat162float(h));
        uint32_t off = (uint32_t)n * 144u + 2u * (uint32_t)k;
        *(__nv_bfloat16*)(g_B2hi + off) = h;
        *(__nv_bfloat16*)(g_B2lo + off) = l;
    }
}

// ---------------- stage 1: temporal edge MLP (66 -> 33 -> 17), 2 edges/thread ----
__global__ __launch_bounds__(256)
void k_stage1(const float* __restrict__ x,
              const float* __restrict__ dts, const float* __restrict__ bf,
              const float* __restrict__ ph,
              const float* __restrict__ W1, const float* __restrict__ b1,
              const float* __restrict__ W2, const float* __restrict__ b2) {
    __shared__ float sW1[66 * 36];
    __shared__ float sW2[33 * 20];
    __shared__ __align__(16) float sB1[34], sB2[18], sF[32], sP[32];
    int tid = threadIdx.x;
    for (int i = tid; i < 66 * 33; i += 256) {
        int r = i / 33, c = i - r * 33;
        sW1[r * 36 + c] = W1[i];
    }
    for (int i = tid; i < 33 * 17; i += 256) {
        int r = i / 17, c = i - r * 17;
        sW2[r * 20 + c] = W2[i];
    }
    if (tid < 33) sB1[tid] = b1[tid];
    if (tid < 17) sB2[tid] = b2[tid];
    if (tid < 32) { sF[tid] = bf[tid]; sP[tid] = ph[tid]; }
    __syncthreads();

    int e0 = blockIdx.x * 512 + tid;
    int e1 = e0 + 256;
    int s0 = g_src[e0], d0 = g_dst[e0];
    int s1 = g_src[e1], d1 = g_dst[e1];
    float dt0 = dts[e0], dt1 = dts[e1];

    const float* xd0 = x + (size_t)d0 * IN_CH;
    const float* xs0 = x + (size_t)s0 * IN_CH;
    const float* xd1 = x + (size_t)d1 * IN_CH;
    const float* xs1 = x + (size_t)s1 * IN_CH;

    ull a0[16], a1[16];
    float t0, t1;
    {
        const ull* bp = (const ull*)sB1;
#pragma unroll
        for (int p = 0; p < 16; p++) { a0[p] = bp[p]; a1[p] = bp[p]; }
        t0 = sB1[32]; t1 = sB1[32];
    }

#define S1_ROW(ROW, V0, V1)                                             \
    {                                                                   \
        ull m0 = pack2(V0), m1 = pack2(V1);                             \
        const ulonglong2* wp = (const ulonglong2*)(sW1 + (ROW) * 36);   \
        ulonglong2 wa = wp[0], wb = wp[1], wc = wp[2], wd = wp[3];      \
        ulonglong2 we = wp[4], wf = wp[5], wg = wp[6], wh = wp[7];      \
        fma2(a0[0], m0, wa.x);  fma2(a1[0], m1, wa.x);                  \
        fma2(a0[1], m0, wa.y);  fma2(a1[1], m1, wa.y);                  \
        fma2(a0[2], m0, wb.x);  fma2(a1[2], m1, wb.x);                  \
        fma2(a0[3], m0, wb.y);  fma2(a1[3], m1, wb.y);                  \
        fma2(a0[4], m0, wc.x);  fma2(a1[4], m1, wc.x);                  \
        fma2(a0[5], m0, wc.y);  fma2(a1[5], m1, wc.y);                  \
        fma2(a0[6], m0, wd.x);  fma2(a1[6], m1, wd.x);                  \
        fma2(a0[7], m0, wd.y);  fma2(a1[7], m1, wd.y);                  \
        fma2(a0[8], m0, we.x);  fma2(a1[8], m1, we.x);                  \
        fma2(a0[9], m0, we.y);  fma2(a1[9], m1, we.y);                  \
        fma2(a0[10], m0, wf.x); fma2(a1[10], m1, wf.x);                 \
        fma2(a0[11], m0, wf.y); fma2(a1[11], m1, wf.y);                 \
        fma2(a0[12], m0, wg.x); fma2(a1[12], m1, wg.x);                 \
        fma2(a0[13], m0, wg.y); fma2(a1[13], m1, wg.y);                 \
        fma2(a0[14], m0, wh.x); fma2(a1[14], m1, wh.x);                 \
        fma2(a0[15], m0, wh.y); fma2(a1[15], m1, wh.y);                 \
        float ws = sW1[(ROW) * 36 + 32];                                \
        t0 = fmaf(V0, ws, t0); t1 = fmaf(V1, ws, t1);                   \
    }

#pragma unroll 1
    for (int i = 0; i < 17; i++) { float v0 = xd0[i], v1 = xd1[i]; S1_ROW(i, v0, v1); }
#pragma unroll 1
    for (int i = 0; i < 17; i++) { float v0 = xs0[i], v1 = xs1[i]; S1_ROW(17 + i, v0, v1); }
#pragma unroll 1
    for (int t = 0; t < 32; t++) {
        float f = sF[t], p = sP[t];
        float v0 = __cosf(dt0 * f + p);
        float v1 = __cosf(dt1 * f + p);
        S1_ROW(34 + t, v0, v1);
    }

    float h0[33], h1[33];
#pragma unroll
    for (int p = 0; p < 16; p++) {
        unpack2(a0[p], h0[2 * p], h0[2 * p + 1]);
        unpack2(a1[p], h1[2 * p], h1[2 * p + 1]);
    }
    h0[32] = t0; h1[32] = t1;
#pragma unroll
    for (int i = 0; i < 33; i++) { h0[i] = fmaxf(h0[i], 0.f); h1[i] = fmaxf(h1[i], 0.f); }

    ull c0[8], c1[8]; float q0, q1;
    {
        const ull* bp = (const ull*)sB2;
#pragma unroll
        for (int p = 0; p < 8; p++) { c0[p] = bp[p]; c1[p] = bp[p]; }
        q0 = sB2[16]; q1 = sB2[16];
    }
#pragma unroll 1
    for (int i = 0; i < 33; i++) {
        ull m0 = pack2(h0[i]), m1 = pack2(h1[i]);
        const ulonglong2* wp = (const ulonglong2*)(sW2 + i * 20);
        ulonglong2 wa = wp[0], wb = wp[1], wc = wp[2], wd = wp[3];
        fma2(c0[0], m0, wa.x); fma2(c1[0], m1, wa.x);
        fma2(c0[1], m0, wa.y); fma2(c1[1], m1, wa.y);
        fma2(c0[2], m0, wb.x); fma2(c1[2], m1, wb.x);
        fma2(c0[3], m0, wb.y); fma2(c1[3], m1, wb.y);
        fma2(c0[4], m0, wc.x); fma2(c1[4], m1, wc.x);
        fma2(c0[5], m0, wc.y); fma2(c1[5], m1, wc.y);
        fma2(c0[6], m0, wd.x); fma2(c1[6], m1, wd.x);
        fma2(c0[7], m0, wd.y); fma2(c1[7], m1, wd.y);
        float ws = sW2[i * 20 + 16];
        q0 = fmaf(h0[i], ws, q0); q1 = fmaf(h1[i], ws, q1);
    }

    {
        float pv[17];
#pragma unroll
        for (int p = 0; p < 8; p++) unpack2(c0[p], pv[2 * p], pv[2 * p + 1]);
        pv[16] = q0;
        float m[17];
#pragma unroll
        for (int j = 0; j < 17; j++) m[j] = (2.f * tanh_fast(pv[j]) - 1.f) * xd0[j];
        float* base = g_msg + (size_t)d0 * 64;
        red4(base + 0, m[0], m[1], m[2], m[3]);
        red4(base + 4, m[4], m[5], m[6], m[7]);
        red4(base + 8, m[8], m[9], m[10], m[11]);
        red4(base + 12, m[12], m[13], m[14], m[15]);
        atomicAdd(base + 16, m[16]);
    }
    {
        float pv[17];
#pragma unroll
        for (int p = 0; p < 8; p++) unpack2(c1[p], pv[2 * p], pv[2 * p + 1]);
        pv[16] = q1;
        float m[17];
#pragma unroll
        for (int j = 0; j < 17; j++) m[j] = (2.f * tanh_fast(pv[j]) - 1.f) * xd1[j];
        float* base = g_msg + (size_t)d1 * 64;
        red4(base + 0, m[0], m[1], m[2], m[3]);
        red4(base + 4, m[4], m[5], m[6], m[7]);
        red4(base + 8, m[8], m[9], m[10], m[11]);
        red4(base + 12, m[12], m[13], m[14], m[15]);
        atomicAdd(base + 16, m[16]);
    }
}

// ---------------- node update + projection: h = (x + msg*rdeg) @ PW + Pb ----------
__global__ __launch_bounds__(256)
void k_proj(const float* __restrict__ x, const float* __restrict__ PW,
            const float* __restrict__ Pb) {
    __shared__ float sW[17 * 64];
    __shared__ __align__(16) float sB[64];
    int tid = threadIdx.x;
    for (int i = tid; i < 17 * 64; i += 256) sW[i] = PW[i];
    if (tid < 64) sB[tid] = Pb[tid];
    __syncthreads();

    int n = blockIdx.x * 128 + (tid >> 1);
    int q = tid & 1;
    if (n >= N_NODES) return;
    float rdeg = g_deg[n];

    ull acc[16];
    {
        const ull* bp = (const ull*)(sB + 32 * q);
#pragma unroll
        for (int p = 0; p < 16; p++) acc[p] = bp[p];
    }

    const float* xp = x + (size_t)n * 17;
    float* mp = g_msg + (size_t)n * 64;

#pragma unroll 1
    for (int k = 0; k < 17; k++) {
        float xm = xp[k] + mp[k] * rdeg;
        ull m = pack2(xm);
        const ulonglong2* wp = (const ulonglong2*)(sW + k * 64 + 32 * q);
#pragma unroll
        for (int h = 0; h < 8; h++) {
            ulonglong2 w = wp[h];
            fma2(acc[2 * h], m, w.x);
            fma2(acc[2 * h + 1], m, w.y);
        }
    }

    float* hp = g_h + (size_t)n * 64 + 32 * q;
#pragma unroll
    for (int h = 0; h < 8; h++) {
        float a, b2, c, d;
        unpack2(acc[2 * h], a, b2);
        unpack2(acc[2 * h + 1], c, d);
        *(float4*)(hp + 4 * h) = make_float4(a, b2, c, d);
    }
    if (q == 0) {
        float4 z = make_float4(0.f, 0.f, 0.f, 0.f);
        *(float4*)(mp + 0) = z; *(float4*)(mp + 4) = z;
        *(float4*)(mp + 8) = z; *(float4*)(mp + 12) = z;
        mp[16] = 0.f;
    }
}

// ---------------- stage 2 layer kernel: warp-independent HMMA pipelines ----------
// 128 threads = 4 independent warps, each owning a 16-edge chunk pipeline.
// Weights (B images) CTA-shared; A1/A2/H2 are per-warp slices; H2 aliases A2.
// NO __syncthreads in the loop — all hazards are warp-local.
#define LW_SLICE 13312
#define LK_SMEM_BYTES (53760 + 4 * LW_SLICE)   // 107008
__global__ __launch_bounds__(128, 2)
void k_layer_w(const float* __restrict__ b1, const float* __restrict__ b2) {
    extern __shared__ unsigned char sm[];
    const uint32_t O_B1H = 0, O_B1L = 17408, O_B2H = 34816, O_B2L = 44032;
    const uint32_t O_BI1 = 53248, O_BI2 = 53504, O_WARP = 53760;
    // per-warp slice offsets
    const uint32_t S_A1H = 0, S_A1L = 4352, S_A2H = 8704, S_A2L = 11008, S_H2 = 8704;

    uint32_t sb = smem_u32(sm);
    int tid = threadIdx.x;
    int w = tid >> 5, l = tid & 31;

    float* sB1f = (float*)(sm + O_BI1);
    float* sB2f = (float*)(sm + O_BI2);
    if (tid < 64) { sB1f[tid] = b1[tid]; sB2f[tid] = b2[tid]; }
    {
        const float4* s; float4* d;
        s = (const float4*)g_B1hi; d = (float4*)(sm + O_B1H);
        for (int i = tid; i < 1088; i += 128) d[i] = s[i];
        s = (const float4*)g_B1lo; d = (float4*)(sm + O_B1L);
        for (int i = tid; i < 1088; i += 128) d[i] = s[i];
        s = (const float4*)g_B2hi; d = (float4*)(sm + O_B2H);
        for (int i = tid; i < 576; i += 128) d[i] = s[i];
        s = (const float4*)g_B2lo; d = (float4*)(sm + O_B2L);
        for (int i = tid; i < 576; i += 128) d[i] = s[i];
    }
    __syncthreads();   // only block-wide sync: weights+biases visible

    unsigned char* wbp = sm + O_WARP + (uint32_t)w * LW_SLICE;
    uint32_t wb = sb + O_WARP + (uint32_t)w * LW_SLICE;

    int e = l >> 1, q = l & 1;                       // edge-in-chunk, row half
    uint32_t arow = (uint32_t)((l & 7) + ((l >> 3) & 1) * 8);
    uint32_t acol = (uint32_t)(l >> 4) * 16u;
    uint32_t brow = (uint32_t)((l & 7) + ((l >> 3) & 2) * 4);
    uint32_t bk = (uint32_t)((l >> 3) & 1) * 16u;

    int gw = blockIdx.x * 4 + w;
    int nw = gridDim.x * 4;

    for (int ch = gw; ch < N_EDGES / 16; ch += nw) {
        int ge = ch * 16 + e;
        int dn = g_dst[ge];
        int row = q ? g_src[ge] : dn;

        // gather: A1[e] = bf16 hi/lo of [h_dst | h_src]
        {
            const float4* hp = (const float4*)(g_h + (size_t)row * 64);
            uint32_t bo = S_A1H + (uint32_t)e * 272u + (q ? 128u : 0u);
#pragma unroll
            for (int i = 0; i < 16; i++) {
                float4 v = hp[i];
                uint32_t h01, l01, h23, l23;
                split2(v.x, v.y, h01, l01);
                split2(v.z, v.w, h23, l23);
                *(uint2*)(wbp + bo + 8u * i) = make_uint2(h01, h23);
                *(uint2*)(wbp + bo + (S_A1L - S_A1H) + 8u * i) = make_uint2(l01, l23);
            }
        }
        __syncwarp();

        // GEMM1: D1 = m_in @ W1 (3-term hi/lo split), K=128
        float d1[8][4];
#pragma unroll
        for (int t = 0; t < 8; t++)
#pragma unroll
            for (int p = 0; p < 4; p++) d1[t][p] = 0.f;
        {
            uint32_t aAh = wb + S_A1H + arow * 272u + acol;
            uint32_t aAl = wb + S_A1L + arow * 272u + acol;
            uint32_t aBh = sb + O_B1H + brow * 272u + bk;
            uint32_t aBl = sb + O_B1L + brow * 272u + bk;
#pragma unroll
            for (int ks = 0; ks < 8; ks++) {
                uint32_t ah[4], al[4];
                ldx4(ah, aAh + 32u * ks);
                ldx4(al, aAl + 32u * ks);
#pragma unroll
                for (int tp = 0; tp < 4; tp++) {
                    uint32_t bh[4], bl[4];
                    uint32_t toff = (uint32_t)tp * (16u * 272u) + 32u * ks;
                    ldx4(bh, aBh + toff);
                    ldx4(bl, aBl + toff);
                    mma16816(d1[2 * tp],     ah, bh[0], bh[1]);
                    mma16816(d1[2 * tp + 1], ah, bh[2], bh[3]);
                    mma16816(d1[2 * tp],     al, bh[0], bh[1]);
                    mma16816(d1[2 * tp + 1], al, bh[2], bh[3]);
                    mma16816(d1[2 * tp],     ah, bl[0], bl[1]);
                    mma16816(d1[2 * tp + 1], ah, bl[2], bl[3]);
                }
            }
        }

        // epilogue1: bias + relu + split -> A2 (warp-local rows)
        {
            int r0 = l >> 2;
            int cc = 2 * (l & 3);
#pragma unroll
            for (int t = 0; t < 8; t++) {
                int c = 8 * t + cc;
                float f0 = fmaxf(d1[t][0] + sB1f[c], 0.f);
                float f1 = fmaxf(d1[t][1] + sB1f[c + 1], 0.f);
                float f2 = fmaxf(d1[t][2] + sB1f[c], 0.f);
                float f3 = fmaxf(d1[t][3] + sB1f[c + 1], 0.f);
                uint32_t h01, l01, h23, l23;
                split2(f0, f1, h01, l01);
                split2(f2, f3, h23, l23);
                uint32_t o0 = (uint32_t)r0 * 144u + (uint32_t)c * 2u;
                uint32_t o1 = (uint32_t)(r0 + 8) * 144u + (uint32_t)c * 2u;
                *(uint32_t*)(wbp + S_A2H + o0) = h01;
                *(uint32_t*)(wbp + S_A2L + o0) = l01;
                *(uint32_t*)(wbp + S_A2H + o1) = h23;
                *(uint32_t*)(wbp + S_A2L + o1) = l23;
            }
        }
        __syncwarp();

        // GEMM2: D2 = hidden @ W2, K=64
        float d2[8][4];
#pragma unroll
        for (int t = 0; t < 8; t++)
#pragma unroll
            for (int p = 0; p < 4; p++) d2[t][p] = 0.f;
        {
            uint32_t aAh = wb + S_A2H + arow * 144u + acol;
            uint32_t aAl = wb + S_A2L + arow * 144u + acol;
            uint32_t aBh = sb + O_B2H + brow * 144u + bk;
            uint32_t aBl = sb + O_B2L + brow * 144u + bk;
#pragma unroll
            for (int ks = 0; ks < 4; ks++) {
                uint32_t ah[4], al[4];
                ldx4(ah, aAh + 32u * ks);
                ldx4(al, aAl + 32u * ks);
#pragma unroll
                for (int tp = 0; tp < 4; tp++) {
                    uint32_t bh[4], bl[4];
                    uint32_t toff = (uint32_t)tp * (16u * 144u) + 32u * ks;
                    ldx4(bh, aBh + toff);
                    ldx4(bl, aBl + toff);
                    mma16816(d2[2 * tp],     ah, bh[0], bh[1]);
                    mma16816(d2[2 * tp + 1], ah, bh[2], bh[3]);
                    mma16816(d2[2 * tp],     al, bh[0], bh[1]);
                    mma16816(d2[2 * tp + 1], al, bh[2], bh[3]);
                    mma16816(d2[2 * tp],     ah, bl[0], bl[1]);
                    mma16816(d2[2 * tp + 1], ah, bl[2], bl[3]);
                }
            }
        }
        __syncwarp();   // all lanes past GEMM2's A2 reads before H2 (alias) writes

        // epilogue2: raw D2 -> H2 fp32 (stride 66 floats; aliases dead A2)
        {
            int r0 = l >> 2;
            int cc = 2 * (l & 3);
#pragma unroll
            for (int t = 0; t < 8; t++) {
                int c = 8 * t + cc;
                *(float2*)(wbp + S_H2 + ((uint32_t)r0 * 66u + (uint32_t)c) * 4u)
                    = make_float2(d2[t][0], d2[t][1]);
                *(float2*)(wbp + S_H2 + ((uint32_t)(r0 + 8) * 66u + (uint32_t)c) * 4u)
                    = make_float2(d2[t][2], d2[t][3]);
            }
        }
        __syncwarp();

        // scatter: lane (e,q) handles cols q*32..q*32+31 of edge e
        {
            const float* hr = (const float*)(wbp + S_H2) + e * 66 + q * 32;
            const float* b2p = sB2f + q * 32;
            float* base = g_msg + (size_t)dn * 64 + q * 32;
            uint32_t a1o = S_A1H + (uint32_t)e * 272u + (uint32_t)q * 64u;  // dst half
#pragma unroll
            for (int c = 0; c < 32; c += 4) {
                uint32_t hu0 = *(uint32_t*)(wbp + a1o + 2u * c);
                uint32_t hu1 = *(uint32_t*)(wbp + a1o + 2u * c + 4u);
                uint32_t lu0 = *(uint32_t*)(wbp + (S_A1L - S_A1H) + a1o + 2u * c);
                uint32_t lu1 = *(uint32_t*)(wbp + (S_A1L - S_A1H) + a1o + 2u * c + 4u);
                float2 h0f = __bfloat1622float2(*(__nv_bfloat162*)&hu0);
                float2 h1f = __bfloat1622float2(*(__nv_bfloat162*)&hu1);
                float2 l0f = __bfloat1622float2(*(__nv_bfloat162*)&lu0);
                float2 l1f = __bfloat1622float2(*(__nv_bfloat162*)&lu1);
                float x0 = h0f.x + l0f.x, x1 = h0f.y + l0f.y;
                float x2 = h1f.x + l1f.x, x3 = h1f.y + l1f.y;
                float v0 = (2.f * tanh_fast(hr[c + 0] + b2p[c + 0]) - 1.f) * x0;
                float v1 = (2.f * tanh_fast(hr[c + 1] + b2p[c + 1]) - 1.f) * x1;
                float v2 = (2.f * tanh_fast(hr[c + 2] + b2p[c + 2]) - 1.f) * x2;
                float v3 = (2.f * tanh_fast(hr[c + 3] + b2p[c + 3]) - 1.f) * x3;
                red4(base + c, v0, v1, v2, v3);
            }
        }
        __syncwarp();   // scatter's A1/H2 reads done before next gather overwrites
    }
}

// ---------------- node update (h += msg*rdeg), zero msg, BN partial stats ---------
__global__ __launch_bounds__(256)
void k_update(int statOff) {
    float* stats = g_stats + statOff;
    int tid = threadIdx.x;
    int base = blockIdx.x * 4096;
    float4* h4 = (float4*)g_h;
    float4* m4 = (float4*)g_msg;
    float s[4] = {0.f, 0.f, 0.f, 0.f}, ss[4] = {0.f, 0.f, 0.f, 0.f};
#pragma unroll 4
    for (int i = 0; i < 16; i++) {
        int idx = base + tid + i * 256;
        if (idx < N_NODES * 16) {
            int n = idx >> 4;
            float rdeg = g_deg[n];
            float4 hv = h4[idx];
            float4 mv = m4[idx];
            hv.x += mv.x * rdeg; hv.y += mv.y * rdeg;
            hv.z += mv.z * rdeg; hv.w += mv.w * rdeg;
            h4[idx] = hv;
            m4[idx] = make_float4(0.f, 0.f, 0.f, 0.f);
            s[0] += hv.x; s[1] += hv.y; s[2] += hv.z; s[3] += hv.w;
            ss[0] += hv.x * hv.x; ss[1] += hv.y * hv.y;
            ss[2] += hv.z * hv.z; ss[3] += hv.w * hv.w;
        }
    }
    __shared__ float sA[256][4], sBm[256][4];
#pragma unroll
    for (int p = 0; p < 4; p++) { sA[tid][p] = s[p]; sBm[tid][p] = ss[p]; }
    __syncthreads();
    if (tid < 16) {
        float rs[4] = {0.f, 0.f, 0.f, 0.f}, rss[4] = {0.f, 0.f, 0.f, 0.f};
#pragma unroll
        for (int j = 0; j < 16; j++) {
#pragma unroll
            for (int p = 0; p < 4; p++) {
                rs[p] += sA[tid + 16 * j][p];
                rss[p] += sBm[tid + 16 * j][p];
            }
        }
        int c0 = tid * 4;
#pragma unroll
        for (int p = 0; p < 4; p++) {
            atomicAdd(&stats[c0 + p], rs[p]);
            atomicAdd(&stats[64 + c0 + p], rss[p]);
        }
    }
}

// ---------------- BN apply + relu ----------------
__global__ void k_bnrelu(int statOff, const float* __restrict__ g, const float* __restrict__ b) {
    const float* stats = g_stats + statOff;
    int idx = blockIdx.x * 256 + threadIdx.x;
    int c0 = (idx & 15) * 4;
    const float invn = 1.f / (float)N_NODES;
    float4* hp = ((float4*)g_h) + idx;
    float4 v = *hp;
    float o[4] = {v.x, v.y, v.z, v.w};
#pragma unroll
    for (int i = 0; i < 4; i++) {
        float m = stats[c0 + i] * invn;
        float var = stats[64 + c0 + i] * invn - m * m;
        float sc = rsqrtf(var + BN_EPS) * g[c0 + i];
        o[i] = fmaxf((o[i] - m) * sc + b[c0 + i], 0.f);
    }
    v.x = o[0]; v.y = o[1]; v.z = o[2]; v.w = o[3];
    *hp = v;
}

// ---------------- classifier ----------------
__global__ void k_clf1(const float* __restrict__ W, const float* __restrict__ b) {
    __shared__ float sW[4096], sB[64];
    int tid = threadIdx.x;
    for (int i = tid; i < 4096; i += 256) sW[i] = W[i];
    if (tid < 64) sB[tid] = b[tid];
    __syncthreads();
    int r = blockIdx.x * 256 + tid;
    if (r >= BATCH) return;
    float acc[64];
#pragma unroll
    for (int c = 0; c < 64; c++) acc[c] = sB[c];
#pragma unroll 1
    for (int k = 0; k < 64; k++) {
        float hk = g_h[(size_t)r * 64 + k];
        const float* w = &sW[k * 64];
#pragma unroll
        for (int c = 0; c < 64; c++) acc[c] += hk * w[c];
    }
    float* z = g_z1 + (size_t)r * 64;
    float* st = g_stats + 256;
#pragma unroll 1
    for (int c = 0; c < 64; c++) {
        z[c] = acc[c];
        atomicAdd(&st[c], acc[c]);
        atomicAdd(&st[64 + c], acc[c] * acc[c]);
    }
}

__global__ void k_clf2(const float* __restrict__ W, const float* __restrict__ b,
                       const float* __restrict__ g1, const float* __restrict__ bb1) {
    __shared__ float sW[2048], sB[32], sScale[64], sBias[64];
    int tid = threadIdx.x;
    for (int i = tid; i < 2048; i += 256) sW[i] = W[i];
    if (tid < 32) sB[tid] = b[tid];
    if (tid < 64) {
        const float invn = 1.f / (float)BATCH;
        float m = g_stats[256 + tid] * invn;
        float var = g_stats[256 + 64 + tid] * invn - m * m;
        float sc = rsqrtf(var + BN_EPS) * g1[tid];
        sScale[tid] = sc;
        sBias[tid] = bb1[tid] - m * sc;
    }
    __syncthreads();
    int r = blockIdx.x * 256 + tid;
    if (r >= BATCH) return;
    float acc[32];
#pragma unroll
    for (int c = 0; c < 32; c++) acc[c] = sB[c];
#pragma unroll 1
    for (int k = 0; k < 64; k++) {
        float v = fmaxf(g_z1[(size_t)r * 64 + k] * sScale[k] + sBias[k], 0.f);
        const float* w = &sW[k * 32];
#pragma unroll
        for (int c = 0; c < 32; c++) acc[c] += v * w[c];
    }
    float* z = g_z2 + (size_t)r * 32;
    float* st = g_stats + 384;
#pragma unroll 1
    for (int c = 0; c < 32; c++) {
        z[c] = acc[c];
        atomicAdd(&st[c], acc[c]);
        atomicAdd(&st[32 + c], acc[c] * acc[c]);
    }
}

__global__ void k_clf3(const float* __restrict__ W3, const float* __restrict__ b3,
                       const float* __restrict__ g2, const float* __restrict__ bb2,
                       float* __restrict__ out) {
    __shared__ float sW[32], sScale[32], sBias[32], sb3;
    int tid = threadIdx.x;
    if (tid < 32) {
        sW[tid] = W3[tid];
        const float invn = 1.f / (float)BATCH;
        float m = g_stats[384 + tid] * invn;
        float var = g_stats[384 + 32 + tid] * invn - m * m;
        float sc = rsqrtf(var + BN_EPS) * g2[tid];
        sScale[tid] = sc;
        sBias[tid] = bb2[tid] - m * sc;
    }
    if (tid == 0) sb3 = b3[0];
    __syncthreads();
    int r = blockIdx.x * 256 + tid;
    if (r >= BATCH) return;
    float a = sb3;
#pragma unroll 1
    for (int k = 0; k < 32; k++)
        a += fmaxf(g_z2[(size_t)r * 32 + k] * sScale[k] + sBias[k], 0.f) * sW[k];
    out[r] = a;
}

// ---------------- launch ----------------
extern "C" void kernel_launch(void* const* d_in, const int* in_sizes, int n_in,
                              void* d_out, int out_size) {
    auto ix = [&](int i) { return (n_in >= 28) ? i : (i > 3 ? i - 1 : i); };
    const float* x    = (const float*)d_in[ix(0)];
    const void*  ei   = d_in[ix(1)];
    const float* dts  = (const float*)d_in[ix(2)];
    const float* bf   = (const float*)d_in[ix(4)];
    const float* ph   = (const float*)d_in[ix(5)];
    const float* tW1  = (const float*)d_in[ix(6)];
    const float* tb1  = (const float*)d_in[ix(7)];
    const float* tW2  = (const float*)d_in[ix(8)];
    const float* tb2  = (const float*)d_in[ix(9)];
    const float* pW   = (const float*)d_in[ix(10)];
    const float* pb   = (const float*)d_in[ix(11)];
    const float* sW1  = (const float*)d_in[ix(12)];
    const float* sb1  = (const float*)d_in[ix(13)];
    const float* sW2  = (const float*)d_in[ix(14)];
    const float* sb2  = (const float*)d_in[ix(15)];
    const float* bng  = (const float*)d_in[ix(16)];
    const float* bnb  = (const float*)d_in[ix(17)];
    const float* cW1  = (const float*)d_in[ix(18)];
    const float* cb1  = (const float*)d_in[ix(19)];
    const float* cg1  = (const float*)d_in[ix(20)];
    const float* cbb1 = (const float*)d_in[ix(21)];
    const float* cW2  = (const float*)d_in[ix(22)];
    const float* cb2  = (const float*)d_in[ix(23)];
    const float* cg2  = (const float*)d_in[ix(24)];
    const float* cbb2 = (const float*)d_in[ix(25)];
    const float* cW3  = (const float*)d_in[ix(26)];
    const float* cb3  = (const float*)d_in[ix(27)];
    float* out = (float*)d_out;

    cudaFuncSetAttribute(k_layer_w, cudaFuncAttributeMaxDynamicSharedMemorySize, LK_SMEM_BYTES);

    k_zero_all<<<1024, 256>>>();
    k_convert_idx<<<N_EDGES / 256, 256>>>(ei);
    k_rdeg<<<(N_NODES + 255) / 256, 256>>>();
    k_stage1<<<N_EDGES / 512, 256>>>(x, dts, bf, ph, tW1, tb1, tW2, tb2);
    k_proj<<<(N_NODES + 127) / 128, 256>>>(x, pW, pb);

    for (int l = 0; l < 2; l++) {
        k_prep_w<<<32, 256>>>(sW1 + l * 8192, sW2 + l * 4096);
        k_layer_w<<<296, 128, LK_SMEM_BYTES>>>(sb1 + l * 64, sb2 + l * 64);
        k_update<<<(N_NODES * 16 + 4095) / 4096, 256>>>(l * 128);
        k_bnrelu<<<(N_NODES * HID / 4) / 256, 256>>>(l * 128, bng + l * 64, bnb + l * 64);
    }

    k_clf1<<<(BATCH + 255) / 256, 256>>>(cW1, cb1);
    k_clf2<<<(BATCH + 255) / 256, 256>>>(cW2, cb2, cg1, cbb1);
    k_clf3<<<(BATCH + 255) / 256, 256>>>(cW3, cb3, cg2, cbb2, out);
    (void)in_sizes; (void)out_size;
}

// round 9
// speedup vs baseline: 2.0010x; 1.0496x over previous
#include <cuda_runtime.h>
#include <cuda_bf16.h>
#include <cstdint>

#define N_NODES 100000
#define N_EDGES 1600000
#define IN_CH   17
#define HID     64
#define BATCH   10000
#define BN_EPS  1e-5f

typedef unsigned long long ull;

// ---------------- device scratch ----------------
__device__ float g_h  [(size_t)N_NODES * HID];
__device__ float g_msg[(size_t)N_NODES * HID];
__device__ float g_P  [(size_t)N_NODES * 128];   // per-node GEMM1 precompute
__device__ float g_deg[N_NODES];                 // raw degree, then inverted in-place
__device__ float g_stats[4 * 128];
__device__ float g_z1[BATCH * 64];
__device__ float g_z2[BATCH * 32];
__device__ int   g_src[N_EDGES];
__device__ int   g_dst[N_EDGES];
// pre-packed bf16 hi/lo weight images (W^T row-major [n][k], row stride 144B)
__device__ __align__(16) unsigned char g_BPhi[128 * 144];  // W1 combined [128 n][64 k]
__device__ __align__(16) unsigned char g_BPlo[128 * 144];
__device__ __align__(16) unsigned char g_B2hi[64 * 144];   // W2 [64 n][64 k]
__device__ __align__(16) unsigned char g_B2lo[64 * 144];

__device__ __forceinline__ float tanh_fast(float x) {
    float e = __expf(2.f * x);
    return 1.f - __fdividef(2.f, e + 1.f);
}
__device__ __forceinline__ ull pack2(float x) {
    ull r; asm("mov.b64 %0,{%1,%1};" : "=l"(r) : "f"(x)); return r;
}
__device__ __forceinline__ void unpack2(ull a, float& x, float& y) {
    asm("mov.b64 {%0,%1},%2;" : "=f"(x), "=f"(y) : "l"(a));
}
__device__ __forceinline__ void fma2(ull& d, ull a, ull b) {
    asm("fma.rn.f32x2 %0,%1,%2,%0;" : "+l"(d) : "l"(a), "l"(b));
}
__device__ __forceinline__ void red4(float* p, float a, float b, float c, float d) {
    asm volatile("{\n\t.reg .u64 q;\n\tcvta.to.global.u64 q,%0;\n\t"
                 "red.global.add.v4.f32 [q],{%1,%2,%3,%4};\n\t}"
                 :: "l"(p), "f"(a), "f"(b), "f"(c), "f"(d) : "memory");
}
__device__ __forceinline__ uint32_t smem_u32(const void* p) {
    uint32_t a;
    asm("{.reg .u64 t; cvta.to.shared.u64 t, %1; cvt.u32.u64 %0, t;}" : "=r"(a) : "l"(p));
    return a;
}
__device__ __forceinline__ void ldx4(uint32_t* r, uint32_t a) {
    asm volatile("ldmatrix.sync.aligned.m8n8.x4.shared.b16 {%0,%1,%2,%3}, [%4];"
                 : "=r"(r[0]), "=r"(r[1]), "=r"(r[2]), "=r"(r[3]) : "r"(a));
}
__device__ __forceinline__ void mma16816(float* d, const uint32_t* a, uint32_t b0, uint32_t b1) {
    asm volatile("mma.sync.aligned.m16n8k16.row.col.f32.bf16.bf16.f32 "
                 "{%0,%1,%2,%3},{%4,%5,%6,%7},{%8,%9},{%0,%1,%2,%3};"
                 : "+f"(d[0]), "+f"(d[1]), "+f"(d[2]), "+f"(d[3])
                 : "r"(a[0]), "r"(a[1]), "r"(a[2]), "r"(a[3]), "r"(b0), "r"(b1));
}
__device__ __forceinline__ void split2(float x, float y, uint32_t& hi, uint32_t& lo) {
    __nv_bfloat162 h = __float22bfloat162_rn(make_float2(x, y));
    float2 hf = __bfloat1622float2(h);
    __nv_bfloat162 l = __float22bfloat162_rn(make_float2(x - hf.x, y - hf.y));
    hi = *(uint32_t*)&h; lo = *(uint32_t*)&l;
}

// ---------------- edge index conversion + degree ----------------
__global__ void k_convert_idx(const void* __restrict__ ei_raw) {
    __shared__ int s_is64;
    if (threadIdx.x == 0) {
        const unsigned* w = (const unsigned*)ei_raw;
        int is64 = 1;
        for (int i = 1; i < 64; i += 2)
            if (w[i] != 0u) { is64 = 0; break; }
        s_is64 = is64;
    }
    __syncthreads();
    int e = blockIdx.x * 256 + threadIdx.x;
    if (e >= N_EDGES) return;
    int s, d;
    if (s_is64) {
        const long long* p = (const long long*)ei_raw;
        s = (int)p[e]; d = (int)p[(size_t)N_EDGES + e];
    } else {
        const int* p = (const int*)ei_raw;
        s = p[e]; d = p[N_EDGES + e];
    }
    g_src[e] = s; g_dst[e] = d;
    atomicAdd(&g_deg[d], 1.f);
}

// ---------------- zero scratch (vectorized) ----------------
__global__ void k_zero_all() {
    int i = blockIdx.x * 256 + threadIdx.x;
    int st = gridDim.x * 256;
    float4 z = make_float4(0.f, 0.f, 0.f, 0.f);
    float4* m4 = (float4*)g_msg;
    for (int k = i; k < N_NODES * HID / 4; k += st) m4[k] = z;
    for (int k = i; k < N_NODES; k += st) g_deg[k] = 0.f;
    if (i < 512) g_stats[i] = 0.f;
}

// ---------------- invert degree in place ----------------
__global__ void k_rdeg() {
    int n = blockIdx.x * 256 + threadIdx.x;
    if (n < N_NODES) g_deg[n] = 1.f / fmaxf(g_deg[n], 1.f);
}

// ---------------- weight prep: combined W1 + W2 -> bf16 hi/lo images -------------
__global__ void k_prep_w(const float* __restrict__ W1, const float* __restrict__ W2) {
    int idx = blockIdx.x * 256 + threadIdx.x;
    if (idx < 8192) {      // BP[nn][k]: nn<128, k<64; top half = W1 rows 0-63, bot = 64-127
        int nn = idx >> 6, k = idx & 63;
        float w = (nn < 64) ? W1[k * 64 + nn] : W1[(64 + k) * 64 + (nn - 64)];
        __nv_bfloat16 h = __float2bfloat16_rn(w);
        __nv_bfloat16 l = __float2bfloat16_rn(w - __bfloat162float(h));
        uint32_t off = (uint32_t)nn * 144u + 2u * (uint32_t)k;
        *(__nv_bfloat16*)(g_BPhi + off) = h;
        *(__nv_bfloat16*)(g_BPlo + off) = l;
    }
    if (idx < 4096) {      // B2[n][k] = W2[k*64+n]
        int n = idx >> 6, k = idx & 63;
        float w = W2[k * 64 + n];
        __nv_bfloat16 h = __float2bfloat16_rn(w);
        __nv_bfloat16 l = __float2bfloat16_rn(w - __bfloat162float(h));
        uint32_t off = (uint32_t)n * 144u + 2u * (uint32_t)k;
        *(__nv_bfloat16*)(g_B2hi + off) = h;
        *(__nv_bfloat16*)(g_B2lo + off) = l;
    }
}

// ---------------- stage 1: temporal edge MLP (66 -> 33 -> 17), 2 edges/thread ----
__global__ __launch_bounds__(256)
void k_stage1(const float* __restrict__ x,
              const float* __restrict__ dts, const float* __restrict__ bf,
              const float* __restrict__ ph,
              const float* __restrict__ W1, const float* __restrict__ b1,
              const float* __restrict__ W2, const float* __restrict__ b2) {
    __shared__ float sW1[66 * 36];
    __shared__ float sW2[33 * 20];
    __shared__ __align__(16) float sB1[34], sB2[18], sF[32], sP[32];
    int tid = threadIdx.x;
    for (int i = tid; i < 66 * 33; i += 256) {
        int r = i / 33, c = i - r * 33;
        sW1[r * 36 + c] = W1[i];
    }
    for (int i = tid; i < 33 * 17; i += 256) {
        int r = i / 17, c = i - r * 17;
        sW2[r * 20 + c] = W2[i];
    }
    if (tid < 33) sB1[tid] = b1[tid];
    if (tid < 17) sB2[tid] = b2[tid];
    if (tid < 32) { sF[tid] = bf[tid]; sP[tid] = ph[tid]; }
    __syncthreads();

    int e0 = blockIdx.x * 512 + tid;
    int e1 = e0 + 256;
    int s0 = g_src[e0], d0 = g_dst[e0];
    int s1 = g_src[e1], d1 = g_dst[e1];
    float dt0 = dts[e0], dt1 = dts[e1];

    const float* xd0 = x + (size_t)d0 * IN_CH;
    const float* xs0 = x + (size_t)s0 * IN_CH;
    const float* xd1 = x + (size_t)d1 * IN_CH;
    const float* xs1 = x + (size_t)s1 * IN_CH;

    ull a0[16], a1[16];
    float t0, t1;
    {
        const ull* bp = (const ull*)sB1;
#pragma unroll
        for (int p = 0; p < 16; p++) { a0[p] = bp[p]; a1[p] = bp[p]; }
        t0 = sB1[32]; t1 = sB1[32];
    }

#define S1_ROW(ROW, V0, V1)                                             \
    {                                                                   \
        ull m0 = pack2(V0), m1 = pack2(V1);                             \
        const ulonglong2* wp = (const ulonglong2*)(sW1 + (ROW) * 36);   \
        ulonglong2 wa = wp[0], wb = wp[1], wc = wp[2], wd = wp[3];      \
        ulonglong2 we = wp[4], wf = wp[5], wg = wp[6], wh = wp[7];      \
        fma2(a0[0], m0, wa.x);  fma2(a1[0], m1, wa.x);                  \
        fma2(a0[1], m0, wa.y);  fma2(a1[1], m1, wa.y);                  \
        fma2(a0[2], m0, wb.x);  fma2(a1[2], m1, wb.x);                  \
        fma2(a0[3], m0, wb.y);  fma2(a1[3], m1, wb.y);                  \
        fma2(a0[4], m0, wc.x);  fma2(a1[4], m1, wc.x);                  \
        fma2(a0[5], m0, wc.y);  fma2(a1[5], m1, wc.y);                  \
        fma2(a0[6], m0, wd.x);  fma2(a1[6], m1, wd.x);                  \
        fma2(a0[7], m0, wd.y);  fma2(a1[7], m1, wd.y);                  \
        fma2(a0[8], m0, we.x);  fma2(a1[8], m1, we.x);                  \
        fma2(a0[9], m0, we.y);  fma2(a1[9], m1, we.y);                  \
        fma2(a0[10], m0, wf.x); fma2(a1[10], m1, wf.x);                 \
        fma2(a0[11], m0, wf.y); fma2(a1[11], m1, wf.y);                 \
        fma2(a0[12], m0, wg.x); fma2(a1[12], m1, wg.x);                 \
        fma2(a0[13], m0, wg.y); fma2(a1[13], m1, wg.y);                 \
        fma2(a0[14], m0, wh.x); fma2(a1[14], m1, wh.x);                 \
        fma2(a0[15], m0, wh.y); fma2(a1[15], m1, wh.y);                 \
        float ws = sW1[(ROW) * 36 + 32];                                \
        t0 = fmaf(V0, ws, t0); t1 = fmaf(V1, ws, t1);                   \
    }

#pragma unroll 1
    for (int i = 0; i < 17; i++) { float v0 = xd0[i], v1 = xd1[i]; S1_ROW(i, v0, v1); }
#pragma unroll 1
    for (int i = 0; i < 17; i++) { float v0 = xs0[i], v1 = xs1[i]; S1_ROW(17 + i, v0, v1); }
#pragma unroll 1
    for (int t = 0; t < 32; t++) {
        float f = sF[t], p = sP[t];
        float v0 = __cosf(dt0 * f + p);
        float v1 = __cosf(dt1 * f + p);
        S1_ROW(34 + t, v0, v1);
    }

    float h0[33], h1[33];
#pragma unroll
    for (int p = 0; p < 16; p++) {
        unpack2(a0[p], h0[2 * p], h0[2 * p + 1]);
        unpack2(a1[p], h1[2 * p], h1[2 * p + 1]);
    }
    h0[32] = t0; h1[32] = t1;
#pragma unroll
    for (int i = 0; i < 33; i++) { h0[i] = fmaxf(h0[i], 0.f); h1[i] = fmaxf(h1[i], 0.f); }

    ull c0[8], c1[8]; float q0, q1;
    {
        const ull* bp = (const ull*)sB2;
#pragma unroll
        for (int p = 0; p < 8; p++) { c0[p] = bp[p]; c1[p] = bp[p]; }
        q0 = sB2[16]; q1 = sB2[16];
    }
#pragma unroll 1
    for (int i = 0; i < 33; i++) {
        ull m0 = pack2(h0[i]), m1 = pack2(h1[i]);
        const ulonglong2* wp = (const ulonglong2*)(sW2 + i * 20);
        ulonglong2 wa = wp[0], wb = wp[1], wc = wp[2], wd = wp[3];
        fma2(c0[0], m0, wa.x); fma2(c1[0], m1, wa.x);
        fma2(c0[1], m0, wa.y); fma2(c1[1], m1, wa.y);
        fma2(c0[2], m0, wb.x); fma2(c1[2], m1, wb.x);
        fma2(c0[3], m0, wb.y); fma2(c1[3], m1, wb.y);
        fma2(c0[4], m0, wc.x); fma2(c1[4], m1, wc.x);
        fma2(c0[5], m0, wc.y); fma2(c1[5], m1, wc.y);
        fma2(c0[6], m0, wd.x); fma2(c1[6], m1, wd.x);
        fma2(c0[7], m0, wd.y); fma2(c1[7], m1, wd.y);
        float ws = sW2[i * 20 + 16];
        q0 = fmaf(h0[i], ws, q0); q1 = fmaf(h1[i], ws, q1);
    }

    {
        float pv[17];
#pragma unroll
        for (int p = 0; p < 8; p++) unpack2(c0[p], pv[2 * p], pv[2 * p + 1]);
        pv[16] = q0;
        float m[17];
#pragma unroll
        for (int j = 0; j < 17; j++) m[j] = (2.f * tanh_fast(pv[j]) - 1.f) * xd0[j];
        float* base = g_msg + (size_t)d0 * 64;
        red4(base + 0, m[0], m[1], m[2], m[3]);
        red4(base + 4, m[4], m[5], m[6], m[7]);
        red4(base + 8, m[8], m[9], m[10], m[11]);
        red4(base + 12, m[12], m[13], m[14], m[15]);
        atomicAdd(base + 16, m[16]);
    }
    {
        float pv[17];
#pragma unroll
        for (int p = 0; p < 8; p++) unpack2(c1[p], pv[2 * p], pv[2 * p + 1]);
        pv[16] = q1;
        float m[17];
#pragma unroll
        for (int j = 0; j < 17; j++) m[j] = (2.f * tanh_fast(pv[j]) - 1.f) * xd1[j];
        float* base = g_msg + (size_t)d1 * 64;
        red4(base + 0, m[0], m[1], m[2], m[3]);
        red4(base + 4, m[4], m[5], m[6], m[7]);
        red4(base + 8, m[8], m[9], m[10], m[11]);
        red4(base + 12, m[12], m[13], m[14], m[15]);
        atomicAdd(base + 16, m[16]);
    }
}

// ---------------- node update + projection: h = (x + msg*rdeg) @ PW + Pb ----------
__global__ __launch_bounds__(256)
void k_proj(const float* __restrict__ x, const float* __restrict__ PW,
            const float* __restrict__ Pb) {
    __shared__ float sW[17 * 64];
    __shared__ __align__(16) float sB[64];
    int tid = threadIdx.x;
    for (int i = tid; i < 17 * 64; i += 256) sW[i] = PW[i];
    if (tid < 64) sB[tid] = Pb[tid];
    __syncthreads();

    int n = blockIdx.x * 128 + (tid >> 1);
    int q = tid & 1;
    if (n >= N_NODES) return;
    float rdeg = g_deg[n];

    ull acc[16];
    {
        const ull* bp = (const ull*)(sB + 32 * q);
#pragma unroll
        for (int p = 0; p < 16; p++) acc[p] = bp[p];
    }

    const float* xp = x + (size_t)n * 17;
    float* mp = g_msg + (size_t)n * 64;

#pragma unroll 1
    for (int k = 0; k < 17; k++) {
        float xm = xp[k] + mp[k] * rdeg;
        ull m = pack2(xm);
        const ulonglong2* wp = (const ulonglong2*)(sW + k * 64 + 32 * q);
#pragma unroll
        for (int h = 0; h < 8; h++) {
            ulonglong2 w = wp[h];
            fma2(acc[2 * h], m, w.x);
            fma2(acc[2 * h + 1], m, w.y);
        }
    }

    float* hp = g_h + (size_t)n * 64 + 32 * q;
#pragma unroll
    for (int h = 0; h < 8; h++) {
        float a, b2, c, d;
        unpack2(acc[2 * h], a, b2);
        unpack2(acc[2 * h + 1], c, d);
        *(float4*)(hp + 4 * h) = make_float4(a, b2, c, d);
    }
    if (q == 0) {
        float4 z = make_float4(0.f, 0.f, 0.f, 0.f);
        *(float4*)(mp + 0) = z; *(float4*)(mp + 4) = z;
        *(float4*)(mp + 8) = z; *(float4*)(mp + 12) = z;
        mp[16] = 0.f;
    }
}

// ---------------- k_pre: P[n] = h[n] @ [W1_top | W1_bot]  (+b1 on top half) -------
// warp-per-16-node chunk, HMMA 3-term hi/lo split, N=128, K=64.
#define PRE_SMEM_BYTES 55552
__global__ __launch_bounds__(128, 3)
void k_pre(const float* __restrict__ b1) {
    extern __shared__ unsigned char sm[];
    const uint32_t O_BPH = 0, O_BPL = 18432, O_B1B = 36864, O_WARP = 37120;
    const uint32_t S_AH = 0, S_AL = 2304;     // per-warp slice (4608 B)

    uint32_t sb = smem_u32(sm);
    int tid = threadIdx.x;
    int w = tid >> 5, l = tid & 31;

    float* sB1f = (float*)(sm + O_B1B);
    if (tid < 64) sB1f[tid] = b1[tid];
    {
        const float4* s; float4* d;
        s = (const float4*)g_BPhi; d = (float4*)(sm + O_BPH);
        for (int i = tid; i < 1152; i += 128) d[i] = s[i];
        s = (const float4*)g_BPlo; d = (float4*)(sm + O_BPL);
        for (int i = tid; i < 1152; i += 128) d[i] = s[i];
    }
    __syncthreads();

    unsigned char* wbp = sm + O_WARP + (uint32_t)w * 4608u;
    uint32_t wb = sb + O_WARP + (uint32_t)w * 4608u;

    int e = l >> 1, q = l & 1;
    uint32_t arow = (uint32_t)((l & 7) + ((l >> 3) & 1) * 8);
    uint32_t acol = (uint32_t)(l >> 4) * 16u;
    uint32_t brow = (uint32_t)((l & 7) + ((l >> 3) & 2) * 4);
    uint32_t bk = (uint32_t)((l >> 3) & 1) * 16u;

    int gw = blockIdx.x * 4 + w;
    int nw = gridDim.x * 4;

    for (int ch = gw; ch < N_NODES / 16; ch += nw) {
        int nbase = ch * 16;
        {   // gather h rows (coalesced) -> bf16 hi/lo A tile
            const float4* hp = (const float4*)(g_h + (size_t)(nbase + e) * 64 + q * 32);
            uint32_t bo = S_AH + (uint32_t)e * 144u + (uint32_t)q * 64u;
#pragma unroll
            for (int i = 0; i < 8; i++) {
                float4 v = hp[i];
                uint32_t h01, l01, h23, l23;
                split2(v.x, v.y, h01, l01);
                split2(v.z, v.w, h23, l23);
                *(uint2*)(wbp + bo + 8u * i) = make_uint2(h01, h23);
                *(uint2*)(wbp + bo + (S_AL - S_AH) + 8u * i) = make_uint2(l01, l23);
            }
        }
        __syncwarp();

        float d[16][4];
#pragma unroll
        for (int t = 0; t < 16; t++)
#pragma unroll
            for (int p = 0; p < 4; p++) d[t][p] = 0.f;
        {
            uint32_t aAh = wb + S_AH + arow * 144u + acol;
            uint32_t aAl = wb + S_AL + arow * 144u + acol;
            uint32_t aBh = sb + O_BPH + brow * 144u + bk;
            uint32_t aBl = sb + O_BPL + brow * 144u + bk;
#pragma unroll
            for (int ks = 0; ks < 4; ks++) {
                uint32_t ah[4], al[4];
                ldx4(ah, aAh + 32u * ks);
                ldx4(al, aAl + 32u * ks);
#pragma unroll
                for (int tp = 0; tp < 8; tp++) {
                    uint32_t bh[4], bl[4];
                    uint32_t toff = (uint32_t)tp * (16u * 144u) + 32u * ks;
                    ldx4(bh, aBh + toff);
                    ldx4(bl, aBl + toff);
                    mma16816(d[2 * tp],     ah, bh[0], bh[1]);
                    mma16816(d[2 * tp + 1], ah, bh[2], bh[3]);
                    mma16816(d[2 * tp],     al, bh[0], bh[1]);
                    mma16816(d[2 * tp + 1], al, bh[2], bh[3]);
                    mma16816(d[2 * tp],     ah, bl[0], bl[1]);
                    mma16816(d[2 * tp + 1], ah, bl[2], bl[3]);
                }
            }
        }

        // epilogue: +b1 on cols<64, store fp32 to g_P
        {
            int r0 = l >> 2;
            int cc = 2 * (l & 3);
            float* P0 = g_P + (size_t)(nbase + r0) * 128;
            float* P1 = g_P + (size_t)(nbase + r0 + 8) * 128;
#pragma unroll
            for (int t = 0; t < 16; t++) {
                int c = 8 * t + cc;
                float ba = (c < 64) ? sB1f[c] : 0.f;
                float bb = (c < 64) ? sB1f[c + 1] : 0.f;
                *(float2*)(P0 + c) = make_float2(d[t][0] + ba, d[t][1] + bb);
                *(float2*)(P1 + c) = make_float2(d[t][2] + ba, d[t][3] + bb);
            }
        }
        __syncwarp();
    }
}

// ---------------- k_edge: hidden = relu(P_top[dst]+P_bot[src]); GEMM2; scatter ----
// warp-per-16-edge chunk; per-warp A2/H2 slice (H2 aliases A2); 4 CTAs/SM.
#define EDGE_SMEM_BYTES 37120
__global__ __launch_bounds__(128, 4)
void k_edge(const float* __restrict__ b2) {
    extern __shared__ unsigned char sm[];
    const uint32_t O_B2H = 0, O_B2L = 9216, O_BI2 = 18432, O_WARP = 18688;
    const uint32_t S_A2H = 0, S_A2L = 2304, S_H2 = 0;   // H2 (4224B) aliases A2H+A2L

    uint32_t sb = smem_u32(sm);
    int tid = threadIdx.x;
    int w = tid >> 5, l = tid & 31;

    float* sB2f = (float*)(sm + O_BI2);
    if (tid < 64) sB2f[tid] = b2[tid];
    {
        const float4* s; float4* d;
        s = (const float4*)g_B2hi; d = (float4*)(sm + O_B2H);
        for (int i = tid; i < 576; i += 128) d[i] = s[i];
        s = (const float4*)g_B2lo; d = (float4*)(sm + O_B2L);
        for (int i = tid; i < 576; i += 128) d[i] = s[i];
    }
    __syncthreads();

    unsigned char* wbp = sm + O_WARP + (uint32_t)w * 4608u;
    uint32_t wb = sb + O_WARP + (uint32_t)w * 4608u;

    int e = l >> 1, q = l & 1;
    uint32_t arow = (uint32_t)((l & 7) + ((l >> 3) & 1) * 8);
    uint32_t acol = (uint32_t)(l >> 4) * 16u;
    uint32_t brow = (uint32_t)((l & 7) + ((l >> 3) & 2) * 4);
    uint32_t bk = (uint32_t)((l >> 3) & 1) * 16u;

    int gw = blockIdx.x * 4 + w;
    int nw = gridDim.x * 4;

    for (int ch = gw; ch < N_EDGES / 16; ch += nw) {
        int ge = ch * 16 + e;
        int dn = g_dst[ge];
        int sn = g_src[ge];

        // hidden = relu(P_top[dst] + P_bot[src]) -> bf16 hi/lo A2
        {
            const float4* pt = (const float4*)(g_P + (size_t)dn * 128 + q * 32);
            const float4* pbm = (const float4*)(g_P + (size_t)sn * 128 + 64 + q * 32);
            uint32_t bo = S_A2H + (uint32_t)e * 144u + (uint32_t)q * 64u;
#pragma unroll
            for (int i = 0; i < 8; i++) {
                float4 a = pt[i], b = pbm[i];
                float f0 = fmaxf(a.x + b.x, 0.f);
                float f1 = fmaxf(a.y + b.y, 0.f);
                float f2 = fmaxf(a.z + b.z, 0.f);
                float f3 = fmaxf(a.w + b.w, 0.f);
                uint32_t h01, l01, h23, l23;
                split2(f0, f1, h01, l01);
                split2(f2, f3, h23, l23);
                *(uint2*)(wbp + bo + 8u * i) = make_uint2(h01, h23);
                *(uint2*)(wbp + bo + (S_A2L - S_A2H) + 8u * i) = make_uint2(l01, l23);
            }
        }
        __syncwarp();

        // GEMM2: D2 = hidden @ W2 (3-term), K=64
        float d2[8][4];
#pragma unroll
        for (int t = 0; t < 8; t++)
#pragma unroll
            for (int p = 0; p < 4; p++) d2[t][p] = 0.f;
        {
            uint32_t aAh = wb + S_A2H + arow * 144u + acol;
            uint32_t aAl = wb + S_A2L + arow * 144u + acol;
            uint32_t aBh = sb + O_B2H + brow * 144u + bk;
            uint32_t aBl = sb + O_B2L + brow * 144u + bk;
#pragma unroll
            for (int ks = 0; ks < 4; ks++) {
                uint32_t ah[4], al[4];
                ldx4(ah, aAh + 32u * ks);
                ldx4(al, aAl + 32u * ks);
#pragma unroll
                for (int tp = 0; tp < 4; tp++) {
                    uint32_t bh[4], bl[4];
                    uint32_t toff = (uint32_t)tp * (16u * 144u) + 32u * ks;
                    ldx4(bh, aBh + toff);
                    ldx4(bl, aBl + toff);
                    mma16816(d2[2 * tp],     ah, bh[0], bh[1]);
                    mma16816(d2[2 * tp + 1], ah, bh[2], bh[3]);
                    mma16816(d2[2 * tp],     al, bh[0], bh[1]);
                    mma16816(d2[2 * tp + 1], al, bh[2], bh[3]);
                    mma16816(d2[2 * tp],     ah, bl[0], bl[1]);
                    mma16816(d2[2 * tp + 1], ah, bl[2], bl[3]);
                }
            }
        }
        __syncwarp();   // all lanes past A2 reads before H2 (alias) writes

        // D2 -> H2 fp32 (stride 66 floats)
        {
            int r0 = l >> 2;
            int cc = 2 * (l & 3);
#pragma unroll
            for (int t = 0; t < 8; t++) {
                int c = 8 * t + cc;
                *(float2*)(wbp + S_H2 + ((uint32_t)r0 * 66u + (uint32_t)c) * 4u)
                    = make_float2(d2[t][0], d2[t][1]);
                *(float2*)(wbp + S_H2 + ((uint32_t)(r0 + 8) * 66u + (uint32_t)c) * 4u)
                    = make_float2(d2[t][2], d2[t][3]);
            }
        }
        __syncwarp();

        // scatter: msg = (2*tanh(D2+b2)-1) * h_dst
        {
            const float* hr = (const float*)(wbp + S_H2) + e * 66 + q * 32;
            const float* b2p = sB2f + q * 32;
            const float4* xr4 = (const float4*)(g_h + (size_t)dn * 64 + q * 32);
            float* base = g_msg + (size_t)dn * 64 + q * 32;
#pragma unroll
            for (int cg = 0; cg < 8; cg++) {
                int c = 4 * cg;
                float4 xv = xr4[cg];
                float v0 = (2.f * tanh_fast(hr[c + 0] + b2p[c + 0]) - 1.f) * xv.x;
                float v1 = (2.f * tanh_fast(hr[c + 1] + b2p[c + 1]) - 1.f) * xv.y;
                float v2 = (2.f * tanh_fast(hr[c + 2] + b2p[c + 2]) - 1.f) * xv.z;
                float v3 = (2.f * tanh_fast(hr[c + 3] + b2p[c + 3]) - 1.f) * xv.w;
                red4(base + c, v0, v1, v2, v3);
            }
        }
        __syncwarp();   // H2 reads done before next iter's A2 (alias) writes
    }
}

// ---------------- node update (h += msg*rdeg), zero msg, BN partial stats ---------
__global__ __launch_bounds__(256)
void k_update(int statOff) {
    float* stats = g_stats + statOff;
    int tid = threadIdx.x;
    int base = blockIdx.x * 4096;
    float4* h4 = (float4*)g_h;
    float4* m4 = (float4*)g_msg;
    float s[4] = {0.f, 0.f, 0.f, 0.f}, ss[4] = {0.f, 0.f, 0.f, 0.f};
#pragma unroll 4
    for (int i = 0; i < 16; i++) {
        int idx = base + tid + i * 256;
        if (idx < N_NODES * 16) {
            int n = idx >> 4;
            float rdeg = g_deg[n];
            float4 hv = h4[idx];
            float4 mv = m4[idx];
            hv.x += mv.x * rdeg; hv.y += mv.y * rdeg;
            hv.z += mv.z * rdeg; hv.w += mv.w * rdeg;
            h4[idx] = hv;
            m4[idx] = make_float4(0.f, 0.f, 0.f, 0.f);
            s[0] += hv.x; s[1] += hv.y; s[2] += hv.z; s[3] += hv.w;
            ss[0] += hv.x * hv.x; ss[1] += hv.y * hv.y;
            ss[2] += hv.z * hv.z; ss[3] += hv.w * hv.w;
        }
    }
    __shared__ float sA[256][4], sBm[256][4];
#pragma unroll
    for (int p = 0; p < 4; p++) { sA[tid][p] = s[p]; sBm[tid][p] = ss[p]; }
    __syncthreads();
    if (tid < 16) {
        float rs[4] = {0.f, 0.f, 0.f, 0.f}, rss[4] = {0.f, 0.f, 0.f, 0.f};
#pragma unroll
        for (int j = 0; j < 16; j++) {
#pragma unroll
            for (int p = 0; p < 4; p++) {
                rs[p] += sA[tid + 16 * j][p];
                rss[p] += sBm[tid + 16 * j][p];
            }
        }
        int c0 = tid * 4;
#pragma unroll
        for (int p = 0; p < 4; p++) {
            atomicAdd(&stats[c0 + p], rs[p]);
            atomicAdd(&stats[64 + c0 + p], rss[p]);
        }
    }
}

// ---------------- BN apply + relu ----------------
__global__ void k_bnrelu(int statOff, const float* __restrict__ g, const float* __restrict__ b) {
    const float* stats = g_stats + statOff;
    int idx = blockIdx.x * 256 + threadIdx.x;
    int c0 = (idx & 15) * 4;
    const float invn = 1.f / (float)N_NODES;
    float4* hp = ((float4*)g_h) + idx;
    float4 v = *hp;
    float o[4] = {v.x, v.y, v.z, v.w};
#pragma unroll
    for (int i = 0; i < 4; i++) {
        float m = stats[c0 + i] * invn;
        float var = stats[64 + c0 + i] * invn - m * m;
        float sc = rsqrtf(var + BN_EPS) * g[c0 + i];
        o[i] = fmaxf((o[i] - m) * sc + b[c0 + i], 0.f);
    }
    v.x = o[0]; v.y = o[1]; v.z = o[2]; v.w = o[3];
    *hp = v;
}

// ---------------- classifier ----------------
__global__ void k_clf1(const float* __restrict__ W, const float* __restrict__ b) {
    __shared__ float sW[4096], sB[64];
    int tid = threadIdx.x;
    for (int i = tid; i < 4096; i += 256) sW[i] = W[i];
    if (tid < 64) sB[tid] = b[tid];
    __syncthreads();
    int r = blockIdx.x * 256 + tid;
    if (r >= BATCH) return;
    float acc[64];
#pragma unroll
    for (int c = 0; c < 64; c++) acc[c] = sB[c];
#pragma unroll 1
    for (int k = 0; k < 64; k++) {
        float hk = g_h[(size_t)r * 64 + k];
        const float* w = &sW[k * 64];
#pragma unroll
        for (int c = 0; c < 64; c++) acc[c] += hk * w[c];
    }
    float* z = g_z1 + (size_t)r * 64;
    float* st = g_stats + 256;
#pragma unroll 1
    for (int c = 0; c < 64; c++) {
        z[c] = acc[c];
        atomicAdd(&st[c], acc[c]);
        atomicAdd(&st[64 + c], acc[c] * acc[c]);
    }
}

__global__ void k_clf2(const float* __restrict__ W, const float* __restrict__ b,
                       const float* __restrict__ g1, const float* __restrict__ bb1) {
    __shared__ float sW[2048], sB[32], sScale[64], sBias[64];
    int tid = threadIdx.x;
    for (int i = tid; i < 2048; i += 256) sW[i] = W[i];
    if (tid < 32) sB[tid] = b[tid];
    if (tid < 64) {
        const float invn = 1.f / (float)BATCH;
        float m = g_stats[256 + tid] * invn;
        float var = g_stats[256 + 64 + tid] * invn - m * m;
        float sc = rsqrtf(var + BN_EPS) * g1[tid];
        sScale[tid] = sc;
        sBias[tid] = bb1[tid] - m * sc;
    }
    __syncthreads();
    int r = blockIdx.x * 256 + tid;
    if (r >= BATCH) return;
    float acc[32];
#pragma unroll
    for (int c = 0; c < 32; c++) acc[c] = sB[c];
#pragma unroll 1
    for (int k = 0; k < 64; k++) {
        float v = fmaxf(g_z1[(size_t)r * 64 + k] * sScale[k] + sBias[k], 0.f);
        const float* w = &sW[k * 32];
#pragma unroll
        for (int c = 0; c < 32; c++) acc[c] += v * w[c];
    }
    float* z = g_z2 + (size_t)r * 32;
    float* st = g_stats + 384;
#pragma unroll 1
    for (int c = 0; c < 32; c++) {
        z[c] = acc[c];
        atomicAdd(&st[c], acc[c]);
        atomicAdd(&st[32 + c], acc[c] * acc[c]);
    }
}

__global__ void k_clf3(const float* __restrict__ W3, const float* __restrict__ b3,
                       const float* __restrict__ g2, const float* __restrict__ bb2,
                       float* __restrict__ out) {
    __shared__ float sW[32], sScale[32], sBias[32], sb3;
    int tid = threadIdx.x;
    if (tid < 32) {
        sW[tid] = W3[tid];
        const float invn = 1.f / (float)BATCH;
        float m = g_stats[384 + tid] * invn;
        float var = g_stats[384 + 32 + tid] * invn - m * m;
        float sc = rsqrtf(var + BN_EPS) * g2[tid];
        sScale[tid] = sc;
        sBias[tid] = bb2[tid] - m * sc;
    }
    if (tid == 0) sb3 = b3[0];
    __syncthreads();
    int r = blockIdx.x * 256 + tid;
    if (r >= BATCH) return;
    float a = sb3;
#pragma unroll 1
    for (int k = 0; k < 32; k++)
        a += fmaxf(g_z2[(size_t)r * 32 + k] * sScale[k] + sBias[k], 0.f) * sW[k];
    out[r] = a;
}

// ---------------- launch ----------------
extern "C" void kernel_launch(void* const* d_in, const int* in_sizes, int n_in,
                              void* d_out, int out_size) {
    auto ix = [&](int i) { return (n_in >= 28) ? i : (i > 3 ? i - 1 : i); };
    const float* x    = (const float*)d_in[ix(0)];
    const void*  ei   = d_in[ix(1)];
    const float* dts  = (const float*)d_in[ix(2)];
    const float* bf   = (const float*)d_in[ix(4)];
    const float* ph   = (const float*)d_in[ix(5)];
    const float* tW1  = (const float*)d_in[ix(6)];
    const float* tb1  = (const float*)d_in[ix(7)];
    const float* tW2  = (const float*)d_in[ix(8)];
    const float* tb2  = (const float*)d_in[ix(9)];
    const float* pW   = (const float*)d_in[ix(10)];
    const float* pb   = (const float*)d_in[ix(11)];
    const float* sW1  = (const float*)d_in[ix(12)];
    const float* sb1  = (const float*)d_in[ix(13)];
    const float* sW2  = (const float*)d_in[ix(14)];
    const float* sb2  = (const float*)d_in[ix(15)];
    const float* bng  = (const float*)d_in[ix(16)];
    const float* bnb  = (const float*)d_in[ix(17)];
    const float* cW1  = (const float*)d_in[ix(18)];
    const float* cb1  = (const float*)d_in[ix(19)];
    const float* cg1  = (const float*)d_in[ix(20)];
    const float* cbb1 = (const float*)d_in[ix(21)];
    const float* cW2  = (const float*)d_in[ix(22)];
    const float* cb2  = (const float*)d_in[ix(23)];
    const float* cg2  = (const float*)d_in[ix(24)];
    const float* cbb2 = (const float*)d_in[ix(25)];
    const float* cW3  = (const float*)d_in[ix(26)];
    const float* cb3  = (const float*)d_in[ix(27)];
    float* out = (float*)d_out;

    cudaFuncSetAttribute(k_pre, cudaFuncAttributeMaxDynamicSharedMemorySize, PRE_SMEM_BYTES);
    cudaFuncSetAttribute(k_edge, cudaFuncAttributeMaxDynamicSharedMemorySize, EDGE_SMEM_BYTES);

    k_zero_all<<<1024, 256>>>();
    k_convert_idx<<<N_EDGES / 256, 256>>>(ei);
    k_rdeg<<<(N_NODES + 255) / 256, 256>>>();
    k_stage1<<<N_EDGES / 512, 256>>>(x, dts, bf, ph, tW1, tb1, tW2, tb2);
    k_proj<<<(N_NODES + 127) / 128, 256>>>(x, pW, pb);

    for (int l = 0; l < 2; l++) {
        k_prep_w<<<32, 256>>>(sW1 + l * 8192, sW2 + l * 4096);
        k_pre<<<444, 128, PRE_SMEM_BYTES>>>(sb1 + l * 64);
        k_edge<<<592, 128, EDGE_SMEM_BYTES>>>(sb2 + l * 64);
        k_update<<<(N_NODES * 16 + 4095) / 4096, 256>>>(l * 128);
        k_bnrelu<<<(N_NODES * HID / 4) / 256, 256>>>(l * 128, bng + l * 64, bnb + l * 64);
    }

    k_clf1<<<(BATCH + 255) / 256, 256>>>(cW1, cb1);
    k_clf2<<<(BATCH + 255) / 256, 256>>>(cW2, cb2, cg1, cbb1);
    k_clf3<<<(BATCH + 255) / 256, 256>>>(cW3, cb3, cg2, cbb2, out);
    (void)in_sizes; (void)out_size;
}